// round 7
// baseline (speedup 1.0000x reference)
#include <cuda_runtime.h>
#include <cuda_bf16.h>
#include <math.h>
#include <stdint.h>

// Problem constants
#define BB    8
#define NQ    900
#define DD    256
#define HH    8
#define HD    32
#define PP    4
#define BEV   200
#define FFN   512
#define MROWS (BB * NQ)          // 7200

// ---------------- scratch (allocation-free: __device__ globals) -------------
__device__ float g_qin  [MROWS * DD];
__device__ float g_qkv  [MROWS * 3 * DD];
__device__ float g_attn [MROWS * DD];
__device__ float g_q1   [MROWS * DD];
__device__ float g_q2   [MROWS * DD];
__device__ float g_offs [MROWS * HH * PP * 2];
__device__ float g_wts  [MROWS * HH * PP];
__device__ float g_fused[MROWS * DD];
__device__ float g_qq2  [MROWS * DD];
__device__ float g_q3   [MROWS * DD];
__device__ float g_mid  [MROWS * FFN];

// ---------------- fused add + LayerNorm: warp per row, 8 rows/block ----------
__global__ void add_ln_warp(const float* __restrict__ a, const float* __restrict__ b,
                            const float* __restrict__ s, const float* __restrict__ bias,
                            float* __restrict__ out) {
    const unsigned full = 0xffffffffu;
    int w = threadIdx.x >> 5, lane = threadIdx.x & 31;
    int row = blockIdx.x * 8 + w;
    if (row >= MROWS) return;
    const float* ap = a + (size_t)row * DD;
    float4 x0 = *(const float4*)(ap + lane * 4);
    float4 x1 = *(const float4*)(ap + 128 + lane * 4);
    if (b) {
        const float* bp = b + (size_t)row * DD;
        float4 b0 = *(const float4*)(bp + lane * 4);
        float4 b1 = *(const float4*)(bp + 128 + lane * 4);
        x0.x += b0.x; x0.y += b0.y; x0.z += b0.z; x0.w += b0.w;
        x1.x += b1.x; x1.y += b1.y; x1.z += b1.z; x1.w += b1.w;
    }
    float sum = x0.x + x0.y + x0.z + x0.w + x1.x + x1.y + x1.z + x1.w;
    #pragma unroll
    for (int o = 16; o; o >>= 1) sum += __shfl_xor_sync(full, sum, o);
    float mean = sum * (1.f / DD);
    float c0x = x0.x - mean, c0y = x0.y - mean, c0z = x0.z - mean, c0w = x0.w - mean;
    float c1x = x1.x - mean, c1y = x1.y - mean, c1z = x1.z - mean, c1w = x1.w - mean;
    float vs = c0x*c0x + c0y*c0y + c0z*c0z + c0w*c0w
             + c1x*c1x + c1y*c1y + c1z*c1z + c1w*c1w;
    #pragma unroll
    for (int o = 16; o; o >>= 1) vs += __shfl_xor_sync(full, vs, o);
    float inv = rsqrtf(vs * (1.f / DD) + 1e-5f);
    float4 s0 = *(const float4*)(s + lane * 4);
    float4 s1 = *(const float4*)(s + 128 + lane * 4);
    float4 g0 = *(const float4*)(bias + lane * 4);
    float4 g1 = *(const float4*)(bias + 128 + lane * 4);
    float* op = out + (size_t)row * DD;
    *(float4*)(op + lane * 4) = make_float4(
        c0x * inv * s0.x + g0.x, c0y * inv * s0.y + g0.y,
        c0z * inv * s0.z + g0.z, c0w * inv * s0.w + g0.w);
    *(float4*)(op + 128 + lane * 4) = make_float4(
        c1x * inv * s1.x + g1.x, c1y * inv * s1.y + g1.y,
        c1z * inv * s1.z + g1.z, c1w * inv * s1.w + g1.w);
}

// ---------------- tf32 helpers ----------------------------------------------
__device__ __forceinline__ uint32_t f2tf32(float f) {
    uint32_t u;
    asm("cvt.rna.tf32.f32 %0, %1;" : "=r"(u) : "f"(f));
    return u;
}

__device__ __forceinline__ void mma1688(float* d, const uint32_t* a, const uint32_t* b) {
    asm volatile(
        "mma.sync.aligned.m16n8k8.row.col.f32.tf32.tf32.f32 "
        "{%0,%1,%2,%3}, {%4,%5,%6,%7}, {%8,%9}, {%0,%1,%2,%3};\n"
        : "+f"(d[0]), "+f"(d[1]), "+f"(d[2]), "+f"(d[3])
        : "r"(a[0]), "r"(a[1]), "r"(a[2]), "r"(a[3]), "r"(b[0]), "r"(b[1]));
}

// ---------------- tensor-core NT GEMM (tf32): C = A*B^T + epi ---------------
// 128x64 tile, BK=16, double-buffered smem (1 sync/iter), 8 warps 4x2.
#define SSTR 20
__global__ __launch_bounds__(256, 2)
void gemm_tc(const float* __restrict__ A, const float* __restrict__ B,
             const float* __restrict__ bias, const float* __restrict__ resid,
             float* __restrict__ C, int M, int N, int K, int relu) {
    __shared__ uint32_t As[2][128 * SSTR];
    __shared__ uint32_t Bs[2][64 * SSTR];
    const int tid = threadIdx.x;
    const int lane = tid & 31, wid = tid >> 5;
    const int g = lane >> 2, tg = lane & 3;
    const int wm = (wid >> 1) * 32, wn = (wid & 1) * 32;
    const int bm = blockIdx.y * 128, bn = blockIdx.x * 64;

    const int rowA0 = tid >> 2, rowA1 = rowA0 + 64;
    const int rowB  = tid >> 2;
    const int kq    = (tid & 3) * 4;

    float4 pa0, pa1, pb;
    const float4 z4 = make_float4(0.f, 0.f, 0.f, 0.f);
    {
        int gm0 = bm + rowA0, gm1 = bm + rowA1;
        pa0 = (gm0 < M) ? *(const float4*)(A + (size_t)gm0 * K + kq) : z4;
        pa1 = (gm1 < M) ? *(const float4*)(A + (size_t)gm1 * K + kq) : z4;
        pb  = *(const float4*)(B + (size_t)(bn + rowB) * K + kq);
    }

    float acc[2][4][4];
    #pragma unroll
    for (int mi = 0; mi < 2; mi++)
        #pragma unroll
        for (int ni = 0; ni < 4; ni++)
            #pragma unroll
            for (int r = 0; r < 4; r++) acc[mi][ni][r] = 0.f;

    // store stage 0
    *(uint4*)&As[0][rowA0 * SSTR + kq] =
        make_uint4(f2tf32(pa0.x), f2tf32(pa0.y), f2tf32(pa0.z), f2tf32(pa0.w));
    *(uint4*)&As[0][rowA1 * SSTR + kq] =
        make_uint4(f2tf32(pa1.x), f2tf32(pa1.y), f2tf32(pa1.z), f2tf32(pa1.w));
    *(uint4*)&Bs[0][rowB * SSTR + kq] =
        make_uint4(f2tf32(pb.x), f2tf32(pb.y), f2tf32(pb.z), f2tf32(pb.w));
    __syncthreads();

    int cur = 0;
    for (int k0 = 0; k0 < K; k0 += 16) {
        const bool more = (k0 + 16) < K;
        if (more) {
            int kn = k0 + 16;
            int gm0 = bm + rowA0, gm1 = bm + rowA1;
            pa0 = (gm0 < M) ? *(const float4*)(A + (size_t)gm0 * K + kn + kq) : z4;
            pa1 = (gm1 < M) ? *(const float4*)(A + (size_t)gm1 * K + kn + kq) : z4;
            pb  = *(const float4*)(B + (size_t)(bn + rowB) * K + kn + kq);
        }
        // compute from buf[cur]
        #pragma unroll
        for (int k8 = 0; k8 < 2; k8++) {
            uint32_t af[2][4], bf[4][2];
            #pragma unroll
            for (int mi = 0; mi < 2; mi++) {
                const uint32_t* base = &As[cur][(wm + mi * 16 + g) * SSTR + k8 * 8 + tg];
                af[mi][0] = base[0];
                af[mi][1] = base[8 * SSTR];
                af[mi][2] = base[4];
                af[mi][3] = base[8 * SSTR + 4];
            }
            #pragma unroll
            for (int ni = 0; ni < 4; ni++) {
                const uint32_t* base = &Bs[cur][(wn + ni * 8 + g) * SSTR + k8 * 8 + tg];
                bf[ni][0] = base[0];
                bf[ni][1] = base[4];
            }
            #pragma unroll
            for (int mi = 0; mi < 2; mi++)
                #pragma unroll
                for (int ni = 0; ni < 4; ni++)
                    mma1688(acc[mi][ni], af[mi], bf[ni]);
        }
        if (more) {
            int nxt = cur ^ 1;
            *(uint4*)&As[nxt][rowA0 * SSTR + kq] =
                make_uint4(f2tf32(pa0.x), f2tf32(pa0.y), f2tf32(pa0.z), f2tf32(pa0.w));
            *(uint4*)&As[nxt][rowA1 * SSTR + kq] =
                make_uint4(f2tf32(pa1.x), f2tf32(pa1.y), f2tf32(pa1.z), f2tf32(pa1.w));
            *(uint4*)&Bs[nxt][rowB * SSTR + kq] =
                make_uint4(f2tf32(pb.x), f2tf32(pb.y), f2tf32(pb.z), f2tf32(pb.w));
            __syncthreads();
            cur = nxt;
        }
    }

    #pragma unroll
    for (int ni = 0; ni < 4; ni++) {
        int c = bn + wn + ni * 8 + 2 * tg;
        float b0 = bias ? bias[c] : 0.f;
        float b1 = bias ? bias[c + 1] : 0.f;
        #pragma unroll
        for (int mi = 0; mi < 2; mi++) {
            int r0 = bm + wm + mi * 16 + g;
            int r1 = r0 + 8;
            float v0 = acc[mi][ni][0] + b0, v1 = acc[mi][ni][1] + b1;
            float v2 = acc[mi][ni][2] + b0, v3 = acc[mi][ni][3] + b1;
            if (relu) {
                v0 = fmaxf(v0, 0.f); v1 = fmaxf(v1, 0.f);
                v2 = fmaxf(v2, 0.f); v3 = fmaxf(v3, 0.f);
            }
            if (r0 < M) {
                if (resid) {
                    float2 rr = *(const float2*)(resid + (size_t)r0 * N + c);
                    v0 += rr.x; v1 += rr.y;
                }
                *(float2*)(C + (size_t)r0 * N + c) = make_float2(v0, v1);
            }
            if (r1 < M) {
                if (resid) {
                    float2 rr = *(const float2*)(resid + (size_t)r1 * N + c);
                    v2 += rr.x; v3 += rr.y;
                }
                *(float2*)(C + (size_t)r1 * N + c) = make_float2(v2, v3);
            }
        }
    }
}

// ---------------- small NT GEMM (N=32 weights head) --------------------------
__global__ void gemm_nt(const float* __restrict__ A, const float* __restrict__ B,
                        const float* __restrict__ bias, const float* __restrict__ resid,
                        float* __restrict__ C, int M, int N, int K, int relu) {
    __shared__ float As[16][68];
    __shared__ float Bs[16][68];
    int tid = threadIdx.x;
    int tx = tid & 15, ty = tid >> 4;
    int bm = blockIdx.y * 64, bn = blockIdx.x * 64;
    int lm = tid >> 2;
    int kq = (tid & 3) * 4;
    float acc[4][4] = {};
    for (int k0 = 0; k0 < K; k0 += 16) {
        int gm = bm + lm;
        float4 va = make_float4(0.f, 0.f, 0.f, 0.f);
        if (gm < M) va = *(const float4*)(A + (size_t)gm * K + k0 + kq);
        As[kq + 0][lm] = va.x; As[kq + 1][lm] = va.y;
        As[kq + 2][lm] = va.z; As[kq + 3][lm] = va.w;
        int gn = bn + lm;
        float4 vb = make_float4(0.f, 0.f, 0.f, 0.f);
        if (gn < N) vb = *(const float4*)(B + (size_t)gn * K + k0 + kq);
        Bs[kq + 0][lm] = vb.x; Bs[kq + 1][lm] = vb.y;
        Bs[kq + 2][lm] = vb.z; Bs[kq + 3][lm] = vb.w;
        __syncthreads();
        #pragma unroll
        for (int k = 0; k < 16; k++) {
            float4 a4 = *(const float4*)&As[k][ty * 4];
            float4 b4 = *(const float4*)&Bs[k][tx * 4];
            float af[4] = {a4.x, a4.y, a4.z, a4.w};
            float bf[4] = {b4.x, b4.y, b4.z, b4.w};
            #pragma unroll
            for (int i = 0; i < 4; i++)
                #pragma unroll
                for (int j = 0; j < 4; j++)
                    acc[i][j] += af[i] * bf[j];
        }
        __syncthreads();
    }
    #pragma unroll
    for (int i = 0; i < 4; i++) {
        int r = bm + ty * 4 + i;
        if (r >= M) continue;
        #pragma unroll
        for (int j = 0; j < 4; j++) {
            int c = bn + tx * 4 + j;
            if (c >= N) continue;
            float v = acc[i][j];
            if (bias) v += bias[c];
            if (relu) v = fmaxf(v, 0.f);
            if (resid) v += resid[(size_t)r * N + c];
            C[(size_t)r * N + c] = v;
        }
    }
}

// ---------------- tensor-core flash attention (tf32, round-4 proven) ---------
// 64-query blocks, 4 warps (16 q each), 64-key tiles, HD=32.
#define KSTR 36
#define VSTR 68
#define PSTR 68
__global__ __launch_bounds__(128)
void attn3_kernel(const float* __restrict__ qkv, float* __restrict__ out) {
    __shared__ float Ks[64 * KSTR];   // K tile [key][d]
    __shared__ float Vs[32 * VSTR];   // V tile transposed [d][key]
    __shared__ float Ps[64 * PSTR];   // P [q][key]

    const int b = blockIdx.z, h = blockIdx.y, qt = blockIdx.x;
    const int tid = threadIdx.x;
    const int w = tid >> 5, lane = tid & 31;
    const int g = lane >> 2, tg = lane & 3;
    const float scale = 0.17677669529663687f;   // 1/sqrt(32)
    const unsigned full = 0xffffffffu;

    // ---- Q fragments (held in registers for whole kernel), pre-scaled ----
    const int r0 = qt * 64 + w * 16 + g;
    const int r1 = r0 + 8;
    uint32_t qa[4][4];
    {
        const float* q0p = qkv + ((size_t)(b * NQ + (r0 < NQ ? r0 : 0))) * 768 + h * HD;
        const float* q1p = qkv + ((size_t)(b * NQ + (r1 < NQ ? r1 : 0))) * 768 + h * HD;
        bool v0 = r0 < NQ, v1 = r1 < NQ;
        #pragma unroll
        for (int s = 0; s < 4; s++) {
            int c0 = s * 8 + tg, c1 = c0 + 4;
            qa[s][0] = v0 ? f2tf32(q0p[c0] * scale) : 0u;
            qa[s][1] = v1 ? f2tf32(q1p[c0] * scale) : 0u;
            qa[s][2] = v0 ? f2tf32(q0p[c1] * scale) : 0u;
            qa[s][3] = v1 ? f2tf32(q1p[c1] * scale) : 0u;
        }
    }

    float m0 = -INFINITY, m1 = -INFINITY, l0 = 0.f, l1 = 0.f;
    float O[4][4];
    #pragma unroll
    for (int nd = 0; nd < 4; nd++)
        #pragma unroll
        for (int r = 0; r < 4; r++) O[nd][r] = 0.f;

    const int NKT = (NQ + 63) / 64;   // 15
    for (int jt = 0; jt < NKT; jt++) {
        __syncthreads();
        // ---- load K tile (cvt'd) and V tile transposed (cvt'd) ----
        {
            int key = tid >> 1, dh = (tid & 1) * 16;
            int kk = jt * 64 + key;
            if (kk < NQ) {
                const float* srcK = qkv + ((size_t)(b * NQ + kk)) * 768 + 256 + h * HD + dh;
                const float* srcV = srcK + 256;
                #pragma unroll
                for (int i = 0; i < 4; i++) {
                    float4 kv = *(const float4*)(srcK + i * 4);
                    *(float4*)&Ks[key * KSTR + dh + i * 4] = make_float4(
                        __uint_as_float(f2tf32(kv.x)), __uint_as_float(f2tf32(kv.y)),
                        __uint_as_float(f2tf32(kv.z)), __uint_as_float(f2tf32(kv.w)));
                    float4 vv = *(const float4*)(srcV + i * 4);
                    Vs[(dh + i * 4 + 0) * VSTR + key] = __uint_as_float(f2tf32(vv.x));
                    Vs[(dh + i * 4 + 1) * VSTR + key] = __uint_as_float(f2tf32(vv.y));
                    Vs[(dh + i * 4 + 2) * VSTR + key] = __uint_as_float(f2tf32(vv.z));
                    Vs[(dh + i * 4 + 3) * VSTR + key] = __uint_as_float(f2tf32(vv.w));
                }
            } else {
                #pragma unroll
                for (int i = 0; i < 4; i++) {
                    *(float4*)&Ks[key * KSTR + dh + i * 4] = make_float4(0.f, 0.f, 0.f, 0.f);
                    Vs[(dh + i * 4 + 0) * VSTR + key] = 0.f;
                    Vs[(dh + i * 4 + 1) * VSTR + key] = 0.f;
                    Vs[(dh + i * 4 + 2) * VSTR + key] = 0.f;
                    Vs[(dh + i * 4 + 3) * VSTR + key] = 0.f;
                }
            }
        }
        __syncthreads();

        // ---- QK: S[16 x 64] per warp ----
        float sacc[8][4];
        #pragma unroll
        for (int ni = 0; ni < 8; ni++)
            #pragma unroll
            for (int r = 0; r < 4; r++) sacc[ni][r] = 0.f;
        #pragma unroll
        for (int s = 0; s < 4; s++) {
            #pragma unroll
            for (int ni = 0; ni < 8; ni++) {
                const float* base = &Ks[(ni * 8 + g) * KSTR + s * 8 + tg];
                uint32_t bf[2] = { __float_as_uint(base[0]), __float_as_uint(base[4]) };
                mma1688(sacc[ni], qa[s], bf);
            }
        }
        // ---- mask invalid keys ----
        int kglob = jt * 64;
        if (kglob + 64 > NQ) {
            #pragma unroll
            for (int ni = 0; ni < 8; ni++) {
                int kc = kglob + ni * 8 + 2 * tg;
                if (kc >= NQ)     { sacc[ni][0] = -1e30f; sacc[ni][2] = -1e30f; }
                if (kc + 1 >= NQ) { sacc[ni][1] = -1e30f; sacc[ni][3] = -1e30f; }
            }
        }

        // ---- online softmax (rows g and g+8; quad reduce over tg lanes) ----
        float mx0 = -INFINITY, mx1 = -INFINITY;
        #pragma unroll
        for (int ni = 0; ni < 8; ni++) {
            mx0 = fmaxf(mx0, fmaxf(sacc[ni][0], sacc[ni][1]));
            mx1 = fmaxf(mx1, fmaxf(sacc[ni][2], sacc[ni][3]));
        }
        mx0 = fmaxf(mx0, __shfl_xor_sync(full, mx0, 1));
        mx0 = fmaxf(mx0, __shfl_xor_sync(full, mx0, 2));
        mx1 = fmaxf(mx1, __shfl_xor_sync(full, mx1, 1));
        mx1 = fmaxf(mx1, __shfl_xor_sync(full, mx1, 2));
        float nm0 = fmaxf(m0, mx0), nm1 = fmaxf(m1, mx1);
        float fac0 = __expf(m0 - nm0), fac1 = __expf(m1 - nm1);
        float sum0 = 0.f, sum1 = 0.f;
        #pragma unroll
        for (int ni = 0; ni < 8; ni++) {
            sacc[ni][0] = __expf(sacc[ni][0] - nm0);
            sacc[ni][1] = __expf(sacc[ni][1] - nm0);
            sacc[ni][2] = __expf(sacc[ni][2] - nm1);
            sacc[ni][3] = __expf(sacc[ni][3] - nm1);
            sum0 += sacc[ni][0] + sacc[ni][1];
            sum1 += sacc[ni][2] + sacc[ni][3];
        }
        sum0 += __shfl_xor_sync(full, sum0, 1);
        sum0 += __shfl_xor_sync(full, sum0, 2);
        sum1 += __shfl_xor_sync(full, sum1, 1);
        sum1 += __shfl_xor_sync(full, sum1, 2);
        l0 = l0 * fac0 + sum0; m0 = nm0;
        l1 = l1 * fac1 + sum1; m1 = nm1;

        // ---- store P to smem (warp-private rows) ----
        int q0 = w * 16 + g;
        #pragma unroll
        for (int ni = 0; ni < 8; ni++) {
            *(float2*)&Ps[q0 * PSTR + ni * 8 + 2 * tg] =
                make_float2(sacc[ni][0], sacc[ni][1]);
            *(float2*)&Ps[(q0 + 8) * PSTR + ni * 8 + 2 * tg] =
                make_float2(sacc[ni][2], sacc[ni][3]);
        }
        __syncwarp();

        // ---- rescale O, then PV: O[16 x 32] += P[16 x 64] * V[64 x 32] ----
        #pragma unroll
        for (int nd = 0; nd < 4; nd++) {
            O[nd][0] *= fac0; O[nd][1] *= fac0;
            O[nd][2] *= fac1; O[nd][3] *= fac1;
        }
        #pragma unroll
        for (int s = 0; s < 8; s++) {
            const float* pb = &Ps[q0 * PSTR + s * 8 + tg];
            uint32_t pa[4] = {
                f2tf32(pb[0]), f2tf32(pb[8 * PSTR]),
                f2tf32(pb[4]), f2tf32(pb[8 * PSTR + 4]) };
            #pragma unroll
            for (int nd = 0; nd < 4; nd++) {
                const float* vb = &Vs[(nd * 8 + g) * VSTR + s * 8 + tg];
                uint32_t bf[2] = { __float_as_uint(vb[0]), __float_as_uint(vb[4]) };
                mma1688(O[nd], pa, bf);
            }
        }
    }

    // ---- epilogue ----
    float inv0 = 1.f / l0, inv1 = 1.f / l1;
    #pragma unroll
    for (int nd = 0; nd < 4; nd++) {
        int c = h * HD + nd * 8 + 2 * tg;
        if (r0 < NQ)
            *(float2*)(out + ((size_t)(b * NQ + r0)) * DD + c) =
                make_float2(O[nd][0] * inv0, O[nd][1] * inv0);
        if (r1 < NQ)
            *(float2*)(out + ((size_t)(b * NQ + r1)) * DD + c) =
                make_float2(O[nd][2] * inv1, O[nd][3] * inv1);
    }
}

// ---------------- deformable sampling: warp = (head), block = (b,q) ---------
__global__ void sample_kernel(const float* __restrict__ mem, const float* __restrict__ ref,
                              const float* __restrict__ offs, const float* __restrict__ wts,
                              float* __restrict__ fused) {
    int row = blockIdx.x;
    int b = row / NQ;
    int h = threadIdx.x >> 5;
    int lane = threadIdx.x & 31;
    const unsigned full = 0xffffffffu;
    float rx = ref[row * 2], ry = ref[row * 2 + 1];
    float gx = 0.f, gy = 0.f, wl = 0.f;
    if (lane < PP) {
        float ox = offs[(size_t)row * (HH * PP * 2) + h * (PP * 2) + lane * 2];
        float oy = offs[(size_t)row * (HH * PP * 2) + h * (PP * 2) + lane * 2 + 1];
        gx = (rx + tanhf(ox) * 0.2f) * (float)BEV - 0.5f;
        gy = (ry + tanhf(oy) * 0.2f) * (float)BEV - 0.5f;
        wl = wts[(size_t)row * (HH * PP) + h * PP + lane];
    }
    float m = wl;
    m = fmaxf(m, __shfl_xor_sync(full, m, 1));
    m = fmaxf(m, __shfl_xor_sync(full, m, 2));
    float e = __expf(wl - m);
    float ssum = e;
    ssum += __shfl_xor_sync(full, ssum, 1);
    ssum += __shfl_xor_sync(full, ssum, 2);
    float w = e / ssum;
    const float* mb = mem + (size_t)b * (BEV * BEV) * DD + h * HD + lane;
    float acc = 0.f;
    #pragma unroll
    for (int p = 0; p < PP; p++) {
        float px = __shfl_sync(full, gx, p);
        float py = __shfl_sync(full, gy, p);
        float pw = __shfl_sync(full, w, p);
        float x0f = floorf(px), y0f = floorf(py);
        float wx1 = px - x0f, wy1 = py - y0f;
        float wx0 = 1.f - wx1, wy0 = 1.f - wy1;
        int x0 = (int)x0f, y0 = (int)y0f;
        bool xv0 = (x0 >= 0) && (x0 < BEV);
        bool xv1 = (x0 + 1 >= 0) && (x0 + 1 < BEV);
        bool yv0 = (y0 >= 0) && (y0 < BEV);
        bool yv1 = (y0 + 1 >= 0) && (y0 + 1 < BEV);
        float v = 0.f;
        if (yv0) {
            if (xv0) v += wx0 * wy0 * mb[(size_t)(y0 * BEV + x0) * DD];
            if (xv1) v += wx1 * wy0 * mb[(size_t)(y0 * BEV + x0 + 1) * DD];
        }
        if (yv1) {
            if (xv0) v += wx0 * wy1 * mb[(size_t)((y0 + 1) * BEV + x0) * DD];
            if (xv1) v += wx1 * wy1 * mb[(size_t)((y0 + 1) * BEV + x0 + 1) * DD];
        }
        acc += pw * v;
    }
    fused[(size_t)row * DD + h * HD + lane] = acc;
}

// ---------------- host launcher ---------------------------------------------
extern "C" void kernel_launch(void* const* d_in, const int* in_sizes, int n_in,
                              void* d_out, int out_size) {
    const float* query = (const float*)d_in[0];
    const float* memory = (const float*)d_in[1];
    const float* refp  = (const float*)d_in[2];
    const float* qpos  = (const float*)d_in[3];
    const float* in_w  = (const float*)d_in[4];
    const float* in_b  = (const float*)d_in[5];
    const float* out_w = (const float*)d_in[6];
    const float* out_b = (const float*)d_in[7];
    const float* off_w = (const float*)d_in[8];
    const float* off_b = (const float*)d_in[9];
    const float* wt_w  = (const float*)d_in[10];
    const float* wt_b  = (const float*)d_in[11];
    const float* co_w  = (const float*)d_in[12];
    const float* co_b  = (const float*)d_in[13];
    const float* f_w1  = (const float*)d_in[14];
    const float* f_b1  = (const float*)d_in[15];
    const float* f_w2  = (const float*)d_in[16];
    const float* f_b2  = (const float*)d_in[17];
    const float* n1s   = (const float*)d_in[18];
    const float* n1b   = (const float*)d_in[19];
    const float* n2s   = (const float*)d_in[20];
    const float* n2b   = (const float*)d_in[21];
    const float* n3s   = (const float*)d_in[22];
    const float* n3b   = (const float*)d_in[23];

    float *qin, *qkv, *attn, *q1, *q2, *offs, *wts, *fused, *qq2, *q3, *mid;
    cudaGetSymbolAddress((void**)&qin,   g_qin);
    cudaGetSymbolAddress((void**)&qkv,   g_qkv);
    cudaGetSymbolAddress((void**)&attn,  g_attn);
    cudaGetSymbolAddress((void**)&q1,    g_q1);
    cudaGetSymbolAddress((void**)&q2,    g_q2);
    cudaGetSymbolAddress((void**)&offs,  g_offs);
    cudaGetSymbolAddress((void**)&wts,   g_wts);
    cudaGetSymbolAddress((void**)&fused, g_fused);
    cudaGetSymbolAddress((void**)&qq2,   g_qq2);
    cudaGetSymbolAddress((void**)&q3,    g_q3);
    cudaGetSymbolAddress((void**)&mid,   g_mid);

    const int M = MROWS;
    const int MTC  = (M + 127) / 128;    // 57
    const int MT64 = (M + 63) / 64;      // 113
    const int LNG  = (M + 7) / 8;        // 900

    // 1. q_in = LN(query + query_pos)
    add_ln_warp<<<LNG, 256>>>(query, qpos, n1s, n1b, qin);
    // 2. qkv = q_in @ in_w^T + in_b
    gemm_tc<<<dim3(12, MTC), 256>>>(qin, in_w, in_b, nullptr, qkv, M, 768, 256, 0);
    // 3. self-attention (tensor-core flash, tf32)
    attn3_kernel<<<dim3((NQ + 63) / 64, HH, BB), 128>>>(qkv, attn);
    // 4. q1 = attn @ out_w^T + out_b + query
    gemm_tc<<<dim3(4, MTC), 256>>>(attn, out_w, out_b, query, q1, M, 256, 256, 0);
    // 5. q2 = LN(q1 + query_pos)
    add_ln_warp<<<LNG, 256>>>(q1, qpos, n2s, n2b, q2);
    // 6/7. offset + weight heads
    gemm_tc<<<dim3(1, MTC), 256>>>(q2, off_w, off_b, nullptr, offs, M, 64, 256, 0);
    gemm_nt<<<dim3(1, MT64), 256>>>(q2, wt_w, wt_b, nullptr, wts, M, 32, 256, 0);
    // 8. deformable BEV sampling -> fused
    sample_kernel<<<M, 256>>>(memory, refp, offs, wts, fused);
    // 9. qq2 = fused @ co_w^T + co_b + q1
    gemm_tc<<<dim3(4, MTC), 256>>>(fused, co_w, co_b, q1, qq2, M, 256, 256, 0);
    // 10. q3 = LN(qq2)
    add_ln_warp<<<LNG, 256>>>(qq2, nullptr, n3s, n3b, q3);
    // 11. mid = relu(q3 @ f_w1^T + f_b1)
    gemm_tc<<<dim3(8, MTC), 256>>>(q3, f_w1, f_b1, nullptr, mid, M, 512, 256, 1);
    // 12. out = mid @ f_w2^T + f_b2 + qq2
    gemm_tc<<<dim3(4, MTC), 256>>>(mid, f_w2, f_b2, qq2, (float*)d_out, M, 256, 512, 0);
    (void)in_sizes; (void)n_in; (void)out_size;
}

// round 8
// speedup vs baseline: 1.4409x; 1.4409x over previous
#include <cuda_runtime.h>
#include <cuda_bf16.h>
#include <math.h>
#include <stdint.h>

// Problem constants
#define BB    8
#define NQ    900
#define DD    256
#define HH    8
#define HD    32
#define PP    4
#define BEV   200
#define FFN   512
#define MROWS (BB * NQ)          // 7200

// ---------------- scratch (allocation-free: __device__ globals) -------------
__device__ float g_qin  [MROWS * DD];
__device__ float g_qkv  [MROWS * 3 * DD];
__device__ float g_attn [MROWS * DD];
__device__ float g_q1   [MROWS * DD];
__device__ float g_q2   [MROWS * DD];
__device__ float g_offs [MROWS * HH * PP * 2];
__device__ float g_wts  [MROWS * HH * PP];
__device__ float g_fused[MROWS * DD];
__device__ float g_qq2  [MROWS * DD];
__device__ float g_q3   [MROWS * DD];
__device__ float g_mid  [MROWS * FFN];

// ---------------- fused add + LayerNorm: warp per row, 8 rows/block ----------
__global__ void add_ln_warp(const float* __restrict__ a, const float* __restrict__ b,
                            const float* __restrict__ s, const float* __restrict__ bias,
                            float* __restrict__ out) {
    const unsigned full = 0xffffffffu;
    int w = threadIdx.x >> 5, lane = threadIdx.x & 31;
    int row = blockIdx.x * 8 + w;
    if (row >= MROWS) return;
    const float* ap = a + (size_t)row * DD;
    float4 x0 = *(const float4*)(ap + lane * 4);
    float4 x1 = *(const float4*)(ap + 128 + lane * 4);
    if (b) {
        const float* bp = b + (size_t)row * DD;
        float4 b0 = *(const float4*)(bp + lane * 4);
        float4 b1 = *(const float4*)(bp + 128 + lane * 4);
        x0.x += b0.x; x0.y += b0.y; x0.z += b0.z; x0.w += b0.w;
        x1.x += b1.x; x1.y += b1.y; x1.z += b1.z; x1.w += b1.w;
    }
    float sum = x0.x + x0.y + x0.z + x0.w + x1.x + x1.y + x1.z + x1.w;
    #pragma unroll
    for (int o = 16; o; o >>= 1) sum += __shfl_xor_sync(full, sum, o);
    float mean = sum * (1.f / DD);
    float c0x = x0.x - mean, c0y = x0.y - mean, c0z = x0.z - mean, c0w = x0.w - mean;
    float c1x = x1.x - mean, c1y = x1.y - mean, c1z = x1.z - mean, c1w = x1.w - mean;
    float vs = c0x*c0x + c0y*c0y + c0z*c0z + c0w*c0w
             + c1x*c1x + c1y*c1y + c1z*c1z + c1w*c1w;
    #pragma unroll
    for (int o = 16; o; o >>= 1) vs += __shfl_xor_sync(full, vs, o);
    float inv = rsqrtf(vs * (1.f / DD) + 1e-5f);
    float4 s0 = *(const float4*)(s + lane * 4);
    float4 s1 = *(const float4*)(s + 128 + lane * 4);
    float4 g0 = *(const float4*)(bias + lane * 4);
    float4 g1 = *(const float4*)(bias + 128 + lane * 4);
    float* op = out + (size_t)row * DD;
    *(float4*)(op + lane * 4) = make_float4(
        c0x * inv * s0.x + g0.x, c0y * inv * s0.y + g0.y,
        c0z * inv * s0.z + g0.z, c0w * inv * s0.w + g0.w);
    *(float4*)(op + 128 + lane * 4) = make_float4(
        c1x * inv * s1.x + g1.x, c1y * inv * s1.y + g1.y,
        c1z * inv * s1.z + g1.z, c1w * inv * s1.w + g1.w);
}

// ---------------- tf32 helpers ----------------------------------------------
__device__ __forceinline__ uint32_t f2tf32(float f) {
    uint32_t u;
    asm("cvt.rna.tf32.f32 %0, %1;" : "=r"(u) : "f"(f));
    return u;
}

__device__ __forceinline__ void mma1688(float* d, const uint32_t* a, const uint32_t* b) {
    asm volatile(
        "mma.sync.aligned.m16n8k8.row.col.f32.tf32.tf32.f32 "
        "{%0,%1,%2,%3}, {%4,%5,%6,%7}, {%8,%9}, {%0,%1,%2,%3};\n"
        : "+f"(d[0]), "+f"(d[1]), "+f"(d[2]), "+f"(d[3])
        : "r"(a[0]), "r"(a[1]), "r"(a[2]), "r"(a[3]), "r"(b[0]), "r"(b[1]));
}

// ---------------- tensor-core NT GEMM (tf32): C = A*B^T + epi ---------------
// Round-4 proven config: 128x64 tile, BK=16, single-buffer smem, reg prefetch,
// 8 warps 4x2, 2 CTAs/SM.
#define SSTR 20
__global__ __launch_bounds__(256, 2)
void gemm_tc(const float* __restrict__ A, const float* __restrict__ B,
             const float* __restrict__ bias, const float* __restrict__ resid,
             float* __restrict__ C, int M, int N, int K, int relu) {
    __shared__ uint32_t As[128 * SSTR];
    __shared__ uint32_t Bs[64 * SSTR];
    const int tid = threadIdx.x;
    const int lane = tid & 31, wid = tid >> 5;
    const int g = lane >> 2, tg = lane & 3;
    const int wm = (wid >> 1) * 32, wn = (wid & 1) * 32;
    const int bm = blockIdx.y * 128, bn = blockIdx.x * 64;

    const int rowA0 = tid >> 2, rowA1 = rowA0 + 64;
    const int rowB  = tid >> 2;            // 0..63
    const int kq    = (tid & 3) * 4;

    float4 pa[2], pb;
    const float4 z4 = make_float4(0.f, 0.f, 0.f, 0.f);

    {
        int gm0 = bm + rowA0, gm1 = bm + rowA1;
        pa[0] = (gm0 < M) ? *(const float4*)(A + (size_t)gm0 * K + kq) : z4;
        pa[1] = (gm1 < M) ? *(const float4*)(A + (size_t)gm1 * K + kq) : z4;
        pb    = *(const float4*)(B + (size_t)(bn + rowB) * K + kq);
    }

    float acc[2][4][4];
    #pragma unroll
    for (int mi = 0; mi < 2; mi++)
        #pragma unroll
        for (int ni = 0; ni < 4; ni++)
            #pragma unroll
            for (int r = 0; r < 4; r++) acc[mi][ni][r] = 0.f;

    for (int k0 = 0; k0 < K; k0 += 16) {
        *(uint4*)&As[rowA0 * SSTR + kq] =
            make_uint4(f2tf32(pa[0].x), f2tf32(pa[0].y), f2tf32(pa[0].z), f2tf32(pa[0].w));
        *(uint4*)&As[rowA1 * SSTR + kq] =
            make_uint4(f2tf32(pa[1].x), f2tf32(pa[1].y), f2tf32(pa[1].z), f2tf32(pa[1].w));
        *(uint4*)&Bs[rowB * SSTR + kq] =
            make_uint4(f2tf32(pb.x), f2tf32(pb.y), f2tf32(pb.z), f2tf32(pb.w));
        __syncthreads();
        if (k0 + 16 < K) {
            int kn = k0 + 16;
            int gm0 = bm + rowA0, gm1 = bm + rowA1;
            pa[0] = (gm0 < M) ? *(const float4*)(A + (size_t)gm0 * K + kn + kq) : z4;
            pa[1] = (gm1 < M) ? *(const float4*)(A + (size_t)gm1 * K + kn + kq) : z4;
            pb    = *(const float4*)(B + (size_t)(bn + rowB) * K + kn + kq);
        }
        #pragma unroll
        for (int k8 = 0; k8 < 2; k8++) {
            uint32_t af[2][4], bf[4][2];
            #pragma unroll
            for (int mi = 0; mi < 2; mi++) {
                const uint32_t* base = &As[(wm + mi * 16 + g) * SSTR + k8 * 8 + tg];
                af[mi][0] = base[0];
                af[mi][1] = base[8 * SSTR];
                af[mi][2] = base[4];
                af[mi][3] = base[8 * SSTR + 4];
            }
            #pragma unroll
            for (int ni = 0; ni < 4; ni++) {
                const uint32_t* base = &Bs[(wn + ni * 8 + g) * SSTR + k8 * 8 + tg];
                bf[ni][0] = base[0];
                bf[ni][1] = base[4];
            }
            #pragma unroll
            for (int mi = 0; mi < 2; mi++)
                #pragma unroll
                for (int ni = 0; ni < 4; ni++)
                    mma1688(acc[mi][ni], af[mi], bf[ni]);
        }
        __syncthreads();
    }

    #pragma unroll
    for (int ni = 0; ni < 4; ni++) {
        int c = bn + wn + ni * 8 + 2 * tg;
        float b0 = bias ? bias[c] : 0.f;
        float b1 = bias ? bias[c + 1] : 0.f;
        #pragma unroll
        for (int mi = 0; mi < 2; mi++) {
            int r0 = bm + wm + mi * 16 + g;
            int r1 = r0 + 8;
            float v0 = acc[mi][ni][0] + b0, v1 = acc[mi][ni][1] + b1;
            float v2 = acc[mi][ni][2] + b0, v3 = acc[mi][ni][3] + b1;
            if (relu) {
                v0 = fmaxf(v0, 0.f); v1 = fmaxf(v1, 0.f);
                v2 = fmaxf(v2, 0.f); v3 = fmaxf(v3, 0.f);
            }
            if (r0 < M) {
                if (resid) {
                    float2 rr = *(const float2*)(resid + (size_t)r0 * N + c);
                    v0 += rr.x; v1 += rr.y;
                }
                *(float2*)(C + (size_t)r0 * N + c) = make_float2(v0, v1);
            }
            if (r1 < M) {
                if (resid) {
                    float2 rr = *(const float2*)(resid + (size_t)r1 * N + c);
                    v2 += rr.x; v3 += rr.y;
                }
                *(float2*)(C + (size_t)r1 * N + c) = make_float2(v2, v3);
            }
        }
    }
}

// ---------------- small NT GEMM (N=32 weights head) --------------------------
__global__ void gemm_nt(const float* __restrict__ A, const float* __restrict__ B,
                        const float* __restrict__ bias, const float* __restrict__ resid,
                        float* __restrict__ C, int M, int N, int K, int relu) {
    __shared__ float As[16][68];
    __shared__ float Bs[16][68];
    int tid = threadIdx.x;
    int tx = tid & 15, ty = tid >> 4;
    int bm = blockIdx.y * 64, bn = blockIdx.x * 64;
    int lm = tid >> 2;
    int kq = (tid & 3) * 4;
    float acc[4][4] = {};
    for (int k0 = 0; k0 < K; k0 += 16) {
        int gm = bm + lm;
        float4 va = make_float4(0.f, 0.f, 0.f, 0.f);
        if (gm < M) va = *(const float4*)(A + (size_t)gm * K + k0 + kq);
        As[kq + 0][lm] = va.x; As[kq + 1][lm] = va.y;
        As[kq + 2][lm] = va.z; As[kq + 3][lm] = va.w;
        int gn = bn + lm;
        float4 vb = make_float4(0.f, 0.f, 0.f, 0.f);
        if (gn < N) vb = *(const float4*)(B + (size_t)gn * K + k0 + kq);
        Bs[kq + 0][lm] = vb.x; Bs[kq + 1][lm] = vb.y;
        Bs[kq + 2][lm] = vb.z; Bs[kq + 3][lm] = vb.w;
        __syncthreads();
        #pragma unroll
        for (int k = 0; k < 16; k++) {
            float4 a4 = *(const float4*)&As[k][ty * 4];
            float4 b4 = *(const float4*)&Bs[k][tx * 4];
            float af[4] = {a4.x, a4.y, a4.z, a4.w};
            float bf[4] = {b4.x, b4.y, b4.z, b4.w};
            #pragma unroll
            for (int i = 0; i < 4; i++)
                #pragma unroll
                for (int j = 0; j < 4; j++)
                    acc[i][j] += af[i] * bf[j];
        }
        __syncthreads();
    }
    #pragma unroll
    for (int i = 0; i < 4; i++) {
        int r = bm + ty * 4 + i;
        if (r >= M) continue;
        #pragma unroll
        for (int j = 0; j < 4; j++) {
            int c = bn + tx * 4 + j;
            if (c >= N) continue;
            float v = acc[i][j];
            if (bias) v += bias[c];
            if (relu) v = fmaxf(v, 0.f);
            if (resid) v += resid[(size_t)r * N + c];
            C[(size_t)r * N + c] = v;
        }
    }
}

// ---------------- tensor-core flash attention (tf32, round-4 proven) ---------
// 64-query blocks, 4 warps (16 q each), 64-key tiles, HD=32.
#define KSTR 36
#define VSTR 68
#define PSTR 68
__global__ __launch_bounds__(128)
void attn3_kernel(const float* __restrict__ qkv, float* __restrict__ out) {
    __shared__ float Ks[64 * KSTR];   // K tile [key][d]
    __shared__ float Vs[32 * VSTR];   // V tile transposed [d][key]
    __shared__ float Ps[64 * PSTR];   // P [q][key]

    const int b = blockIdx.z, h = blockIdx.y, qt = blockIdx.x;
    const int tid = threadIdx.x;
    const int w = tid >> 5, lane = tid & 31;
    const int g = lane >> 2, tg = lane & 3;
    const float scale = 0.17677669529663687f;   // 1/sqrt(32)
    const unsigned full = 0xffffffffu;

    // ---- Q fragments (held in registers for whole kernel), pre-scaled ----
    const int r0 = qt * 64 + w * 16 + g;
    const int r1 = r0 + 8;
    uint32_t qa[4][4];
    {
        const float* q0p = qkv + ((size_t)(b * NQ + (r0 < NQ ? r0 : 0))) * 768 + h * HD;
        const float* q1p = qkv + ((size_t)(b * NQ + (r1 < NQ ? r1 : 0))) * 768 + h * HD;
        bool v0 = r0 < NQ, v1 = r1 < NQ;
        #pragma unroll
        for (int s = 0; s < 4; s++) {
            int c0 = s * 8 + tg, c1 = c0 + 4;
            qa[s][0] = v0 ? f2tf32(q0p[c0] * scale) : 0u;
            qa[s][1] = v1 ? f2tf32(q1p[c0] * scale) : 0u;
            qa[s][2] = v0 ? f2tf32(q0p[c1] * scale) : 0u;
            qa[s][3] = v1 ? f2tf32(q1p[c1] * scale) : 0u;
        }
    }

    float m0 = -INFINITY, m1 = -INFINITY, l0 = 0.f, l1 = 0.f;
    float O[4][4];
    #pragma unroll
    for (int nd = 0; nd < 4; nd++)
        #pragma unroll
        for (int r = 0; r < 4; r++) O[nd][r] = 0.f;

    const int NKT = (NQ + 63) / 64;   // 15
    for (int jt = 0; jt < NKT; jt++) {
        __syncthreads();
        // ---- load K tile (cvt'd) and V tile transposed (cvt'd) ----
        {
            int key = tid >> 1, dh = (tid & 1) * 16;
            int kk = jt * 64 + key;
            if (kk < NQ) {
                const float* srcK = qkv + ((size_t)(b * NQ + kk)) * 768 + 256 + h * HD + dh;
                const float* srcV = srcK + 256;
                #pragma unroll
                for (int i = 0; i < 4; i++) {
                    float4 kv = *(const float4*)(srcK + i * 4);
                    *(float4*)&Ks[key * KSTR + dh + i * 4] = make_float4(
                        __uint_as_float(f2tf32(kv.x)), __uint_as_float(f2tf32(kv.y)),
                        __uint_as_float(f2tf32(kv.z)), __uint_as_float(f2tf32(kv.w)));
                    float4 vv = *(const float4*)(srcV + i * 4);
                    Vs[(dh + i * 4 + 0) * VSTR + key] = __uint_as_float(f2tf32(vv.x));
                    Vs[(dh + i * 4 + 1) * VSTR + key] = __uint_as_float(f2tf32(vv.y));
                    Vs[(dh + i * 4 + 2) * VSTR + key] = __uint_as_float(f2tf32(vv.z));
                    Vs[(dh + i * 4 + 3) * VSTR + key] = __uint_as_float(f2tf32(vv.w));
                }
            } else {
                #pragma unroll
                for (int i = 0; i < 4; i++) {
                    *(float4*)&Ks[key * KSTR + dh + i * 4] = make_float4(0.f, 0.f, 0.f, 0.f);
                    Vs[(dh + i * 4 + 0) * VSTR + key] = 0.f;
                    Vs[(dh + i * 4 + 1) * VSTR + key] = 0.f;
                    Vs[(dh + i * 4 + 2) * VSTR + key] = 0.f;
                    Vs[(dh + i * 4 + 3) * VSTR + key] = 0.f;
                }
            }
        }
        __syncthreads();

        // ---- QK: S[16 x 64] per warp ----
        float sacc[8][4];
        #pragma unroll
        for (int ni = 0; ni < 8; ni++)
            #pragma unroll
            for (int r = 0; r < 4; r++) sacc[ni][r] = 0.f;
        #pragma unroll
        for (int s = 0; s < 4; s++) {
            #pragma unroll
            for (int ni = 0; ni < 8; ni++) {
                const float* base = &Ks[(ni * 8 + g) * KSTR + s * 8 + tg];
                uint32_t bf[2] = { __float_as_uint(base[0]), __float_as_uint(base[4]) };
                mma1688(sacc[ni], qa[s], bf);
            }
        }
        // ---- mask invalid keys ----
        int kglob = jt * 64;
        if (kglob + 64 > NQ) {
            #pragma unroll
            for (int ni = 0; ni < 8; ni++) {
                int kc = kglob + ni * 8 + 2 * tg;
                if (kc >= NQ)     { sacc[ni][0] = -1e30f; sacc[ni][2] = -1e30f; }
                if (kc + 1 >= NQ) { sacc[ni][1] = -1e30f; sacc[ni][3] = -1e30f; }
            }
        }

        // ---- online softmax (rows g and g+8; quad reduce over tg lanes) ----
        float mx0 = -INFINITY, mx1 = -INFINITY;
        #pragma unroll
        for (int ni = 0; ni < 8; ni++) {
            mx0 = fmaxf(mx0, fmaxf(sacc[ni][0], sacc[ni][1]));
            mx1 = fmaxf(mx1, fmaxf(sacc[ni][2], sacc[ni][3]));
        }
        mx0 = fmaxf(mx0, __shfl_xor_sync(full, mx0, 1));
        mx0 = fmaxf(mx0, __shfl_xor_sync(full, mx0, 2));
        mx1 = fmaxf(mx1, __shfl_xor_sync(full, mx1, 1));
        mx1 = fmaxf(mx1, __shfl_xor_sync(full, mx1, 2));
        float nm0 = fmaxf(m0, mx0), nm1 = fmaxf(m1, mx1);
        float fac0 = __expf(m0 - nm0), fac1 = __expf(m1 - nm1);
        float sum0 = 0.f, sum1 = 0.f;
        #pragma unroll
        for (int ni = 0; ni < 8; ni++) {
            sacc[ni][0] = __expf(sacc[ni][0] - nm0);
            sacc[ni][1] = __expf(sacc[ni][1] - nm0);
            sacc[ni][2] = __expf(sacc[ni][2] - nm1);
            sacc[ni][3] = __expf(sacc[ni][3] - nm1);
            sum0 += sacc[ni][0] + sacc[ni][1];
            sum1 += sacc[ni][2] + sacc[ni][3];
        }
        sum0 += __shfl_xor_sync(full, sum0, 1);
        sum0 += __shfl_xor_sync(full, sum0, 2);
        sum1 += __shfl_xor_sync(full, sum1, 1);
        sum1 += __shfl_xor_sync(full, sum1, 2);
        l0 = l0 * fac0 + sum0; m0 = nm0;
        l1 = l1 * fac1 + sum1; m1 = nm1;

        // ---- store P to smem (warp-private rows) ----
        int q0 = w * 16 + g;
        #pragma unroll
        for (int ni = 0; ni < 8; ni++) {
            *(float2*)&Ps[q0 * PSTR + ni * 8 + 2 * tg] =
                make_float2(sacc[ni][0], sacc[ni][1]);
            *(float2*)&Ps[(q0 + 8) * PSTR + ni * 8 + 2 * tg] =
                make_float2(sacc[ni][2], sacc[ni][3]);
        }
        __syncwarp();

        // ---- rescale O, then PV: O[16 x 32] += P[16 x 64] * V[64 x 32] ----
        #pragma unroll
        for (int nd = 0; nd < 4; nd++) {
            O[nd][0] *= fac0; O[nd][1] *= fac0;
            O[nd][2] *= fac1; O[nd][3] *= fac1;
        }
        #pragma unroll
        for (int s = 0; s < 8; s++) {
            const float* pb = &Ps[q0 * PSTR + s * 8 + tg];
            uint32_t pa[4] = {
                f2tf32(pb[0]), f2tf32(pb[8 * PSTR]),
                f2tf32(pb[4]), f2tf32(pb[8 * PSTR + 4]) };
            #pragma unroll
            for (int nd = 0; nd < 4; nd++) {
                const float* vb = &Vs[(nd * 8 + g) * VSTR + s * 8 + tg];
                uint32_t bf[2] = { __float_as_uint(vb[0]), __float_as_uint(vb[4]) };
                mma1688(O[nd], pa, bf);
            }
        }
    }

    // ---- epilogue ----
    float inv0 = 1.f / l0, inv1 = 1.f / l1;
    #pragma unroll
    for (int nd = 0; nd < 4; nd++) {
        int c = h * HD + nd * 8 + 2 * tg;
        if (r0 < NQ)
            *(float2*)(out + ((size_t)(b * NQ + r0)) * DD + c) =
                make_float2(O[nd][0] * inv0, O[nd][1] * inv0);
        if (r1 < NQ)
            *(float2*)(out + ((size_t)(b * NQ + r1)) * DD + c) =
                make_float2(O[nd][2] * inv1, O[nd][3] * inv1);
    }
}

// ---------------- deformable sampling: warp = (head), block = (b,q) ---------
__global__ void sample_kernel(const float* __restrict__ mem, const float* __restrict__ ref,
                              const float* __restrict__ offs, const float* __restrict__ wts,
                              float* __restrict__ fused) {
    int row = blockIdx.x;
    int b = row / NQ;
    int h = threadIdx.x >> 5;
    int lane = threadIdx.x & 31;
    const unsigned full = 0xffffffffu;
    float rx = ref[row * 2], ry = ref[row * 2 + 1];
    float gx = 0.f, gy = 0.f, wl = 0.f;
    if (lane < PP) {
        float ox = offs[(size_t)row * (HH * PP * 2) + h * (PP * 2) + lane * 2];
        float oy = offs[(size_t)row * (HH * PP * 2) + h * (PP * 2) + lane * 2 + 1];
        gx = (rx + tanhf(ox) * 0.2f) * (float)BEV - 0.5f;
        gy = (ry + tanhf(oy) * 0.2f) * (float)BEV - 0.5f;
        wl = wts[(size_t)row * (HH * PP) + h * PP + lane];
    }
    float m = wl;
    m = fmaxf(m, __shfl_xor_sync(full, m, 1));
    m = fmaxf(m, __shfl_xor_sync(full, m, 2));
    float e = __expf(wl - m);
    float ssum = e;
    ssum += __shfl_xor_sync(full, ssum, 1);
    ssum += __shfl_xor_sync(full, ssum, 2);
    float w = e / ssum;
    const float* mb = mem + (size_t)b * (BEV * BEV) * DD + h * HD + lane;
    float acc = 0.f;
    #pragma unroll
    for (int p = 0; p < PP; p++) {
        float px = __shfl_sync(full, gx, p);
        float py = __shfl_sync(full, gy, p);
        float pw = __shfl_sync(full, w, p);
        float x0f = floorf(px), y0f = floorf(py);
        float wx1 = px - x0f, wy1 = py - y0f;
        float wx0 = 1.f - wx1, wy0 = 1.f - wy1;
        int x0 = (int)x0f, y0 = (int)y0f;
        bool xv0 = (x0 >= 0) && (x0 < BEV);
        bool xv1 = (x0 + 1 >= 0) && (x0 + 1 < BEV);
        bool yv0 = (y0 >= 0) && (y0 < BEV);
        bool yv1 = (y0 + 1 >= 0) && (y0 + 1 < BEV);
        float v = 0.f;
        if (yv0) {
            if (xv0) v += wx0 * wy0 * mb[(size_t)(y0 * BEV + x0) * DD];
            if (xv1) v += wx1 * wy0 * mb[(size_t)(y0 * BEV + x0 + 1) * DD];
        }
        if (yv1) {
            if (xv0) v += wx0 * wy1 * mb[(size_t)((y0 + 1) * BEV + x0) * DD];
            if (xv1) v += wx1 * wy1 * mb[(size_t)((y0 + 1) * BEV + x0 + 1) * DD];
        }
        acc += pw * v;
    }
    fused[(size_t)row * DD + h * HD + lane] = acc;
}

// ---------------- host launcher ---------------------------------------------
extern "C" void kernel_launch(void* const* d_in, const int* in_sizes, int n_in,
                              void* d_out, int out_size) {
    const float* query = (const float*)d_in[0];
    const float* memory = (const float*)d_in[1];
    const float* refp  = (const float*)d_in[2];
    const float* qpos  = (const float*)d_in[3];
    const float* in_w  = (const float*)d_in[4];
    const float* in_b  = (const float*)d_in[5];
    const float* out_w = (const float*)d_in[6];
    const float* out_b = (const float*)d_in[7];
    const float* off_w = (const float*)d_in[8];
    const float* off_b = (const float*)d_in[9];
    const float* wt_w  = (const float*)d_in[10];
    const float* wt_b  = (const float*)d_in[11];
    const float* co_w  = (const float*)d_in[12];
    const float* co_b  = (const float*)d_in[13];
    const float* f_w1  = (const float*)d_in[14];
    const float* f_b1  = (const float*)d_in[15];
    const float* f_w2  = (const float*)d_in[16];
    const float* f_b2  = (const float*)d_in[17];
    const float* n1s   = (const float*)d_in[18];
    const float* n1b   = (const float*)d_in[19];
    const float* n2s   = (const float*)d_in[20];
    const float* n2b   = (const float*)d_in[21];
    const float* n3s   = (const float*)d_in[22];
    const float* n3b   = (const float*)d_in[23];

    float *qin, *qkv, *attn, *q1, *q2, *offs, *wts, *fused, *qq2, *q3, *mid;
    cudaGetSymbolAddress((void**)&qin,   g_qin);
    cudaGetSymbolAddress((void**)&qkv,   g_qkv);
    cudaGetSymbolAddress((void**)&attn,  g_attn);
    cudaGetSymbolAddress((void**)&q1,    g_q1);
    cudaGetSymbolAddress((void**)&q2,    g_q2);
    cudaGetSymbolAddress((void**)&offs,  g_offs);
    cudaGetSymbolAddress((void**)&wts,   g_wts);
    cudaGetSymbolAddress((void**)&fused, g_fused);
    cudaGetSymbolAddress((void**)&qq2,   g_qq2);
    cudaGetSymbolAddress((void**)&q3,    g_q3);
    cudaGetSymbolAddress((void**)&mid,   g_mid);

    const int M = MROWS;
    const int MTC  = (M + 127) / 128;    // 57
    const int MT64 = (M + 63) / 64;      // 113
    const int LNG  = (M + 7) / 8;        // 900

    // 1. q_in = LN(query + query_pos)
    add_ln_warp<<<LNG, 256>>>(query, qpos, n1s, n1b, qin);
    // 2. qkv = q_in @ in_w^T + in_b
    gemm_tc<<<dim3(12, MTC), 256>>>(qin, in_w, in_b, nullptr, qkv, M, 768, 256, 0);
    // 3. self-attention (tensor-core flash, tf32)
    attn3_kernel<<<dim3((NQ + 63) / 64, HH, BB), 128>>>(qkv, attn);
    // 4. q1 = attn @ out_w^T + out_b + query
    gemm_tc<<<dim3(4, MTC), 256>>>(attn, out_w, out_b, query, q1, M, 256, 256, 0);
    // 5. q2 = LN(q1 + query_pos)
    add_ln_warp<<<LNG, 256>>>(q1, qpos, n2s, n2b, q2);
    // 6/7. offset + weight heads
    gemm_tc<<<dim3(1, MTC), 256>>>(q2, off_w, off_b, nullptr, offs, M, 64, 256, 0);
    gemm_nt<<<dim3(1, MT64), 256>>>(q2, wt_w, wt_b, nullptr, wts, M, 32, 256, 0);
    // 8. deformable BEV sampling -> fused
    sample_kernel<<<M, 256>>>(memory, refp, offs, wts, fused);
    // 9. qq2 = fused @ co_w^T + co_b + q1
    gemm_tc<<<dim3(4, MTC), 256>>>(fused, co_w, co_b, q1, qq2, M, 256, 256, 0);
    // 10. q3 = LN(qq2)
    add_ln_warp<<<LNG, 256>>>(qq2, nullptr, n3s, n3b, q3);
    // 11. mid = relu(q3 @ f_w1^T + f_b1)
    gemm_tc<<<dim3(8, MTC), 256>>>(q3, f_w1, f_b1, nullptr, mid, M, 512, 256, 1);
    // 12. out = mid @ f_w2^T + f_b2 + qq2
    gemm_tc<<<dim3(4, MTC), 256>>>(mid, f_w2, f_b2, qq2, (float*)d_out, M, 256, 512, 0);
    (void)in_sizes; (void)n_in; (void)out_size;
}

// round 11
// speedup vs baseline: 1.4810x; 1.0278x over previous
#include <cuda_runtime.h>
#include <cuda_bf16.h>
#include <math.h>
#include <stdint.h>

// Problem constants
#define BB    8
#define NQ    900
#define DD    256
#define HH    8
#define HD    32
#define PP    4
#define BEV   200
#define FFN   512
#define MROWS (BB * NQ)          // 7200

// ---------------- scratch (allocation-free: __device__ globals) -------------
__device__ float g_qin  [MROWS * DD];
__device__ float g_qkv  [MROWS * 3 * DD];
__device__ float g_attn [MROWS * DD];
__device__ float g_q1   [MROWS * DD];
__device__ float g_q2   [MROWS * DD];
__device__ float g_offs [MROWS * HH * PP * 2];
__device__ float g_wts  [MROWS * HH * PP];
__device__ float g_fused[MROWS * DD];
__device__ float g_qq2  [MROWS * DD];
__device__ float g_q3   [MROWS * DD];
__device__ float g_mid  [MROWS * FFN];

// ---------------- fused add + LayerNorm: warp per row, 8 rows/block ----------
__global__ void add_ln_warp(const float* __restrict__ a, const float* __restrict__ b,
                            const float* __restrict__ s, const float* __restrict__ bias,
                            float* __restrict__ out) {
    const unsigned full = 0xffffffffu;
    int w = threadIdx.x >> 5, lane = threadIdx.x & 31;
    int row = blockIdx.x * 8 + w;
    if (row >= MROWS) return;
    const float* ap = a + (size_t)row * DD;
    float4 x0 = *(const float4*)(ap + lane * 4);
    float4 x1 = *(const float4*)(ap + 128 + lane * 4);
    if (b) {
        const float* bp = b + (size_t)row * DD;
        float4 b0 = *(const float4*)(bp + lane * 4);
        float4 b1 = *(const float4*)(bp + 128 + lane * 4);
        x0.x += b0.x; x0.y += b0.y; x0.z += b0.z; x0.w += b0.w;
        x1.x += b1.x; x1.y += b1.y; x1.z += b1.z; x1.w += b1.w;
    }
    float sum = x0.x + x0.y + x0.z + x0.w + x1.x + x1.y + x1.z + x1.w;
    #pragma unroll
    for (int o = 16; o; o >>= 1) sum += __shfl_xor_sync(full, sum, o);
    float mean = sum * (1.f / DD);
    float c0x = x0.x - mean, c0y = x0.y - mean, c0z = x0.z - mean, c0w = x0.w - mean;
    float c1x = x1.x - mean, c1y = x1.y - mean, c1z = x1.z - mean, c1w = x1.w - mean;
    float vs = c0x*c0x + c0y*c0y + c0z*c0z + c0w*c0w
             + c1x*c1x + c1y*c1y + c1z*c1z + c1w*c1w;
    #pragma unroll
    for (int o = 16; o; o >>= 1) vs += __shfl_xor_sync(full, vs, o);
    float inv = rsqrtf(vs * (1.f / DD) + 1e-5f);
    float4 s0 = *(const float4*)(s + lane * 4);
    float4 s1 = *(const float4*)(s + 128 + lane * 4);
    float4 g0 = *(const float4*)(bias + lane * 4);
    float4 g1 = *(const float4*)(bias + 128 + lane * 4);
    float* op = out + (size_t)row * DD;
    *(float4*)(op + lane * 4) = make_float4(
        c0x * inv * s0.x + g0.x, c0y * inv * s0.y + g0.y,
        c0z * inv * s0.z + g0.z, c0w * inv * s0.w + g0.w);
    *(float4*)(op + 128 + lane * 4) = make_float4(
        c1x * inv * s1.x + g1.x, c1y * inv * s1.y + g1.y,
        c1z * inv * s1.z + g1.z, c1w * inv * s1.w + g1.w);
}

// ---------------- tf32 helpers ----------------------------------------------
__device__ __forceinline__ uint32_t f2tf32(float f) {
    uint32_t u;
    asm("cvt.rna.tf32.f32 %0, %1;" : "=r"(u) : "f"(f));
    return u;
}

__device__ __forceinline__ void mma1688(float* d, const uint32_t* a, const uint32_t* b) {
    asm volatile(
        "mma.sync.aligned.m16n8k8.row.col.f32.tf32.tf32.f32 "
        "{%0,%1,%2,%3}, {%4,%5,%6,%7}, {%8,%9}, {%0,%1,%2,%3};\n"
        : "+f"(d[0]), "+f"(d[1]), "+f"(d[2]), "+f"(d[3])
        : "r"(a[0]), "r"(a[1]), "r"(a[2]), "r"(a[3]), "r"(b[0]), "r"(b[1]));
}

// ---------------- tensor-core NT GEMM (tf32): C = A*B^T + epi ---------------
// 128x64 tile, BK=16, single-buffer smem, reg prefetch, 8 warps 4x2, 2 CTAs/SM.
// Logical-k permutation: mma lane-k (tg, tg+4) reads physical (2tg, 2tg+1)
// -> all fragment pair loads are single LDS.64. SSTR=24 is 64-bit conflict-free
// (fragment word = row*12 + 4*k8 + tg -> 12g+tg mod 32 all-distinct).
#define SSTR 24
__global__ __launch_bounds__(256, 2)
void gemm_tc(const float* __restrict__ A, const float* __restrict__ B,
             const float* __restrict__ bias, const float* __restrict__ resid,
             float* __restrict__ C, int M, int N, int K, int relu) {
    __shared__ __align__(16) uint32_t As[128 * SSTR];
    __shared__ __align__(16) uint32_t Bs[64 * SSTR];
    const int tid = threadIdx.x;
    const int lane = tid & 31, wid = tid >> 5;
    const int g = lane >> 2, tg = lane & 3;
    const int wm = (wid >> 1) * 32, wn = (wid & 1) * 32;
    const int bm = blockIdx.y * 128, bn = blockIdx.x * 64;

    const int rowA0 = tid >> 2, rowA1 = rowA0 + 64;
    const int rowB  = tid >> 2;            // 0..63
    const int kq    = (tid & 3) * 4;

    float4 pa[2], pb;
    const float4 z4 = make_float4(0.f, 0.f, 0.f, 0.f);

    {
        int gm0 = bm + rowA0, gm1 = bm + rowA1;
        pa[0] = (gm0 < M) ? *(const float4*)(A + (size_t)gm0 * K + kq) : z4;
        pa[1] = (gm1 < M) ? *(const float4*)(A + (size_t)gm1 * K + kq) : z4;
        pb    = *(const float4*)(B + (size_t)(bn + rowB) * K + kq);
    }

    float acc[2][4][4];
    #pragma unroll
    for (int mi = 0; mi < 2; mi++)
        #pragma unroll
        for (int ni = 0; ni < 4; ni++)
            #pragma unroll
            for (int r = 0; r < 4; r++) acc[mi][ni][r] = 0.f;

    for (int k0 = 0; k0 < K; k0 += 16) {
        *(uint4*)&As[rowA0 * SSTR + kq] =
            make_uint4(f2tf32(pa[0].x), f2tf32(pa[0].y), f2tf32(pa[0].z), f2tf32(pa[0].w));
        *(uint4*)&As[rowA1 * SSTR + kq] =
            make_uint4(f2tf32(pa[1].x), f2tf32(pa[1].y), f2tf32(pa[1].z), f2tf32(pa[1].w));
        *(uint4*)&Bs[rowB * SSTR + kq] =
            make_uint4(f2tf32(pb.x), f2tf32(pb.y), f2tf32(pb.z), f2tf32(pb.w));
        __syncthreads();
        if (k0 + 16 < K) {
            int kn = k0 + 16;
            int gm0 = bm + rowA0, gm1 = bm + rowA1;
            pa[0] = (gm0 < M) ? *(const float4*)(A + (size_t)gm0 * K + kn + kq) : z4;
            pa[1] = (gm1 < M) ? *(const float4*)(A + (size_t)gm1 * K + kn + kq) : z4;
            pb    = *(const float4*)(B + (size_t)(bn + rowB) * K + kn + kq);
        }
        #pragma unroll
        for (int k8 = 0; k8 < 2; k8++) {
            uint32_t af[2][4], bf[4][2];
            #pragma unroll
            for (int mi = 0; mi < 2; mi++) {
                const uint32_t* base = &As[(wm + mi * 16 + g) * SSTR + k8 * 8 + 2 * tg];
                uint2 lo = *(const uint2*)base;
                uint2 hi = *(const uint2*)(base + 8 * SSTR);
                af[mi][0] = lo.x; af[mi][2] = lo.y;
                af[mi][1] = hi.x; af[mi][3] = hi.y;
            }
            #pragma unroll
            for (int ni = 0; ni < 4; ni++) {
                uint2 v = *(const uint2*)&Bs[(wn + ni * 8 + g) * SSTR + k8 * 8 + 2 * tg];
                bf[ni][0] = v.x; bf[ni][1] = v.y;
            }
            #pragma unroll
            for (int mi = 0; mi < 2; mi++)
                #pragma unroll
                for (int ni = 0; ni < 4; ni++)
                    mma1688(acc[mi][ni], af[mi], bf[ni]);
        }
        __syncthreads();
    }

    #pragma unroll
    for (int ni = 0; ni < 4; ni++) {
        int c = bn + wn + ni * 8 + 2 * tg;
        float b0 = bias ? bias[c] : 0.f;
        float b1 = bias ? bias[c + 1] : 0.f;
        #pragma unroll
        for (int mi = 0; mi < 2; mi++) {
            int r0 = bm + wm + mi * 16 + g;
            int r1 = r0 + 8;
            float v0 = acc[mi][ni][0] + b0, v1 = acc[mi][ni][1] + b1;
            float v2 = acc[mi][ni][2] + b0, v3 = acc[mi][ni][3] + b1;
            if (relu) {
                v0 = fmaxf(v0, 0.f); v1 = fmaxf(v1, 0.f);
                v2 = fmaxf(v2, 0.f); v3 = fmaxf(v3, 0.f);
            }
            if (r0 < M) {
                if (resid) {
                    float2 rr = *(const float2*)(resid + (size_t)r0 * N + c);
                    v0 += rr.x; v1 += rr.y;
                }
                *(float2*)(C + (size_t)r0 * N + c) = make_float2(v0, v1);
            }
            if (r1 < M) {
                if (resid) {
                    float2 rr = *(const float2*)(resid + (size_t)r1 * N + c);
                    v2 += rr.x; v3 += rr.y;
                }
                *(float2*)(C + (size_t)r1 * N + c) = make_float2(v2, v3);
            }
        }
    }
}

// ---------------- small NT GEMM (N=32 weights head) --------------------------
__global__ void gemm_nt(const float* __restrict__ A, const float* __restrict__ B,
                        const float* __restrict__ bias, const float* __restrict__ resid,
                        float* __restrict__ C, int M, int N, int K, int relu) {
    __shared__ float As[16][68];
    __shared__ float Bs[16][68];
    int tid = threadIdx.x;
    int tx = tid & 15, ty = tid >> 4;
    int bm = blockIdx.y * 64, bn = blockIdx.x * 64;
    int lm = tid >> 2;
    int kq = (tid & 3) * 4;
    float acc[4][4] = {};
    for (int k0 = 0; k0 < K; k0 += 16) {
        int gm = bm + lm;
        float4 va = make_float4(0.f, 0.f, 0.f, 0.f);
        if (gm < M) va = *(const float4*)(A + (size_t)gm * K + k0 + kq);
        As[kq + 0][lm] = va.x; As[kq + 1][lm] = va.y;
        As[kq + 2][lm] = va.z; As[kq + 3][lm] = va.w;
        int gn = bn + lm;
        float4 vb = make_float4(0.f, 0.f, 0.f, 0.f);
        if (gn < N) vb = *(const float4*)(B + (size_t)gn * K + k0 + kq);
        Bs[kq + 0][lm] = vb.x; Bs[kq + 1][lm] = vb.y;
        Bs[kq + 2][lm] = vb.z; Bs[kq + 3][lm] = vb.w;
        __syncthreads();
        #pragma unroll
        for (int k = 0; k < 16; k++) {
            float4 a4 = *(const float4*)&As[k][ty * 4];
            float4 b4 = *(const float4*)&Bs[k][tx * 4];
            float af[4] = {a4.x, a4.y, a4.z, a4.w};
            float bf[4] = {b4.x, b4.y, b4.z, b4.w};
            #pragma unroll
            for (int i = 0; i < 4; i++)
                #pragma unroll
                for (int j = 0; j < 4; j++)
                    acc[i][j] += af[i] * bf[j];
        }
        __syncthreads();
    }
    #pragma unroll
    for (int i = 0; i < 4; i++) {
        int r = bm + ty * 4 + i;
        if (r >= M) continue;
        #pragma unroll
        for (int j = 0; j < 4; j++) {
            int c = bn + tx * 4 + j;
            if (c >= N) continue;
            float v = acc[i][j];
            if (bias) v += bias[c];
            if (relu) v = fmaxf(v, 0.f);
            if (resid) v += resid[(size_t)r * N + c];
            C[(size_t)r * N + c] = v;
        }
    }
}

// ---------------- tensor-core flash attention (tf32, LDS.64 pairs) -----------
// 64-query blocks, 4 warps (16 q each), 64-key tiles, HD=32.
// Logical-k permutation: fragment pairs read physical (2tg, 2tg+1).
// Ks [64 key][32 d] stride 40; Vs [32 d][64 key] stride 72 (>=64!); Ps stride 72.
#define KSTR 40
#define VSTR 72
#define PSTR 72
__global__ __launch_bounds__(128)
void attn3_kernel(const float* __restrict__ qkv, float* __restrict__ out) {
    __shared__ __align__(16) float Ks[64 * KSTR];   // K tile [key][d]
    __shared__ __align__(16) float Vs[32 * VSTR];   // V tile transposed [d][key]
    __shared__ __align__(16) float Ps[64 * PSTR];   // P [q][key]

    const int b = blockIdx.z, h = blockIdx.y, qt = blockIdx.x;
    const int tid = threadIdx.x;
    const int w = tid >> 5, lane = tid & 31;
    const int g = lane >> 2, tg = lane & 3;
    const float scale = 0.17677669529663687f;   // 1/sqrt(32)
    const unsigned full = 0xffffffffu;

    // ---- Q fragments (pre-scaled, permuted cols 2tg / 2tg+1) ----
    const int r0 = qt * 64 + w * 16 + g;
    const int r1 = r0 + 8;
    uint32_t qa[4][4];
    {
        const float* q0p = qkv + ((size_t)(b * NQ + (r0 < NQ ? r0 : 0))) * 768 + h * HD;
        const float* q1p = qkv + ((size_t)(b * NQ + (r1 < NQ ? r1 : 0))) * 768 + h * HD;
        bool v0 = r0 < NQ, v1 = r1 < NQ;
        #pragma unroll
        for (int s = 0; s < 4; s++) {
            int c0 = s * 8 + 2 * tg;
            qa[s][0] = v0 ? f2tf32(q0p[c0] * scale) : 0u;
            qa[s][2] = v0 ? f2tf32(q0p[c0 + 1] * scale) : 0u;
            qa[s][1] = v1 ? f2tf32(q1p[c0] * scale) : 0u;
            qa[s][3] = v1 ? f2tf32(q1p[c0 + 1] * scale) : 0u;
        }
    }

    float m0 = -INFINITY, m1 = -INFINITY, l0 = 0.f, l1 = 0.f;
    float O[4][4];
    #pragma unroll
    for (int nd = 0; nd < 4; nd++)
        #pragma unroll
        for (int r = 0; r < 4; r++) O[nd][r] = 0.f;

    const int NKT = (NQ + 63) / 64;   // 15
    for (int jt = 0; jt < NKT; jt++) {
        __syncthreads();
        // ---- load K tile (cvt'd) and V tile transposed (cvt'd) ----
        {
            int key = tid >> 1, dh = (tid & 1) * 16;
            int kk = jt * 64 + key;
            if (kk < NQ) {
                const float* srcK = qkv + ((size_t)(b * NQ + kk)) * 768 + 256 + h * HD + dh;
                const float* srcV = srcK + 256;
                #pragma unroll
                for (int i = 0; i < 4; i++) {
                    float4 kv = *(const float4*)(srcK + i * 4);
                    *(float4*)&Ks[key * KSTR + dh + i * 4] = make_float4(
                        __uint_as_float(f2tf32(kv.x)), __uint_as_float(f2tf32(kv.y)),
                        __uint_as_float(f2tf32(kv.z)), __uint_as_float(f2tf32(kv.w)));
                    float4 vv = *(const float4*)(srcV + i * 4);
                    Vs[(dh + i * 4 + 0) * VSTR + key] = __uint_as_float(f2tf32(vv.x));
                    Vs[(dh + i * 4 + 1) * VSTR + key] = __uint_as_float(f2tf32(vv.y));
                    Vs[(dh + i * 4 + 2) * VSTR + key] = __uint_as_float(f2tf32(vv.z));
                    Vs[(dh + i * 4 + 3) * VSTR + key] = __uint_as_float(f2tf32(vv.w));
                }
            } else {
                #pragma unroll
                for (int i = 0; i < 4; i++) {
                    *(float4*)&Ks[key * KSTR + dh + i * 4] = make_float4(0.f, 0.f, 0.f, 0.f);
                    Vs[(dh + i * 4 + 0) * VSTR + key] = 0.f;
                    Vs[(dh + i * 4 + 1) * VSTR + key] = 0.f;
                    Vs[(dh + i * 4 + 2) * VSTR + key] = 0.f;
                    Vs[(dh + i * 4 + 3) * VSTR + key] = 0.f;
                }
            }
        }
        __syncthreads();

        // ---- QK: S[16 x 64] per warp (paired LDS.64 K fragments) ----
        float sacc[8][4];
        #pragma unroll
        for (int ni = 0; ni < 8; ni++)
            #pragma unroll
            for (int r = 0; r < 4; r++) sacc[ni][r] = 0.f;
        #pragma unroll
        for (int s = 0; s < 4; s++) {
            #pragma unroll
            for (int ni = 0; ni < 8; ni++) {
                float2 kv = *(const float2*)&Ks[(ni * 8 + g) * KSTR + s * 8 + 2 * tg];
                uint32_t bf[2] = { __float_as_uint(kv.x), __float_as_uint(kv.y) };
                mma1688(sacc[ni], qa[s], bf);
            }
        }
        // ---- mask invalid keys (output cols = physical keys, unchanged) ----
        int kglob = jt * 64;
        if (kglob + 64 > NQ) {
            #pragma unroll
            for (int ni = 0; ni < 8; ni++) {
                int kc = kglob + ni * 8 + 2 * tg;
                if (kc >= NQ)     { sacc[ni][0] = -1e30f; sacc[ni][2] = -1e30f; }
                if (kc + 1 >= NQ) { sacc[ni][1] = -1e30f; sacc[ni][3] = -1e30f; }
            }
        }

        // ---- online softmax (rows g and g+8; quad reduce over tg lanes) ----
        float mx0 = -INFINITY, mx1 = -INFINITY;
        #pragma unroll
        for (int ni = 0; ni < 8; ni++) {
            mx0 = fmaxf(mx0, fmaxf(sacc[ni][0], sacc[ni][1]));
            mx1 = fmaxf(mx1, fmaxf(sacc[ni][2], sacc[ni][3]));
        }
        mx0 = fmaxf(mx0, __shfl_xor_sync(full, mx0, 1));
        mx0 = fmaxf(mx0, __shfl_xor_sync(full, mx0, 2));
        mx1 = fmaxf(mx1, __shfl_xor_sync(full, mx1, 1));
        mx1 = fmaxf(mx1, __shfl_xor_sync(full, mx1, 2));
        float nm0 = fmaxf(m0, mx0), nm1 = fmaxf(m1, mx1);
        float fac0 = __expf(m0 - nm0), fac1 = __expf(m1 - nm1);
        float sum0 = 0.f, sum1 = 0.f;
        #pragma unroll
        for (int ni = 0; ni < 8; ni++) {
            sacc[ni][0] = __expf(sacc[ni][0] - nm0);
            sacc[ni][1] = __expf(sacc[ni][1] - nm0);
            sacc[ni][2] = __expf(sacc[ni][2] - nm1);
            sacc[ni][3] = __expf(sacc[ni][3] - nm1);
            sum0 += sacc[ni][0] + sacc[ni][1];
            sum1 += sacc[ni][2] + sacc[ni][3];
        }
        sum0 += __shfl_xor_sync(full, sum0, 1);
        sum0 += __shfl_xor_sync(full, sum0, 2);
        sum1 += __shfl_xor_sync(full, sum1, 1);
        sum1 += __shfl_xor_sync(full, sum1, 2);
        l0 = l0 * fac0 + sum0; m0 = nm0;
        l1 = l1 * fac1 + sum1; m1 = nm1;

        // ---- store P to smem (warp-private rows, adjacent key pairs) ----
        int q0 = w * 16 + g;
        #pragma unroll
        for (int ni = 0; ni < 8; ni++) {
            *(float2*)&Ps[q0 * PSTR + ni * 8 + 2 * tg] =
                make_float2(sacc[ni][0], sacc[ni][1]);
            *(float2*)&Ps[(q0 + 8) * PSTR + ni * 8 + 2 * tg] =
                make_float2(sacc[ni][2], sacc[ni][3]);
        }
        __syncwarp();

        // ---- rescale O, then PV with paired LDS.64 P/V fragments ----
        #pragma unroll
        for (int nd = 0; nd < 4; nd++) {
            O[nd][0] *= fac0; O[nd][1] *= fac0;
            O[nd][2] *= fac1; O[nd][3] *= fac1;
        }
        #pragma unroll
        for (int s = 0; s < 8; s++) {
            float2 plo = *(const float2*)&Ps[q0 * PSTR + s * 8 + 2 * tg];
            float2 phi = *(const float2*)&Ps[(q0 + 8) * PSTR + s * 8 + 2 * tg];
            uint32_t pa[4] = { f2tf32(plo.x), f2tf32(phi.x),
                               f2tf32(plo.y), f2tf32(phi.y) };
            #pragma unroll
            for (int nd = 0; nd < 4; nd++) {
                float2 vv = *(const float2*)&Vs[(nd * 8 + g) * VSTR + s * 8 + 2 * tg];
                uint32_t bf[2] = { __float_as_uint(vv.x), __float_as_uint(vv.y) };
                mma1688(O[nd], pa, bf);
            }
        }
    }

    // ---- epilogue ----
    float inv0 = 1.f / l0, inv1 = 1.f / l1;
    #pragma unroll
    for (int nd = 0; nd < 4; nd++) {
        int c = h * HD + nd * 8 + 2 * tg;
        if (r0 < NQ)
            *(float2*)(out + ((size_t)(b * NQ + r0)) * DD + c) =
                make_float2(O[nd][0] * inv0, O[nd][1] * inv0);
        if (r1 < NQ)
            *(float2*)(out + ((size_t)(b * NQ + r1)) * DD + c) =
                make_float2(O[nd][2] * inv1, O[nd][3] * inv1);
    }
}

// ---------------- deformable sampling: warp = (head), block = (b,q) ---------
__global__ void sample_kernel(const float* __restrict__ mem, const float* __restrict__ ref,
                              const float* __restrict__ offs, const float* __restrict__ wts,
                              float* __restrict__ fused) {
    int row = blockIdx.x;
    int b = row / NQ;
    int h = threadIdx.x >> 5;
    int lane = threadIdx.x & 31;
    const unsigned full = 0xffffffffu;
    float rx = ref[row * 2], ry = ref[row * 2 + 1];
    float gx = 0.f, gy = 0.f, wl = 0.f;
    if (lane < PP) {
        float ox = offs[(size_t)row * (HH * PP * 2) + h * (PP * 2) + lane * 2];
        float oy = offs[(size_t)row * (HH * PP * 2) + h * (PP * 2) + lane * 2 + 1];
        gx = (rx + tanhf(ox) * 0.2f) * (float)BEV - 0.5f;
        gy = (ry + tanhf(oy) * 0.2f) * (float)BEV - 0.5f;
        wl = wts[(size_t)row * (HH * PP) + h * PP + lane];
    }
    float m = wl;
    m = fmaxf(m, __shfl_xor_sync(full, m, 1));
    m = fmaxf(m, __shfl_xor_sync(full, m, 2));
    float e = __expf(wl - m);
    float ssum = e;
    ssum += __shfl_xor_sync(full, ssum, 1);
    ssum += __shfl_xor_sync(full, ssum, 2);
    float w = e / ssum;
    const float* mb = mem + (size_t)b * (BEV * BEV) * DD + h * HD + lane;
    float acc = 0.f;
    #pragma unroll
    for (int p = 0; p < PP; p++) {
        float px = __shfl_sync(full, gx, p);
        float py = __shfl_sync(full, gy, p);
        float pw = __shfl_sync(full, w, p);
        float x0f = floorf(px), y0f = floorf(py);
        float wx1 = px - x0f, wy1 = py - y0f;
        float wx0 = 1.f - wx1, wy0 = 1.f - wy1;
        int x0 = (int)x0f, y0 = (int)y0f;
        bool xv0 = (x0 >= 0) && (x0 < BEV);
        bool xv1 = (x0 + 1 >= 0) && (x0 + 1 < BEV);
        bool yv0 = (y0 >= 0) && (y0 < BEV);
        bool yv1 = (y0 + 1 >= 0) && (y0 + 1 < BEV);
        float v = 0.f;
        if (yv0) {
            if (xv0) v += wx0 * wy0 * mb[(size_t)(y0 * BEV + x0) * DD];
            if (xv1) v += wx1 * wy0 * mb[(size_t)(y0 * BEV + x0 + 1) * DD];
        }
        if (yv1) {
            if (xv0) v += wx0 * wy1 * mb[(size_t)((y0 + 1) * BEV + x0) * DD];
            if (xv1) v += wx1 * wy1 * mb[(size_t)((y0 + 1) * BEV + x0 + 1) * DD];
        }
        acc += pw * v;
    }
    fused[(size_t)row * DD + h * HD + lane] = acc;
}

// ---------------- host launcher ---------------------------------------------
extern "C" void kernel_launch(void* const* d_in, const int* in_sizes, int n_in,
                              void* d_out, int out_size) {
    const float* query = (const float*)d_in[0];
    const float* memory = (const float*)d_in[1];
    const float* refp  = (const float*)d_in[2];
    const float* qpos  = (const float*)d_in[3];
    const float* in_w  = (const float*)d_in[4];
    const float* in_b  = (const float*)d_in[5];
    const float* out_w = (const float*)d_in[6];
    const float* out_b = (const float*)d_in[7];
    const float* off_w = (const float*)d_in[8];
    const float* off_b = (const float*)d_in[9];
    const float* wt_w  = (const float*)d_in[10];
    const float* wt_b  = (const float*)d_in[11];
    const float* co_w  = (const float*)d_in[12];
    const float* co_b  = (const float*)d_in[13];
    const float* f_w1  = (const float*)d_in[14];
    const float* f_b1  = (const float*)d_in[15];
    const float* f_w2  = (const float*)d_in[16];
    const float* f_b2  = (const float*)d_in[17];
    const float* n1s   = (const float*)d_in[18];
    const float* n1b   = (const float*)d_in[19];
    const float* n2s   = (const float*)d_in[20];
    const float* n2b   = (const float*)d_in[21];
    const float* n3s   = (const float*)d_in[22];
    const float* n3b   = (const float*)d_in[23];

    float *qin, *qkv, *attn, *q1, *q2, *offs, *wts, *fused, *qq2, *q3, *mid;
    cudaGetSymbolAddress((void**)&qin,   g_qin);
    cudaGetSymbolAddress((void**)&qkv,   g_qkv);
    cudaGetSymbolAddress((void**)&attn,  g_attn);
    cudaGetSymbolAddress((void**)&q1,    g_q1);
    cudaGetSymbolAddress((void**)&q2,    g_q2);
    cudaGetSymbolAddress((void**)&offs,  g_offs);
    cudaGetSymbolAddress((void**)&wts,   g_wts);
    cudaGetSymbolAddress((void**)&fused, g_fused);
    cudaGetSymbolAddress((void**)&qq2,   g_qq2);
    cudaGetSymbolAddress((void**)&q3,    g_q3);
    cudaGetSymbolAddress((void**)&mid,   g_mid);

    const int M = MROWS;
    const int MTC  = (M + 127) / 128;    // 57
    const int MT64 = (M + 63) / 64;      // 113
    const int LNG  = (M + 7) / 8;        // 900

    // 1. q_in = LN(query + query_pos)
    add_ln_warp<<<LNG, 256>>>(query, qpos, n1s, n1b, qin);
    // 2. qkv = q_in @ in_w^T + in_b
    gemm_tc<<<dim3(12, MTC), 256>>>(qin, in_w, in_b, nullptr, qkv, M, 768, 256, 0);
    // 3. self-attention (tensor-core flash, tf32)
    attn3_kernel<<<dim3((NQ + 63) / 64, HH, BB), 128>>>(qkv, attn);
    // 4. q1 = attn @ out_w^T + out_b + query
    gemm_tc<<<dim3(4, MTC), 256>>>(attn, out_w, out_b, query, q1, M, 256, 256, 0);
    // 5. q2 = LN(q1 + query_pos)
    add_ln_warp<<<LNG, 256>>>(q1, qpos, n2s, n2b, q2);
    // 6/7. offset + weight heads
    gemm_tc<<<dim3(1, MTC), 256>>>(q2, off_w, off_b, nullptr, offs, M, 64, 256, 0);
    gemm_nt<<<dim3(1, MT64), 256>>>(q2, wt_w, wt_b, nullptr, wts, M, 32, 256, 0);
    // 8. deformable BEV sampling -> fused
    sample_kernel<<<M, 256>>>(memory, refp, offs, wts, fused);
    // 9. qq2 = fused @ co_w^T + co_b + q1
    gemm_tc<<<dim3(4, MTC), 256>>>(fused, co_w, co_b, q1, qq2, M, 256, 256, 0);
    // 10. q3 = LN(qq2)
    add_ln_warp<<<LNG, 256>>>(qq2, nullptr, n3s, n3b, q3);
    // 11. mid = relu(q3 @ f_w1^T + f_b1)
    gemm_tc<<<dim3(8, MTC), 256>>>(q3, f_w1, f_b1, nullptr, mid, M, 512, 256, 1);
    // 12. out = mid @ f_w2^T + f_b2 + qq2
    gemm_tc<<<dim3(4, MTC), 256>>>(mid, f_w2, f_b2, qq2, (float*)d_out, M, 256, 512, 0);
    (void)in_sizes; (void)n_in; (void)out_size;
}

// round 13
// speedup vs baseline: 1.5661x; 1.0575x over previous
#include <cuda_runtime.h>
#include <cuda_bf16.h>
#include <math.h>
#include <stdint.h>

// Problem constants
#define BB    8
#define NQ    900
#define DD    256
#define HH    8
#define HD    32
#define PP    4
#define BEV   200
#define FFN   512
#define MROWS (BB * NQ)          // 7200

// ---------------- scratch (allocation-free: __device__ globals) -------------
__device__ float g_qin  [MROWS * DD];
__device__ float g_qkv  [MROWS * 3 * DD];
__device__ float g_attn [MROWS * DD];
__device__ float g_q1   [MROWS * DD];
__device__ float g_q2   [MROWS * DD];
__device__ float g_offs [MROWS * HH * PP * 2];
__device__ float g_wts  [MROWS * HH * PP];
__device__ float g_fused[MROWS * DD];
__device__ float g_qq2  [MROWS * DD];
__device__ float g_q3   [MROWS * DD];
__device__ float g_mid  [MROWS * FFN];

// ---------------- fused add + LayerNorm: warp per row, 8 rows/block ----------
__global__ void add_ln_warp(const float* __restrict__ a, const float* __restrict__ b,
                            const float* __restrict__ s, const float* __restrict__ bias,
                            float* __restrict__ out) {
    const unsigned full = 0xffffffffu;
    int w = threadIdx.x >> 5, lane = threadIdx.x & 31;
    int row = blockIdx.x * 8 + w;
    if (row >= MROWS) return;
    const float* ap = a + (size_t)row * DD;
    float4 x0 = *(const float4*)(ap + lane * 4);
    float4 x1 = *(const float4*)(ap + 128 + lane * 4);
    if (b) {
        const float* bp = b + (size_t)row * DD;
        float4 b0 = *(const float4*)(bp + lane * 4);
        float4 b1 = *(const float4*)(bp + 128 + lane * 4);
        x0.x += b0.x; x0.y += b0.y; x0.z += b0.z; x0.w += b0.w;
        x1.x += b1.x; x1.y += b1.y; x1.z += b1.z; x1.w += b1.w;
    }
    float sum = x0.x + x0.y + x0.z + x0.w + x1.x + x1.y + x1.z + x1.w;
    #pragma unroll
    for (int o = 16; o; o >>= 1) sum += __shfl_xor_sync(full, sum, o);
    float mean = sum * (1.f / DD);
    float c0x = x0.x - mean, c0y = x0.y - mean, c0z = x0.z - mean, c0w = x0.w - mean;
    float c1x = x1.x - mean, c1y = x1.y - mean, c1z = x1.z - mean, c1w = x1.w - mean;
    float vs = c0x*c0x + c0y*c0y + c0z*c0z + c0w*c0w
             + c1x*c1x + c1y*c1y + c1z*c1z + c1w*c1w;
    #pragma unroll
    for (int o = 16; o; o >>= 1) vs += __shfl_xor_sync(full, vs, o);
    float inv = rsqrtf(vs * (1.f / DD) + 1e-5f);
    float4 s0 = *(const float4*)(s + lane * 4);
    float4 s1 = *(const float4*)(s + 128 + lane * 4);
    float4 g0 = *(const float4*)(bias + lane * 4);
    float4 g1 = *(const float4*)(bias + 128 + lane * 4);
    float* op = out + (size_t)row * DD;
    *(float4*)(op + lane * 4) = make_float4(
        c0x * inv * s0.x + g0.x, c0y * inv * s0.y + g0.y,
        c0z * inv * s0.z + g0.z, c0w * inv * s0.w + g0.w);
    *(float4*)(op + 128 + lane * 4) = make_float4(
        c1x * inv * s1.x + g1.x, c1y * inv * s1.y + g1.y,
        c1z * inv * s1.z + g1.z, c1w * inv * s1.w + g1.w);
}

// ---------------- tf32 helpers ----------------------------------------------
__device__ __forceinline__ uint32_t f2tf32(float f) {
    uint32_t u;
    asm("cvt.rna.tf32.f32 %0, %1;" : "=r"(u) : "f"(f));
    return u;
}

__device__ __forceinline__ void mma1688(float* d, const uint32_t* a, const uint32_t* b) {
    asm volatile(
        "mma.sync.aligned.m16n8k8.row.col.f32.tf32.tf32.f32 "
        "{%0,%1,%2,%3}, {%4,%5,%6,%7}, {%8,%9}, {%0,%1,%2,%3};\n"
        : "+f"(d[0]), "+f"(d[1]), "+f"(d[2]), "+f"(d[3])
        : "r"(a[0]), "r"(a[1]), "r"(a[2]), "r"(a[3]), "r"(b[0]), "r"(b[1]));
}

__device__ __forceinline__ uint32_t smem_u32(const void* p) {
    uint32_t a;
    asm("{ .reg .u64 t; cvta.to.shared.u64 t, %1; cvt.u32.u64 %0, t; }"
        : "=r"(a) : "l"(p));
    return a;
}
__device__ __forceinline__ void cpa16(uint32_t d, const float* s) {
    asm volatile("cp.async.cg.shared.global [%0], [%1], 16;"
                 :: "r"(d), "l"(s) : "memory");
}

// ---------------- tensor-core NT GEMM (tf32): C = A*B^T + epi ---------------
// 128x64 tile, BK=16, 4-stage cp.async pipeline (canonical single-sync order:
// wait -> sync -> refill stage i+3 into buffer consumed at iter i-1 -> compute).
// 8 warps 4x2, 2 CTAs/SM. tf32 cvt at fragment load (numerically identical).
// Logical-k permutation: lane-k (tg, tg+4) reads physical (2tg, 2tg+1) ->
// fragment pairs are single LDS.64; SSTR=24 floats is 64-bit conflict-free.
#define SSTR 24
#define STAGE_FLOATS ((128 + 64) * SSTR)       // 4608 floats = 18432 B
#define NSTAGE 4
#define GT_SMEM (NSTAGE * STAGE_FLOATS * 4)    // 73728 B
__global__ __launch_bounds__(256, 2)
void gemm_tc(const float* __restrict__ A, const float* __restrict__ B,
             const float* __restrict__ bias, const float* __restrict__ resid,
             float* __restrict__ C, int M, int N, int K, int relu) {
    extern __shared__ __align__(16) float sm[];
    const int tid = threadIdx.x;
    const int lane = tid & 31, wid = tid >> 5;
    const int g = lane >> 2, tg = lane & 3;
    const int wm = (wid >> 1) * 32, wn = (wid & 1) * 32;
    const int bm = blockIdx.y * 128, bn = blockIdx.x * 64;

    const int rowA0 = tid >> 2, rowA1 = rowA0 + 64;
    const int rowB  = tid >> 2;            // 0..63
    const int kq    = (tid & 3) * 4;

    // clamped global row pointers (garbage rows only feed discarded outputs)
    int gm0 = bm + rowA0; if (gm0 >= M) gm0 = M - 1;
    int gm1 = bm + rowA1; if (gm1 >= M) gm1 = M - 1;
    const float* a0p = A + (size_t)gm0 * K + kq;
    const float* a1p = A + (size_t)gm1 * K + kq;
    const float* bp  = B + (size_t)(bn + rowB) * K + kq;

    const uint32_t sbase = smem_u32(sm);
    const uint32_t dA0 = sbase + (uint32_t)(rowA0 * SSTR + kq) * 4u;
    const uint32_t dA1 = sbase + (uint32_t)(rowA1 * SSTR + kq) * 4u;
    const uint32_t dB  = sbase + (uint32_t)(128 * SSTR + rowB * SSTR + kq) * 4u;

    const int NIT = K >> 4;   // 16 or 32 (K = 256 / 512)

    // prologue: issue stages 0,1,2 (stage 3 left for the loop)
    #pragma unroll
    for (int s = 0; s < 3; s++) {
        uint32_t off = (uint32_t)(s * STAGE_FLOATS) * 4u;
        cpa16(dA0 + off, a0p + s * 16);
        cpa16(dA1 + off, a1p + s * 16);
        cpa16(dB  + off, bp  + s * 16);
        asm volatile("cp.async.commit_group;" ::: "memory");
    }

    float acc[2][4][4];
    #pragma unroll
    for (int mi = 0; mi < 2; mi++)
        #pragma unroll
        for (int ni = 0; ni < 4; ni++)
            #pragma unroll
            for (int r = 0; r < 4; r++) acc[mi][ni][r] = 0.f;

    for (int i = 0; i < NIT; i++) {
        // wait until stage i is complete. committed = min(3+i, NIT);
        // pending allowed = committed - (i+1): 2 normally, 1 / 0 at tail.
        if (i <= NIT - 3)      asm volatile("cp.async.wait_group 2;" ::: "memory");
        else if (i == NIT - 2) asm volatile("cp.async.wait_group 1;" ::: "memory");
        else                   asm volatile("cp.async.wait_group 0;" ::: "memory");
        __syncthreads();   // stage-i data visible; all warps past iter i-1 reads

        // refill stage i+3 into buffer (i+3)%4 == (i-1)%4 (consumed last iter)
        int snext = i + 3;
        if (snext < NIT) {
            uint32_t off = (uint32_t)((snext & 3) * STAGE_FLOATS) * 4u;
            const int kof = snext * 16;
            cpa16(dA0 + off, a0p + kof);
            cpa16(dA1 + off, a1p + kof);
            cpa16(dB  + off, bp  + kof);
            asm volatile("cp.async.commit_group;" ::: "memory");
        }

        // compute from buffer i%4
        const float* Abuf = sm + (i & 3) * STAGE_FLOATS;
        const float* Bbuf = Abuf + 128 * SSTR;
        #pragma unroll
        for (int k8 = 0; k8 < 2; k8++) {
            uint32_t af[2][4], bf[4][2];
            #pragma unroll
            for (int mi = 0; mi < 2; mi++) {
                const float* base = &Abuf[(wm + mi * 16 + g) * SSTR + k8 * 8 + 2 * tg];
                float2 lo = *(const float2*)base;
                float2 hi = *(const float2*)(base + 8 * SSTR);
                af[mi][0] = f2tf32(lo.x); af[mi][2] = f2tf32(lo.y);
                af[mi][1] = f2tf32(hi.x); af[mi][3] = f2tf32(hi.y);
            }
            #pragma unroll
            for (int ni = 0; ni < 4; ni++) {
                float2 v = *(const float2*)&Bbuf[(wn + ni * 8 + g) * SSTR + k8 * 8 + 2 * tg];
                bf[ni][0] = f2tf32(v.x); bf[ni][1] = f2tf32(v.y);
            }
            #pragma unroll
            for (int mi = 0; mi < 2; mi++)
                #pragma unroll
                for (int ni = 0; ni < 4; ni++)
                    mma1688(acc[mi][ni], af[mi], bf[ni]);
        }
    }

    #pragma unroll
    for (int ni = 0; ni < 4; ni++) {
        int c = bn + wn + ni * 8 + 2 * tg;
        float b0 = bias ? bias[c] : 0.f;
        float b1 = bias ? bias[c + 1] : 0.f;
        #pragma unroll
        for (int mi = 0; mi < 2; mi++) {
            int r0 = bm + wm + mi * 16 + g;
            int r1 = r0 + 8;
            float v0 = acc[mi][ni][0] + b0, v1 = acc[mi][ni][1] + b1;
            float v2 = acc[mi][ni][2] + b0, v3 = acc[mi][ni][3] + b1;
            if (relu) {
                v0 = fmaxf(v0, 0.f); v1 = fmaxf(v1, 0.f);
                v2 = fmaxf(v2, 0.f); v3 = fmaxf(v3, 0.f);
            }
            if (r0 < M) {
                if (resid) {
                    float2 rr = *(const float2*)(resid + (size_t)r0 * N + c);
                    v0 += rr.x; v1 += rr.y;
                }
                *(float2*)(C + (size_t)r0 * N + c) = make_float2(v0, v1);
            }
            if (r1 < M) {
                if (resid) {
                    float2 rr = *(const float2*)(resid + (size_t)r1 * N + c);
                    v2 += rr.x; v3 += rr.y;
                }
                *(float2*)(C + (size_t)r1 * N + c) = make_float2(v2, v3);
            }
        }
    }
}

// ---------------- small NT GEMM (N=32 weights head) --------------------------
__global__ void gemm_nt(const float* __restrict__ A, const float* __restrict__ B,
                        const float* __restrict__ bias, const float* __restrict__ resid,
                        float* __restrict__ C, int M, int N, int K, int relu) {
    __shared__ float As[16][68];
    __shared__ float Bs[16][68];
    int tid = threadIdx.x;
    int tx = tid & 15, ty = tid >> 4;
    int bm = blockIdx.y * 64, bn = blockIdx.x * 64;
    int lm = tid >> 2;
    int kq = (tid & 3) * 4;
    float acc[4][4] = {};
    for (int k0 = 0; k0 < K; k0 += 16) {
        int gm = bm + lm;
        float4 va = make_float4(0.f, 0.f, 0.f, 0.f);
        if (gm < M) va = *(const float4*)(A + (size_t)gm * K + k0 + kq);
        As[kq + 0][lm] = va.x; As[kq + 1][lm] = va.y;
        As[kq + 2][lm] = va.z; As[kq + 3][lm] = va.w;
        int gn = bn + lm;
        float4 vb = make_float4(0.f, 0.f, 0.f, 0.f);
        if (gn < N) vb = *(const float4*)(B + (size_t)gn * K + k0 + kq);
        Bs[kq + 0][lm] = vb.x; Bs[kq + 1][lm] = vb.y;
        Bs[kq + 2][lm] = vb.z; Bs[kq + 3][lm] = vb.w;
        __syncthreads();
        #pragma unroll
        for (int k = 0; k < 16; k++) {
            float4 a4 = *(const float4*)&As[k][ty * 4];
            float4 b4 = *(const float4*)&Bs[k][tx * 4];
            float af[4] = {a4.x, a4.y, a4.z, a4.w};
            float bf[4] = {b4.x, b4.y, b4.z, b4.w};
            #pragma unroll
            for (int i = 0; i < 4; i++)
                #pragma unroll
                for (int j = 0; j < 4; j++)
                    acc[i][j] += af[i] * bf[j];
        }
        __syncthreads();
    }
    #pragma unroll
    for (int i = 0; i < 4; i++) {
        int r = bm + ty * 4 + i;
        if (r >= M) continue;
        #pragma unroll
        for (int j = 0; j < 4; j++) {
            int c = bn + tx * 4 + j;
            if (c >= N) continue;
            float v = acc[i][j];
            if (bias) v += bias[c];
            if (relu) v = fmaxf(v, 0.f);
            if (resid) v += resid[(size_t)r * N + c];
            C[(size_t)r * N + c] = v;
        }
    }
}

// ---------------- tensor-core flash attention (tf32, LDS.64 pairs) -----------
// 64-query blocks, 4 warps (16 q each), 64-key tiles, HD=32.
// Logical-k permutation: fragment pairs read physical (2tg, 2tg+1).
// Ks [64 key][32 d] stride 40; Vs [32 d][64 key] stride 72; Ps stride 72.
#define KSTR 40
#define VSTR 72
#define PSTR 72
__global__ __launch_bounds__(128)
void attn3_kernel(const float* __restrict__ qkv, float* __restrict__ out) {
    __shared__ __align__(16) float Ks[64 * KSTR];
    __shared__ __align__(16) float Vs[32 * VSTR];
    __shared__ __align__(16) float Ps[64 * PSTR];

    const int b = blockIdx.z, h = blockIdx.y, qt = blockIdx.x;
    const int tid = threadIdx.x;
    const int w = tid >> 5, lane = tid & 31;
    const int g = lane >> 2, tg = lane & 3;
    const float scale = 0.17677669529663687f;   // 1/sqrt(32)
    const unsigned full = 0xffffffffu;

    const int r0 = qt * 64 + w * 16 + g;
    const int r1 = r0 + 8;
    uint32_t qa[4][4];
    {
        const float* q0p = qkv + ((size_t)(b * NQ + (r0 < NQ ? r0 : 0))) * 768 + h * HD;
        const float* q1p = qkv + ((size_t)(b * NQ + (r1 < NQ ? r1 : 0))) * 768 + h * HD;
        bool v0 = r0 < NQ, v1 = r1 < NQ;
        #pragma unroll
        for (int s = 0; s < 4; s++) {
            int c0 = s * 8 + 2 * tg;
            qa[s][0] = v0 ? f2tf32(q0p[c0] * scale) : 0u;
            qa[s][2] = v0 ? f2tf32(q0p[c0 + 1] * scale) : 0u;
            qa[s][1] = v1 ? f2tf32(q1p[c0] * scale) : 0u;
            qa[s][3] = v1 ? f2tf32(q1p[c0 + 1] * scale) : 0u;
        }
    }

    float m0 = -INFINITY, m1 = -INFINITY, l0 = 0.f, l1 = 0.f;
    float O[4][4];
    #pragma unroll
    for (int nd = 0; nd < 4; nd++)
        #pragma unroll
        for (int r = 0; r < 4; r++) O[nd][r] = 0.f;

    const int NKT = (NQ + 63) / 64;   // 15
    for (int jt = 0; jt < NKT; jt++) {
        __syncthreads();
        {
            int key = tid >> 1, dh = (tid & 1) * 16;
            int kk = jt * 64 + key;
            if (kk < NQ) {
                const float* srcK = qkv + ((size_t)(b * NQ + kk)) * 768 + 256 + h * HD + dh;
                const float* srcV = srcK + 256;
                #pragma unroll
                for (int i = 0; i < 4; i++) {
                    float4 kv = *(const float4*)(srcK + i * 4);
                    *(float4*)&Ks[key * KSTR + dh + i * 4] = make_float4(
                        __uint_as_float(f2tf32(kv.x)), __uint_as_float(f2tf32(kv.y)),
                        __uint_as_float(f2tf32(kv.z)), __uint_as_float(f2tf32(kv.w)));
                    float4 vv = *(const float4*)(srcV + i * 4);
                    Vs[(dh + i * 4 + 0) * VSTR + key] = __uint_as_float(f2tf32(vv.x));
                    Vs[(dh + i * 4 + 1) * VSTR + key] = __uint_as_float(f2tf32(vv.y));
                    Vs[(dh + i * 4 + 2) * VSTR + key] = __uint_as_float(f2tf32(vv.z));
                    Vs[(dh + i * 4 + 3) * VSTR + key] = __uint_as_float(f2tf32(vv.w));
                }
            } else {
                #pragma unroll
                for (int i = 0; i < 4; i++) {
                    *(float4*)&Ks[key * KSTR + dh + i * 4] = make_float4(0.f, 0.f, 0.f, 0.f);
                    Vs[(dh + i * 4 + 0) * VSTR + key] = 0.f;
                    Vs[(dh + i * 4 + 1) * VSTR + key] = 0.f;
                    Vs[(dh + i * 4 + 2) * VSTR + key] = 0.f;
                    Vs[(dh + i * 4 + 3) * VSTR + key] = 0.f;
                }
            }
        }
        __syncthreads();

        float sacc[8][4];
        #pragma unroll
        for (int ni = 0; ni < 8; ni++)
            #pragma unroll
            for (int r = 0; r < 4; r++) sacc[ni][r] = 0.f;
        #pragma unroll
        for (int s = 0; s < 4; s++) {
            #pragma unroll
            for (int ni = 0; ni < 8; ni++) {
                float2 kv = *(const float2*)&Ks[(ni * 8 + g) * KSTR + s * 8 + 2 * tg];
                uint32_t bf[2] = { __float_as_uint(kv.x), __float_as_uint(kv.y) };
                mma1688(sacc[ni], qa[s], bf);
            }
        }
        int kglob = jt * 64;
        if (kglob + 64 > NQ) {
            #pragma unroll
            for (int ni = 0; ni < 8; ni++) {
                int kc = kglob + ni * 8 + 2 * tg;
                if (kc >= NQ)     { sacc[ni][0] = -1e30f; sacc[ni][2] = -1e30f; }
                if (kc + 1 >= NQ) { sacc[ni][1] = -1e30f; sacc[ni][3] = -1e30f; }
            }
        }

        float mx0 = -INFINITY, mx1 = -INFINITY;
        #pragma unroll
        for (int ni = 0; ni < 8; ni++) {
            mx0 = fmaxf(mx0, fmaxf(sacc[ni][0], sacc[ni][1]));
            mx1 = fmaxf(mx1, fmaxf(sacc[ni][2], sacc[ni][3]));
        }
        mx0 = fmaxf(mx0, __shfl_xor_sync(full, mx0, 1));
        mx0 = fmaxf(mx0, __shfl_xor_sync(full, mx0, 2));
        mx1 = fmaxf(mx1, __shfl_xor_sync(full, mx1, 1));
        mx1 = fmaxf(mx1, __shfl_xor_sync(full, mx1, 2));
        float nm0 = fmaxf(m0, mx0), nm1 = fmaxf(m1, mx1);
        float fac0 = __expf(m0 - nm0), fac1 = __expf(m1 - nm1);
        float sum0 = 0.f, sum1 = 0.f;
        #pragma unroll
        for (int ni = 0; ni < 8; ni++) {
            sacc[ni][0] = __expf(sacc[ni][0] - nm0);
            sacc[ni][1] = __expf(sacc[ni][1] - nm0);
            sacc[ni][2] = __expf(sacc[ni][2] - nm1);
            sacc[ni][3] = __expf(sacc[ni][3] - nm1);
            sum0 += sacc[ni][0] + sacc[ni][1];
            sum1 += sacc[ni][2] + sacc[ni][3];
        }
        sum0 += __shfl_xor_sync(full, sum0, 1);
        sum0 += __shfl_xor_sync(full, sum0, 2);
        sum1 += __shfl_xor_sync(full, sum1, 1);
        sum1 += __shfl_xor_sync(full, sum1, 2);
        l0 = l0 * fac0 + sum0; m0 = nm0;
        l1 = l1 * fac1 + sum1; m1 = nm1;

        int q0 = w * 16 + g;
        #pragma unroll
        for (int ni = 0; ni < 8; ni++) {
            *(float2*)&Ps[q0 * PSTR + ni * 8 + 2 * tg] =
                make_float2(sacc[ni][0], sacc[ni][1]);
            *(float2*)&Ps[(q0 + 8) * PSTR + ni * 8 + 2 * tg] =
                make_float2(sacc[ni][2], sacc[ni][3]);
        }
        __syncwarp();

        #pragma unroll
        for (int nd = 0; nd < 4; nd++) {
            O[nd][0] *= fac0; O[nd][1] *= fac0;
            O[nd][2] *= fac1; O[nd][3] *= fac1;
        }
        #pragma unroll
        for (int s = 0; s < 8; s++) {
            float2 plo = *(const float2*)&Ps[q0 * PSTR + s * 8 + 2 * tg];
            float2 phi = *(const float2*)&Ps[(q0 + 8) * PSTR + s * 8 + 2 * tg];
            uint32_t pa[4] = { f2tf32(plo.x), f2tf32(phi.x),
                               f2tf32(plo.y), f2tf32(phi.y) };
            #pragma unroll
            for (int nd = 0; nd < 4; nd++) {
                float2 vv = *(const float2*)&Vs[(nd * 8 + g) * VSTR + s * 8 + 2 * tg];
                uint32_t bf[2] = { __float_as_uint(vv.x), __float_as_uint(vv.y) };
                mma1688(O[nd], pa, bf);
            }
        }
    }

    float inv0 = 1.f / l0, inv1 = 1.f / l1;
    #pragma unroll
    for (int nd = 0; nd < 4; nd++) {
        int c = h * HD + nd * 8 + 2 * tg;
        if (r0 < NQ)
            *(float2*)(out + ((size_t)(b * NQ + r0)) * DD + c) =
                make_float2(O[nd][0] * inv0, O[nd][1] * inv0);
        if (r1 < NQ)
            *(float2*)(out + ((size_t)(b * NQ + r1)) * DD + c) =
                make_float2(O[nd][2] * inv1, O[nd][3] * inv1);
    }
}

// ---------------- deformable sampling: warp = (head), block = (b,q) ---------
__global__ void sample_kernel(const float* __restrict__ mem, const float* __restrict__ ref,
                              const float* __restrict__ offs, const float* __restrict__ wts,
                              float* __restrict__ fused) {
    int row = blockIdx.x;
    int b = row / NQ;
    int h = threadIdx.x >> 5;
    int lane = threadIdx.x & 31;
    const unsigned full = 0xffffffffu;
    float rx = ref[row * 2], ry = ref[row * 2 + 1];
    float gx = 0.f, gy = 0.f, wl = 0.f;
    if (lane < PP) {
        float ox = offs[(size_t)row * (HH * PP * 2) + h * (PP * 2) + lane * 2];
        float oy = offs[(size_t)row * (HH * PP * 2) + h * (PP * 2) + lane * 2 + 1];
        gx = (rx + tanhf(ox) * 0.2f) * (float)BEV - 0.5f;
        gy = (ry + tanhf(oy) * 0.2f) * (float)BEV - 0.5f;
        wl = wts[(size_t)row * (HH * PP) + h * PP + lane];
    }
    float m = wl;
    m = fmaxf(m, __shfl_xor_sync(full, m, 1));
    m = fmaxf(m, __shfl_xor_sync(full, m, 2));
    float e = __expf(wl - m);
    float ssum = e;
    ssum += __shfl_xor_sync(full, ssum, 1);
    ssum += __shfl_xor_sync(full, ssum, 2);
    float w = e / ssum;
    const float* mb = mem + (size_t)b * (BEV * BEV) * DD + h * HD + lane;
    float acc = 0.f;
    #pragma unroll
    for (int p = 0; p < PP; p++) {
        float px = __shfl_sync(full, gx, p);
        float py = __shfl_sync(full, gy, p);
        float pw = __shfl_sync(full, w, p);
        float x0f = floorf(px), y0f = floorf(py);
        float wx1 = px - x0f, wy1 = py - y0f;
        float wx0 = 1.f - wx1, wy0 = 1.f - wy1;
        int x0 = (int)x0f, y0 = (int)y0f;
        bool xv0 = (x0 >= 0) && (x0 < BEV);
        bool xv1 = (x0 + 1 >= 0) && (x0 + 1 < BEV);
        bool yv0 = (y0 >= 0) && (y0 < BEV);
        bool yv1 = (y0 + 1 >= 0) && (y0 + 1 < BEV);
        float v = 0.f;
        if (yv0) {
            if (xv0) v += wx0 * wy0 * mb[(size_t)(y0 * BEV + x0) * DD];
            if (xv1) v += wx1 * wy0 * mb[(size_t)(y0 * BEV + x0 + 1) * DD];
        }
        if (yv1) {
            if (xv0) v += wx0 * wy1 * mb[(size_t)((y0 + 1) * BEV + x0) * DD];
            if (xv1) v += wx1 * wy1 * mb[(size_t)((y0 + 1) * BEV + x0 + 1) * DD];
        }
        acc += pw * v;
    }
    fused[(size_t)row * DD + h * HD + lane] = acc;
}

// ---------------- host launcher ---------------------------------------------
extern "C" void kernel_launch(void* const* d_in, const int* in_sizes, int n_in,
                              void* d_out, int out_size) {
    const float* query = (const float*)d_in[0];
    const float* memory = (const float*)d_in[1];
    const float* refp  = (const float*)d_in[2];
    const float* qpos  = (const float*)d_in[3];
    const float* in_w  = (const float*)d_in[4];
    const float* in_b  = (const float*)d_in[5];
    const float* out_w = (const float*)d_in[6];
    const float* out_b = (const float*)d_in[7];
    const float* off_w = (const float*)d_in[8];
    const float* off_b = (const float*)d_in[9];
    const float* wt_w  = (const float*)d_in[10];
    const float* wt_b  = (const float*)d_in[11];
    const float* co_w  = (const float*)d_in[12];
    const float* co_b  = (const float*)d_in[13];
    const float* f_w1  = (const float*)d_in[14];
    const float* f_b1  = (const float*)d_in[15];
    const float* f_w2  = (const float*)d_in[16];
    const float* f_b2  = (const float*)d_in[17];
    const float* n1s   = (const float*)d_in[18];
    const float* n1b   = (const float*)d_in[19];
    const float* n2s   = (const float*)d_in[20];
    const float* n2b   = (const float*)d_in[21];
    const float* n3s   = (const float*)d_in[22];
    const float* n3b   = (const float*)d_in[23];

    float *qin, *qkv, *attn, *q1, *q2, *offs, *wts, *fused, *qq2, *q3, *mid;
    cudaGetSymbolAddress((void**)&qin,   g_qin);
    cudaGetSymbolAddress((void**)&qkv,   g_qkv);
    cudaGetSymbolAddress((void**)&attn,  g_attn);
    cudaGetSymbolAddress((void**)&q1,    g_q1);
    cudaGetSymbolAddress((void**)&q2,    g_q2);
    cudaGetSymbolAddress((void**)&offs,  g_offs);
    cudaGetSymbolAddress((void**)&wts,   g_wts);
    cudaGetSymbolAddress((void**)&fused, g_fused);
    cudaGetSymbolAddress((void**)&qq2,   g_qq2);
    cudaGetSymbolAddress((void**)&q3,    g_q3);
    cudaGetSymbolAddress((void**)&mid,   g_mid);

    const int M = MROWS;
    const int MTC  = (M + 127) / 128;    // 57
    const int MT64 = (M + 63) / 64;      // 113
    const int LNG  = (M + 7) / 8;        // 900

    cudaFuncSetAttribute(gemm_tc, cudaFuncAttributeMaxDynamicSharedMemorySize,
                         GT_SMEM);

    // 1. q_in = LN(query + query_pos)
    add_ln_warp<<<LNG, 256>>>(query, qpos, n1s, n1b, qin);
    // 2. qkv = q_in @ in_w^T + in_b
    gemm_tc<<<dim3(12, MTC), 256, GT_SMEM>>>(qin, in_w, in_b, nullptr, qkv, M, 768, 256, 0);
    // 3. self-attention (tensor-core flash, tf32)
    attn3_kernel<<<dim3((NQ + 63) / 64, HH, BB), 128>>>(qkv, attn);
    // 4. q1 = attn @ out_w^T + out_b + query
    gemm_tc<<<dim3(4, MTC), 256, GT_SMEM>>>(attn, out_w, out_b, query, q1, M, 256, 256, 0);
    // 5. q2 = LN(q1 + query_pos)
    add_ln_warp<<<LNG, 256>>>(q1, qpos, n2s, n2b, q2);
    // 6/7. offset + weight heads
    gemm_tc<<<dim3(1, MTC), 256, GT_SMEM>>>(q2, off_w, off_b, nullptr, offs, M, 64, 256, 0);
    gemm_nt<<<dim3(1, MT64), 256>>>(q2, wt_w, wt_b, nullptr, wts, M, 32, 256, 0);
    // 8. deformable BEV sampling -> fused
    sample_kernel<<<M, 256>>>(memory, refp, offs, wts, fused);
    // 9. qq2 = fused @ co_w^T + co_b + q1
    gemm_tc<<<dim3(4, MTC), 256, GT_SMEM>>>(fused, co_w, co_b, q1, qq2, M, 256, 256, 0);
    // 10. q3 = LN(qq2)
    add_ln_warp<<<LNG, 256>>>(qq2, nullptr, n3s, n3b, q3);
    // 11. mid = relu(q3 @ f_w1^T + f_b1)
    gemm_tc<<<dim3(8, MTC), 256, GT_SMEM>>>(q3, f_w1, f_b1, nullptr, mid, M, 512, 256, 1);
    // 12. out = mid @ f_w2^T + f_b2 + qq2
    gemm_tc<<<dim3(4, MTC), 256, GT_SMEM>>>(mid, f_w2, f_b2, qq2, (float*)d_out, M, 256, 512, 0);
    (void)in_sizes; (void)n_in; (void)out_size;
}

// round 14
// speedup vs baseline: 1.6692x; 1.0658x over previous
#include <cuda_runtime.h>
#include <cuda_bf16.h>
#include <cuda_fp16.h>
#include <math.h>
#include <stdint.h>

// Problem constants
#define BB    8
#define NQ    900
#define DD    256
#define HH    8
#define HD    32
#define PP    4
#define BEV   200
#define FFN   512
#define MROWS (BB * NQ)          // 7200

// ---------------- scratch (allocation-free: __device__ globals) -------------
__device__ float g_qin  [MROWS * DD];
__device__ float g_qkv  [MROWS * 3 * DD];
__device__ float g_attn [MROWS * DD];
__device__ float g_q1   [MROWS * DD];
__device__ float g_q2   [MROWS * DD];
__device__ float g_offs [MROWS * HH * PP * 2];
__device__ float g_wts  [MROWS * HH * PP];
__device__ float g_fused[MROWS * DD];
__device__ float g_qq2  [MROWS * DD];
__device__ float g_q3   [MROWS * DD];
__device__ float g_mid  [MROWS * FFN];

// ---------------- fused add + LayerNorm: warp per row, 8 rows/block ----------
__global__ void add_ln_warp(const float* __restrict__ a, const float* __restrict__ b,
                            const float* __restrict__ s, const float* __restrict__ bias,
                            float* __restrict__ out) {
    const unsigned full = 0xffffffffu;
    int w = threadIdx.x >> 5, lane = threadIdx.x & 31;
    int row = blockIdx.x * 8 + w;
    if (row >= MROWS) return;
    const float* ap = a + (size_t)row * DD;
    float4 x0 = *(const float4*)(ap + lane * 4);
    float4 x1 = *(const float4*)(ap + 128 + lane * 4);
    if (b) {
        const float* bp = b + (size_t)row * DD;
        float4 b0 = *(const float4*)(bp + lane * 4);
        float4 b1 = *(const float4*)(bp + 128 + lane * 4);
        x0.x += b0.x; x0.y += b0.y; x0.z += b0.z; x0.w += b0.w;
        x1.x += b1.x; x1.y += b1.y; x1.z += b1.z; x1.w += b1.w;
    }
    float sum = x0.x + x0.y + x0.z + x0.w + x1.x + x1.y + x1.z + x1.w;
    #pragma unroll
    for (int o = 16; o; o >>= 1) sum += __shfl_xor_sync(full, sum, o);
    float mean = sum * (1.f / DD);
    float c0x = x0.x - mean, c0y = x0.y - mean, c0z = x0.z - mean, c0w = x0.w - mean;
    float c1x = x1.x - mean, c1y = x1.y - mean, c1z = x1.z - mean, c1w = x1.w - mean;
    float vs = c0x*c0x + c0y*c0y + c0z*c0z + c0w*c0w
             + c1x*c1x + c1y*c1y + c1z*c1z + c1w*c1w;
    #pragma unroll
    for (int o = 16; o; o >>= 1) vs += __shfl_xor_sync(full, vs, o);
    float inv = rsqrtf(vs * (1.f / DD) + 1e-5f);
    float4 s0 = *(const float4*)(s + lane * 4);
    float4 s1 = *(const float4*)(s + 128 + lane * 4);
    float4 g0 = *(const float4*)(bias + lane * 4);
    float4 g1 = *(const float4*)(bias + 128 + lane * 4);
    float* op = out + (size_t)row * DD;
    *(float4*)(op + lane * 4) = make_float4(
        c0x * inv * s0.x + g0.x, c0y * inv * s0.y + g0.y,
        c0z * inv * s0.z + g0.z, c0w * inv * s0.w + g0.w);
    *(float4*)(op + 128 + lane * 4) = make_float4(
        c1x * inv * s1.x + g1.x, c1y * inv * s1.y + g1.y,
        c1z * inv * s1.z + g1.z, c1w * inv * s1.w + g1.w);
}

// ---------------- fp16 helpers ----------------------------------------------
__device__ __forceinline__ uint32_t f2h2(float lo, float hi) {
    __half2 h = __floats2half2_rn(lo, hi);
    return *(uint32_t*)&h;
}
// fp16 m16n8k16 mma, fp32 accumulate. D layout identical to m16n8k8.
__device__ __forceinline__ void mmaf16(float* d, const uint32_t* a, const uint32_t* b) {
    asm volatile(
        "mma.sync.aligned.m16n8k16.row.col.f32.f16.f16.f32 "
        "{%0,%1,%2,%3}, {%4,%5,%6,%7}, {%8,%9}, {%0,%1,%2,%3};\n"
        : "+f"(d[0]), "+f"(d[1]), "+f"(d[2]), "+f"(d[3])
        : "r"(a[0]), "r"(a[1]), "r"(a[2]), "r"(a[3]), "r"(b[0]), "r"(b[1]));
}

__device__ __forceinline__ uint32_t smem_u32(const void* p) {
    uint32_t a;
    asm("{ .reg .u64 t; cvta.to.shared.u64 t, %1; cvt.u32.u64 %0, t; }"
        : "=r"(a) : "l"(p));
    return a;
}
__device__ __forceinline__ void cpa16(uint32_t d, const float* s) {
    asm volatile("cp.async.cg.shared.global [%0], [%1], 16;"
                 :: "r"(d), "l"(s) : "memory");
}

// ---------------- tensor-core NT GEMM (fp16 mma): C = A*B^T + epi -----------
// 128x64 tile, BK=16, 4-stage cp.async (fp32 staging), 8 warps 4x2, 2 CTAs/SM.
// fp16 m16n8k16: one mma per (mi,ni) per 16-K iter. Fragment k-pairs are the
// natural f16 layout (k=2tg,2tg+1 and +8) -> float2 LDS.64 + one f16x2 cvt.
// SSTR=24 floats: fragment word = row*12 + {tg, 4+tg} -> conflict-free.
#define SSTR 24
#define STAGE_FLOATS ((128 + 64) * SSTR)       // 4608 floats = 18432 B
#define NSTAGE 4
#define GT_SMEM (NSTAGE * STAGE_FLOATS * 4)    // 73728 B
__global__ __launch_bounds__(256, 2)
void gemm_tc(const float* __restrict__ A, const float* __restrict__ B,
             const float* __restrict__ bias, const float* __restrict__ resid,
             float* __restrict__ C, int M, int N, int K, int relu) {
    extern __shared__ __align__(16) float sm[];
    const int tid = threadIdx.x;
    const int lane = tid & 31, wid = tid >> 5;
    const int g = lane >> 2, tg = lane & 3;
    const int wm = (wid >> 1) * 32, wn = (wid & 1) * 32;
    const int bm = blockIdx.y * 128, bn = blockIdx.x * 64;

    const int rowA0 = tid >> 2, rowA1 = rowA0 + 64;
    const int rowB  = tid >> 2;            // 0..63
    const int kq    = (tid & 3) * 4;

    int gm0 = bm + rowA0; if (gm0 >= M) gm0 = M - 1;
    int gm1 = bm + rowA1; if (gm1 >= M) gm1 = M - 1;
    const float* a0p = A + (size_t)gm0 * K + kq;
    const float* a1p = A + (size_t)gm1 * K + kq;
    const float* bp  = B + (size_t)(bn + rowB) * K + kq;

    const uint32_t sbase = smem_u32(sm);
    const uint32_t dA0 = sbase + (uint32_t)(rowA0 * SSTR + kq) * 4u;
    const uint32_t dA1 = sbase + (uint32_t)(rowA1 * SSTR + kq) * 4u;
    const uint32_t dB  = sbase + (uint32_t)(128 * SSTR + rowB * SSTR + kq) * 4u;

    const int NIT = K >> 4;   // 16 or 32

    #pragma unroll
    for (int s = 0; s < 3; s++) {
        uint32_t off = (uint32_t)(s * STAGE_FLOATS) * 4u;
        cpa16(dA0 + off, a0p + s * 16);
        cpa16(dA1 + off, a1p + s * 16);
        cpa16(dB  + off, bp  + s * 16);
        asm volatile("cp.async.commit_group;" ::: "memory");
    }

    float acc[2][4][4];
    #pragma unroll
    for (int mi = 0; mi < 2; mi++)
        #pragma unroll
        for (int ni = 0; ni < 4; ni++)
            #pragma unroll
            for (int r = 0; r < 4; r++) acc[mi][ni][r] = 0.f;

    for (int i = 0; i < NIT; i++) {
        if (i <= NIT - 3)      asm volatile("cp.async.wait_group 2;" ::: "memory");
        else if (i == NIT - 2) asm volatile("cp.async.wait_group 1;" ::: "memory");
        else                   asm volatile("cp.async.wait_group 0;" ::: "memory");
        __syncthreads();

        int snext = i + 3;
        if (snext < NIT) {
            uint32_t off = (uint32_t)((snext & 3) * STAGE_FLOATS) * 4u;
            const int kof = snext * 16;
            cpa16(dA0 + off, a0p + kof);
            cpa16(dA1 + off, a1p + kof);
            cpa16(dB  + off, bp  + kof);
            asm volatile("cp.async.commit_group;" ::: "memory");
        }

        const float* Abuf = sm + (i & 3) * STAGE_FLOATS;
        const float* Bbuf = Abuf + 128 * SSTR;
        uint32_t af[2][4], bf[4][2];
        #pragma unroll
        for (int mi = 0; mi < 2; mi++) {
            const float* r0b = &Abuf[(wm + mi * 16 + g) * SSTR];
            const float* r1b = r0b + 8 * SSTR;
            float2 a00 = *(const float2*)(r0b + 2 * tg);
            float2 a10 = *(const float2*)(r1b + 2 * tg);
            float2 a01 = *(const float2*)(r0b + 8 + 2 * tg);
            float2 a11 = *(const float2*)(r1b + 8 + 2 * tg);
            af[mi][0] = f2h2(a00.x, a00.y);
            af[mi][1] = f2h2(a10.x, a10.y);
            af[mi][2] = f2h2(a01.x, a01.y);
            af[mi][3] = f2h2(a11.x, a11.y);
        }
        #pragma unroll
        for (int ni = 0; ni < 4; ni++) {
            const float* cb = &Bbuf[(wn + ni * 8 + g) * SSTR];
            float2 b0 = *(const float2*)(cb + 2 * tg);
            float2 b1 = *(const float2*)(cb + 8 + 2 * tg);
            bf[ni][0] = f2h2(b0.x, b0.y);
            bf[ni][1] = f2h2(b1.x, b1.y);
        }
        #pragma unroll
        for (int mi = 0; mi < 2; mi++)
            #pragma unroll
            for (int ni = 0; ni < 4; ni++)
                mmaf16(acc[mi][ni], af[mi], bf[ni]);
    }

    #pragma unroll
    for (int ni = 0; ni < 4; ni++) {
        int c = bn + wn + ni * 8 + 2 * tg;
        float b0 = bias ? bias[c] : 0.f;
        float b1 = bias ? bias[c + 1] : 0.f;
        #pragma unroll
        for (int mi = 0; mi < 2; mi++) {
            int r0 = bm + wm + mi * 16 + g;
            int r1 = r0 + 8;
            float v0 = acc[mi][ni][0] + b0, v1 = acc[mi][ni][1] + b1;
            float v2 = acc[mi][ni][2] + b0, v3 = acc[mi][ni][3] + b1;
            if (relu) {
                v0 = fmaxf(v0, 0.f); v1 = fmaxf(v1, 0.f);
                v2 = fmaxf(v2, 0.f); v3 = fmaxf(v3, 0.f);
            }
            if (r0 < M) {
                if (resid) {
                    float2 rr = *(const float2*)(resid + (size_t)r0 * N + c);
                    v0 += rr.x; v1 += rr.y;
                }
                *(float2*)(C + (size_t)r0 * N + c) = make_float2(v0, v1);
            }
            if (r1 < M) {
                if (resid) {
                    float2 rr = *(const float2*)(resid + (size_t)r1 * N + c);
                    v2 += rr.x; v3 += rr.y;
                }
                *(float2*)(C + (size_t)r1 * N + c) = make_float2(v2, v3);
            }
        }
    }
}

// ---------------- small NT GEMM (N=32 weights head) --------------------------
__global__ void gemm_nt(const float* __restrict__ A, const float* __restrict__ B,
                        const float* __restrict__ bias, const float* __restrict__ resid,
                        float* __restrict__ C, int M, int N, int K, int relu) {
    __shared__ float As[16][68];
    __shared__ float Bs[16][68];
    int tid = threadIdx.x;
    int tx = tid & 15, ty = tid >> 4;
    int bm = blockIdx.y * 64, bn = blockIdx.x * 64;
    int lm = tid >> 2;
    int kq = (tid & 3) * 4;
    float acc[4][4] = {};
    for (int k0 = 0; k0 < K; k0 += 16) {
        int gm = bm + lm;
        float4 va = make_float4(0.f, 0.f, 0.f, 0.f);
        if (gm < M) va = *(const float4*)(A + (size_t)gm * K + k0 + kq);
        As[kq + 0][lm] = va.x; As[kq + 1][lm] = va.y;
        As[kq + 2][lm] = va.z; As[kq + 3][lm] = va.w;
        int gn = bn + lm;
        float4 vb = make_float4(0.f, 0.f, 0.f, 0.f);
        if (gn < N) vb = *(const float4*)(B + (size_t)gn * K + k0 + kq);
        Bs[kq + 0][lm] = vb.x; Bs[kq + 1][lm] = vb.y;
        Bs[kq + 2][lm] = vb.z; Bs[kq + 3][lm] = vb.w;
        __syncthreads();
        #pragma unroll
        for (int k = 0; k < 16; k++) {
            float4 a4 = *(const float4*)&As[k][ty * 4];
            float4 b4 = *(const float4*)&Bs[k][tx * 4];
            float af[4] = {a4.x, a4.y, a4.z, a4.w};
            float bf[4] = {b4.x, b4.y, b4.z, b4.w};
            #pragma unroll
            for (int i = 0; i < 4; i++)
                #pragma unroll
                for (int j = 0; j < 4; j++)
                    acc[i][j] += af[i] * bf[j];
        }
        __syncthreads();
    }
    #pragma unroll
    for (int i = 0; i < 4; i++) {
        int r = bm + ty * 4 + i;
        if (r >= M) continue;
        #pragma unroll
        for (int j = 0; j < 4; j++) {
            int c = bn + tx * 4 + j;
            if (c >= N) continue;
            float v = acc[i][j];
            if (bias) v += bias[c];
            if (relu) v = fmaxf(v, 0.f);
            if (resid) v += resid[(size_t)r * N + c];
            C[(size_t)r * N + c] = v;
        }
    }
}

// ---------------- tensor-core flash attention (fp16 mma) ---------------------
// 64-query blocks, 4 warps (16 q each), 64-key tiles, HD=32.
// K/V/P stored raw fp32 in smem; f16x2 cvt at fragment load.
// Ks [64 key][32 d] stride 40; Vs [32 d][64 key] stride 72; Ps stride 72.
#define KSTR 40
#define VSTR 72
#define PSTR 72
__global__ __launch_bounds__(128)
void attn3_kernel(const float* __restrict__ qkv, float* __restrict__ out) {
    __shared__ __align__(16) float Ks[64 * KSTR];
    __shared__ __align__(16) float Vs[32 * VSTR];
    __shared__ __align__(16) float Ps[64 * PSTR];

    const int b = blockIdx.z, h = blockIdx.y, qt = blockIdx.x;
    const int tid = threadIdx.x;
    const int w = tid >> 5, lane = tid & 31;
    const int g = lane >> 2, tg = lane & 3;
    const float scale = 0.17677669529663687f;   // 1/sqrt(32)
    const unsigned full = 0xffffffffu;

    // ---- Q fragments (pre-scaled, packed f16x2 k-pairs), 2 k16 steps ----
    const int r0 = qt * 64 + w * 16 + g;
    const int r1 = r0 + 8;
    uint32_t qa[2][4];
    {
        const float* q0p = qkv + ((size_t)(b * NQ + (r0 < NQ ? r0 : 0))) * 768 + h * HD;
        const float* q1p = qkv + ((size_t)(b * NQ + (r1 < NQ ? r1 : 0))) * 768 + h * HD;
        bool v0 = r0 < NQ, v1 = r1 < NQ;
        #pragma unroll
        for (int s = 0; s < 2; s++) {
            int c0 = s * 16 + 2 * tg;
            qa[s][0] = v0 ? f2h2(q0p[c0] * scale, q0p[c0 + 1] * scale) : 0u;
            qa[s][1] = v1 ? f2h2(q1p[c0] * scale, q1p[c0 + 1] * scale) : 0u;
            qa[s][2] = v0 ? f2h2(q0p[c0 + 8] * scale, q0p[c0 + 9] * scale) : 0u;
            qa[s][3] = v1 ? f2h2(q1p[c0 + 8] * scale, q1p[c0 + 9] * scale) : 0u;
        }
    }

    float m0 = -INFINITY, m1 = -INFINITY, l0 = 0.f, l1 = 0.f;
    float O[4][4];
    #pragma unroll
    for (int nd = 0; nd < 4; nd++)
        #pragma unroll
        for (int r = 0; r < 4; r++) O[nd][r] = 0.f;

    const int NKT = (NQ + 63) / 64;   // 15
    for (int jt = 0; jt < NKT; jt++) {
        __syncthreads();
        // ---- load K tile raw and V tile transposed raw ----
        {
            int key = tid >> 1, dh = (tid & 1) * 16;
            int kk = jt * 64 + key;
            if (kk < NQ) {
                const float* srcK = qkv + ((size_t)(b * NQ + kk)) * 768 + 256 + h * HD + dh;
                const float* srcV = srcK + 256;
                #pragma unroll
                for (int i = 0; i < 4; i++) {
                    *(float4*)&Ks[key * KSTR + dh + i * 4] = *(const float4*)(srcK + i * 4);
                    float4 vv = *(const float4*)(srcV + i * 4);
                    Vs[(dh + i * 4 + 0) * VSTR + key] = vv.x;
                    Vs[(dh + i * 4 + 1) * VSTR + key] = vv.y;
                    Vs[(dh + i * 4 + 2) * VSTR + key] = vv.z;
                    Vs[(dh + i * 4 + 3) * VSTR + key] = vv.w;
                }
            } else {
                #pragma unroll
                for (int i = 0; i < 4; i++) {
                    *(float4*)&Ks[key * KSTR + dh + i * 4] = make_float4(0.f, 0.f, 0.f, 0.f);
                    Vs[(dh + i * 4 + 0) * VSTR + key] = 0.f;
                    Vs[(dh + i * 4 + 1) * VSTR + key] = 0.f;
                    Vs[(dh + i * 4 + 2) * VSTR + key] = 0.f;
                    Vs[(dh + i * 4 + 3) * VSTR + key] = 0.f;
                }
            }
        }
        __syncthreads();

        // ---- QK: S[16 x 64] per warp, fp16 k16 mmas (2 per ni) ----
        float sacc[8][4];
        #pragma unroll
        for (int ni = 0; ni < 8; ni++)
            #pragma unroll
            for (int r = 0; r < 4; r++) sacc[ni][r] = 0.f;
        #pragma unroll
        for (int s = 0; s < 2; s++) {
            #pragma unroll
            for (int ni = 0; ni < 8; ni++) {
                const float* kb = &Ks[(ni * 8 + g) * KSTR + s * 16];
                float2 k0 = *(const float2*)(kb + 2 * tg);
                float2 k1 = *(const float2*)(kb + 8 + 2 * tg);
                uint32_t bf[2] = { f2h2(k0.x, k0.y), f2h2(k1.x, k1.y) };
                mmaf16(sacc[ni], qa[s], bf);
            }
        }
        // ---- mask invalid keys ----
        int kglob = jt * 64;
        if (kglob + 64 > NQ) {
            #pragma unroll
            for (int ni = 0; ni < 8; ni++) {
                int kc = kglob + ni * 8 + 2 * tg;
                if (kc >= NQ)     { sacc[ni][0] = -1e30f; sacc[ni][2] = -1e30f; }
                if (kc + 1 >= NQ) { sacc[ni][1] = -1e30f; sacc[ni][3] = -1e30f; }
            }
        }

        // ---- online softmax (rows g and g+8; quad reduce over tg lanes) ----
        float mx0 = -INFINITY, mx1 = -INFINITY;
        #pragma unroll
        for (int ni = 0; ni < 8; ni++) {
            mx0 = fmaxf(mx0, fmaxf(sacc[ni][0], sacc[ni][1]));
            mx1 = fmaxf(mx1, fmaxf(sacc[ni][2], sacc[ni][3]));
        }
        mx0 = fmaxf(mx0, __shfl_xor_sync(full, mx0, 1));
        mx0 = fmaxf(mx0, __shfl_xor_sync(full, mx0, 2));
        mx1 = fmaxf(mx1, __shfl_xor_sync(full, mx1, 1));
        mx1 = fmaxf(mx1, __shfl_xor_sync(full, mx1, 2));
        float nm0 = fmaxf(m0, mx0), nm1 = fmaxf(m1, mx1);
        float fac0 = __expf(m0 - nm0), fac1 = __expf(m1 - nm1);
        float sum0 = 0.f, sum1 = 0.f;
        #pragma unroll
        for (int ni = 0; ni < 8; ni++) {
            sacc[ni][0] = __expf(sacc[ni][0] - nm0);
            sacc[ni][1] = __expf(sacc[ni][1] - nm0);
            sacc[ni][2] = __expf(sacc[ni][2] - nm1);
            sacc[ni][3] = __expf(sacc[ni][3] - nm1);
            sum0 += sacc[ni][0] + sacc[ni][1];
            sum1 += sacc[ni][2] + sacc[ni][3];
        }
        sum0 += __shfl_xor_sync(full, sum0, 1);
        sum0 += __shfl_xor_sync(full, sum0, 2);
        sum1 += __shfl_xor_sync(full, sum1, 1);
        sum1 += __shfl_xor_sync(full, sum1, 2);
        l0 = l0 * fac0 + sum0; m0 = nm0;
        l1 = l1 * fac1 + sum1; m1 = nm1;

        // ---- store P to smem (warp-private rows, adjacent key pairs) ----
        int q0 = w * 16 + g;
        #pragma unroll
        for (int ni = 0; ni < 8; ni++) {
            *(float2*)&Ps[q0 * PSTR + ni * 8 + 2 * tg] =
                make_float2(sacc[ni][0], sacc[ni][1]);
            *(float2*)&Ps[(q0 + 8) * PSTR + ni * 8 + 2 * tg] =
                make_float2(sacc[ni][2], sacc[ni][3]);
        }
        __syncwarp();

        // ---- rescale O, then PV: fp16 k16 mmas (4 s-steps over 64 keys) ----
        #pragma unroll
        for (int nd = 0; nd < 4; nd++) {
            O[nd][0] *= fac0; O[nd][1] *= fac0;
            O[nd][2] *= fac1; O[nd][3] *= fac1;
        }
        #pragma unroll
        for (int s = 0; s < 4; s++) {
            const float* p0b = &Ps[q0 * PSTR + s * 16];
            const float* p1b = &Ps[(q0 + 8) * PSTR + s * 16];
            float2 p00 = *(const float2*)(p0b + 2 * tg);
            float2 p10 = *(const float2*)(p1b + 2 * tg);
            float2 p01 = *(const float2*)(p0b + 8 + 2 * tg);
            float2 p11 = *(const float2*)(p1b + 8 + 2 * tg);
            uint32_t pa[4] = { f2h2(p00.x, p00.y), f2h2(p10.x, p10.y),
                               f2h2(p01.x, p01.y), f2h2(p11.x, p11.y) };
            #pragma unroll
            for (int nd = 0; nd < 4; nd++) {
                const float* vb = &Vs[(nd * 8 + g) * VSTR + s * 16];
                float2 v0 = *(const float2*)(vb + 2 * tg);
                float2 v1 = *(const float2*)(vb + 8 + 2 * tg);
                uint32_t bf[2] = { f2h2(v0.x, v0.y), f2h2(v1.x, v1.y) };
                mmaf16(O[nd], pa, bf);
            }
        }
    }

    // ---- epilogue ----
    float inv0 = 1.f / l0, inv1 = 1.f / l1;
    #pragma unroll
    for (int nd = 0; nd < 4; nd++) {
        int c = h * HD + nd * 8 + 2 * tg;
        if (r0 < NQ)
            *(float2*)(out + ((size_t)(b * NQ + r0)) * DD + c) =
                make_float2(O[nd][0] * inv0, O[nd][1] * inv0);
        if (r1 < NQ)
            *(float2*)(out + ((size_t)(b * NQ + r1)) * DD + c) =
                make_float2(O[nd][2] * inv1, O[nd][3] * inv1);
    }
}

// ---------------- deformable sampling: warp = (head), block = (b,q) ---------
__global__ void sample_kernel(const float* __restrict__ mem, const float* __restrict__ ref,
                              const float* __restrict__ offs, const float* __restrict__ wts,
                              float* __restrict__ fused) {
    int row = blockIdx.x;
    int b = row / NQ;
    int h = threadIdx.x >> 5;
    int lane = threadIdx.x & 31;
    const unsigned full = 0xffffffffu;
    float rx = ref[row * 2], ry = ref[row * 2 + 1];
    float gx = 0.f, gy = 0.f, wl = 0.f;
    if (lane < PP) {
        float ox = offs[(size_t)row * (HH * PP * 2) + h * (PP * 2) + lane * 2];
        float oy = offs[(size_t)row * (HH * PP * 2) + h * (PP * 2) + lane * 2 + 1];
        gx = (rx + tanhf(ox) * 0.2f) * (float)BEV - 0.5f;
        gy = (ry + tanhf(oy) * 0.2f) * (float)BEV - 0.5f;
        wl = wts[(size_t)row * (HH * PP) + h * PP + lane];
    }
    float m = wl;
    m = fmaxf(m, __shfl_xor_sync(full, m, 1));
    m = fmaxf(m, __shfl_xor_sync(full, m, 2));
    float e = __expf(wl - m);
    float ssum = e;
    ssum += __shfl_xor_sync(full, ssum, 1);
    ssum += __shfl_xor_sync(full, ssum, 2);
    float w = e / ssum;
    const float* mb = mem + (size_t)b * (BEV * BEV) * DD + h * HD + lane;
    float acc = 0.f;
    #pragma unroll
    for (int p = 0; p < PP; p++) {
        float px = __shfl_sync(full, gx, p);
        float py = __shfl_sync(full, gy, p);
        float pw = __shfl_sync(full, w, p);
        float x0f = floorf(px), y0f = floorf(py);
        float wx1 = px - x0f, wy1 = py - y0f;
        float wx0 = 1.f - wx1, wy0 = 1.f - wy1;
        int x0 = (int)x0f, y0 = (int)y0f;
        bool xv0 = (x0 >= 0) && (x0 < BEV);
        bool xv1 = (x0 + 1 >= 0) && (x0 + 1 < BEV);
        bool yv0 = (y0 >= 0) && (y0 < BEV);
        bool yv1 = (y0 + 1 >= 0) && (y0 + 1 < BEV);
        float v = 0.f;
        if (yv0) {
            if (xv0) v += wx0 * wy0 * mb[(size_t)(y0 * BEV + x0) * DD];
            if (xv1) v += wx1 * wy0 * mb[(size_t)(y0 * BEV + x0 + 1) * DD];
        }
        if (yv1) {
            if (xv0) v += wx0 * wy1 * mb[(size_t)((y0 + 1) * BEV + x0) * DD];
            if (xv1) v += wx1 * wy1 * mb[(size_t)((y0 + 1) * BEV + x0 + 1) * DD];
        }
        acc += pw * v;
    }
    fused[(size_t)row * DD + h * HD + lane] = acc;
}

// ---------------- host launcher ---------------------------------------------
extern "C" void kernel_launch(void* const* d_in, const int* in_sizes, int n_in,
                              void* d_out, int out_size) {
    const float* query = (const float*)d_in[0];
    const float* memory = (const float*)d_in[1];
    const float* refp  = (const float*)d_in[2];
    const float* qpos  = (const float*)d_in[3];
    const float* in_w  = (const float*)d_in[4];
    const float* in_b  = (const float*)d_in[5];
    const float* out_w = (const float*)d_in[6];
    const float* out_b = (const float*)d_in[7];
    const float* off_w = (const float*)d_in[8];
    const float* off_b = (const float*)d_in[9];
    const float* wt_w  = (const float*)d_in[10];
    const float* wt_b  = (const float*)d_in[11];
    const float* co_w  = (const float*)d_in[12];
    const float* co_b  = (const float*)d_in[13];
    const float* f_w1  = (const float*)d_in[14];
    const float* f_b1  = (const float*)d_in[15];
    const float* f_w2  = (const float*)d_in[16];
    const float* f_b2  = (const float*)d_in[17];
    const float* n1s   = (const float*)d_in[18];
    const float* n1b   = (const float*)d_in[19];
    const float* n2s   = (const float*)d_in[20];
    const float* n2b   = (const float*)d_in[21];
    const float* n3s   = (const float*)d_in[22];
    const float* n3b   = (const float*)d_in[23];

    float *qin, *qkv, *attn, *q1, *q2, *offs, *wts, *fused, *qq2, *q3, *mid;
    cudaGetSymbolAddress((void**)&qin,   g_qin);
    cudaGetSymbolAddress((void**)&qkv,   g_qkv);
    cudaGetSymbolAddress((void**)&attn,  g_attn);
    cudaGetSymbolAddress((void**)&q1,    g_q1);
    cudaGetSymbolAddress((void**)&q2,    g_q2);
    cudaGetSymbolAddress((void**)&offs,  g_offs);
    cudaGetSymbolAddress((void**)&wts,   g_wts);
    cudaGetSymbolAddress((void**)&fused, g_fused);
    cudaGetSymbolAddress((void**)&qq2,   g_qq2);
    cudaGetSymbolAddress((void**)&q3,    g_q3);
    cudaGetSymbolAddress((void**)&mid,   g_mid);

    const int M = MROWS;
    const int MTC  = (M + 127) / 128;    // 57
    const int MT64 = (M + 63) / 64;      // 113
    const int LNG  = (M + 7) / 8;        // 900

    cudaFuncSetAttribute(gemm_tc, cudaFuncAttributeMaxDynamicSharedMemorySize,
                         GT_SMEM);

    // 1. q_in = LN(query + query_pos)
    add_ln_warp<<<LNG, 256>>>(query, qpos, n1s, n1b, qin);
    // 2. qkv = q_in @ in_w^T + in_b
    gemm_tc<<<dim3(12, MTC), 256, GT_SMEM>>>(qin, in_w, in_b, nullptr, qkv, M, 768, 256, 0);
    // 3. self-attention (tensor-core flash, fp16 mma)
    attn3_kernel<<<dim3((NQ + 63) / 64, HH, BB), 128>>>(qkv, attn);
    // 4. q1 = attn @ out_w^T + out_b + query
    gemm_tc<<<dim3(4, MTC), 256, GT_SMEM>>>(attn, out_w, out_b, query, q1, M, 256, 256, 0);
    // 5. q2 = LN(q1 + query_pos)
    add_ln_warp<<<LNG, 256>>>(q1, qpos, n2s, n2b, q2);
    // 6/7. offset + weight heads
    gemm_tc<<<dim3(1, MTC), 256, GT_SMEM>>>(q2, off_w, off_b, nullptr, offs, M, 64, 256, 0);
    gemm_nt<<<dim3(1, MT64), 256>>>(q2, wt_w, wt_b, nullptr, wts, M, 32, 256, 0);
    // 8. deformable BEV sampling -> fused
    sample_kernel<<<M, 256>>>(memory, refp, offs, wts, fused);
    // 9. qq2 = fused @ co_w^T + co_b + q1
    gemm_tc<<<dim3(4, MTC), 256, GT_SMEM>>>(fused, co_w, co_b, q1, qq2, M, 256, 256, 0);
    // 10. q3 = LN(qq2)
    add_ln_warp<<<LNG, 256>>>(qq2, nullptr, n3s, n3b, q3);
    // 11. mid = relu(q3 @ f_w1^T + f_b1)
    gemm_tc<<<dim3(8, MTC), 256, GT_SMEM>>>(q3, f_w1, f_b1, nullptr, mid, M, 512, 256, 1);
    // 12. out = mid @ f_w2^T + f_b2 + qq2
    gemm_tc<<<dim3(4, MTC), 256, GT_SMEM>>>(mid, f_w2, f_b2, qq2, (float*)d_out, M, 256, 512, 0);
    (void)in_sizes; (void)n_in; (void)out_size;
}

// round 15
// speedup vs baseline: 1.8051x; 1.0814x over previous
#include <cuda_runtime.h>
#include <cuda_bf16.h>
#include <cuda_fp16.h>
#include <math.h>
#include <stdint.h>

// Problem constants
#define BB    8
#define NQ    900
#define DD    256
#define HH    8
#define HD    32
#define PP    4
#define BEV   200
#define FFN   512
#define MROWS (BB * NQ)          // 7200

// ---------------- scratch (allocation-free: __device__ globals) -------------
__device__ float g_qin  [MROWS * DD];
__device__ float g_qkv  [MROWS * 3 * DD];
__device__ float g_attn [MROWS * DD];
__device__ float g_q1   [MROWS * DD];
__device__ float g_q2   [MROWS * DD];
__device__ float g_offs [MROWS * HH * PP * 2];
__device__ float g_wts  [MROWS * HH * PP];
__device__ float g_fused[MROWS * DD];
__device__ float g_qq2  [MROWS * DD];
__device__ float g_q3   [MROWS * DD];
__device__ float g_mid  [MROWS * FFN];

// ---------------- fused add + LayerNorm: warp per row, 8 rows/block ----------
__global__ void add_ln_warp(const float* __restrict__ a, const float* __restrict__ b,
                            const float* __restrict__ s, const float* __restrict__ bias,
                            float* __restrict__ out) {
    const unsigned full = 0xffffffffu;
    int w = threadIdx.x >> 5, lane = threadIdx.x & 31;
    int row = blockIdx.x * 8 + w;
    if (row >= MROWS) return;
    const float* ap = a + (size_t)row * DD;
    float4 x0 = *(const float4*)(ap + lane * 4);
    float4 x1 = *(const float4*)(ap + 128 + lane * 4);
    if (b) {
        const float* bp = b + (size_t)row * DD;
        float4 b0 = *(const float4*)(bp + lane * 4);
        float4 b1 = *(const float4*)(bp + 128 + lane * 4);
        x0.x += b0.x; x0.y += b0.y; x0.z += b0.z; x0.w += b0.w;
        x1.x += b1.x; x1.y += b1.y; x1.z += b1.z; x1.w += b1.w;
    }
    float sum = x0.x + x0.y + x0.z + x0.w + x1.x + x1.y + x1.z + x1.w;
    #pragma unroll
    for (int o = 16; o; o >>= 1) sum += __shfl_xor_sync(full, sum, o);
    float mean = sum * (1.f / DD);
    float c0x = x0.x - mean, c0y = x0.y - mean, c0z = x0.z - mean, c0w = x0.w - mean;
    float c1x = x1.x - mean, c1y = x1.y - mean, c1z = x1.z - mean, c1w = x1.w - mean;
    float vs = c0x*c0x + c0y*c0y + c0z*c0z + c0w*c0w
             + c1x*c1x + c1y*c1y + c1z*c1z + c1w*c1w;
    #pragma unroll
    for (int o = 16; o; o >>= 1) vs += __shfl_xor_sync(full, vs, o);
    float inv = rsqrtf(vs * (1.f / DD) + 1e-5f);
    float4 s0 = *(const float4*)(s + lane * 4);
    float4 s1 = *(const float4*)(s + 128 + lane * 4);
    float4 g0 = *(const float4*)(bias + lane * 4);
    float4 g1 = *(const float4*)(bias + 128 + lane * 4);
    float* op = out + (size_t)row * DD;
    *(float4*)(op + lane * 4) = make_float4(
        c0x * inv * s0.x + g0.x, c0y * inv * s0.y + g0.y,
        c0z * inv * s0.z + g0.z, c0w * inv * s0.w + g0.w);
    *(float4*)(op + 128 + lane * 4) = make_float4(
        c1x * inv * s1.x + g1.x, c1y * inv * s1.y + g1.y,
        c1z * inv * s1.z + g1.z, c1w * inv * s1.w + g1.w);
}

// ---------------- fp16 helpers ----------------------------------------------
__device__ __forceinline__ uint32_t f2h2(float lo, float hi) {
    __half2 h = __floats2half2_rn(lo, hi);
    return *(uint32_t*)&h;
}
__device__ __forceinline__ void mmaf16(float* d, const uint32_t* a, const uint32_t* b) {
    asm volatile(
        "mma.sync.aligned.m16n8k16.row.col.f32.f16.f16.f32 "
        "{%0,%1,%2,%3}, {%4,%5,%6,%7}, {%8,%9}, {%0,%1,%2,%3};\n"
        : "+f"(d[0]), "+f"(d[1]), "+f"(d[2]), "+f"(d[3])
        : "r"(a[0]), "r"(a[1]), "r"(a[2]), "r"(a[3]), "r"(b[0]), "r"(b[1]));
}

__device__ __forceinline__ uint32_t smem_u32(const void* p) {
    uint32_t a;
    asm("{ .reg .u64 t; cvta.to.shared.u64 t, %1; cvt.u32.u64 %0, t; }"
        : "=r"(a) : "l"(p));
    return a;
}
__device__ __forceinline__ void cpa16(uint32_t d, const float* s) {
    asm volatile("cp.async.cg.shared.global [%0], [%1], 16;"
                 :: "r"(d), "l"(s) : "memory");
}
// cp.async with src-size (0 -> zero-fill)
__device__ __forceinline__ void cpa16z(uint32_t d, const float* s, unsigned sz) {
    asm volatile("cp.async.cg.shared.global [%0], [%1], 16, %2;"
                 :: "r"(d), "l"(s), "r"(sz) : "memory");
}

// ---------------- tensor-core NT GEMM (fp16 mma): C = A*B^T + epi -----------
// 128x64 tile, BK=16, 4-stage cp.async, 8 warps 4x2, 2 CTAs/SM. (round-13/14)
#define SSTR 24
#define STAGE_FLOATS ((128 + 64) * SSTR)       // 4608 floats = 18432 B
#define NSTAGE 4
#define GT_SMEM (NSTAGE * STAGE_FLOATS * 4)    // 73728 B
__global__ __launch_bounds__(256, 2)
void gemm_tc(const float* __restrict__ A, const float* __restrict__ B,
             const float* __restrict__ bias, const float* __restrict__ resid,
             float* __restrict__ C, int M, int N, int K, int relu) {
    extern __shared__ __align__(16) float sm[];
    const int tid = threadIdx.x;
    const int lane = tid & 31, wid = tid >> 5;
    const int g = lane >> 2, tg = lane & 3;
    const int wm = (wid >> 1) * 32, wn = (wid & 1) * 32;
    const int bm = blockIdx.y * 128, bn = blockIdx.x * 64;

    const int rowA0 = tid >> 2, rowA1 = rowA0 + 64;
    const int rowB  = tid >> 2;
    const int kq    = (tid & 3) * 4;

    int gm0 = bm + rowA0; if (gm0 >= M) gm0 = M - 1;
    int gm1 = bm + rowA1; if (gm1 >= M) gm1 = M - 1;
    const float* a0p = A + (size_t)gm0 * K + kq;
    const float* a1p = A + (size_t)gm1 * K + kq;
    const float* bp  = B + (size_t)(bn + rowB) * K + kq;

    const uint32_t sbase = smem_u32(sm);
    const uint32_t dA0 = sbase + (uint32_t)(rowA0 * SSTR + kq) * 4u;
    const uint32_t dA1 = sbase + (uint32_t)(rowA1 * SSTR + kq) * 4u;
    const uint32_t dB  = sbase + (uint32_t)(128 * SSTR + rowB * SSTR + kq) * 4u;

    const int NIT = K >> 4;

    #pragma unroll
    for (int s = 0; s < 3; s++) {
        uint32_t off = (uint32_t)(s * STAGE_FLOATS) * 4u;
        cpa16(dA0 + off, a0p + s * 16);
        cpa16(dA1 + off, a1p + s * 16);
        cpa16(dB  + off, bp  + s * 16);
        asm volatile("cp.async.commit_group;" ::: "memory");
    }

    float acc[2][4][4];
    #pragma unroll
    for (int mi = 0; mi < 2; mi++)
        #pragma unroll
        for (int ni = 0; ni < 4; ni++)
            #pragma unroll
            for (int r = 0; r < 4; r++) acc[mi][ni][r] = 0.f;

    for (int i = 0; i < NIT; i++) {
        if (i <= NIT - 3)      asm volatile("cp.async.wait_group 2;" ::: "memory");
        else if (i == NIT - 2) asm volatile("cp.async.wait_group 1;" ::: "memory");
        else                   asm volatile("cp.async.wait_group 0;" ::: "memory");
        __syncthreads();

        int snext = i + 3;
        if (snext < NIT) {
            uint32_t off = (uint32_t)((snext & 3) * STAGE_FLOATS) * 4u;
            const int kof = snext * 16;
            cpa16(dA0 + off, a0p + kof);
            cpa16(dA1 + off, a1p + kof);
            cpa16(dB  + off, bp  + kof);
            asm volatile("cp.async.commit_group;" ::: "memory");
        }

        const float* Abuf = sm + (i & 3) * STAGE_FLOATS;
        const float* Bbuf = Abuf + 128 * SSTR;
        uint32_t af[2][4], bf[4][2];
        #pragma unroll
        for (int mi = 0; mi < 2; mi++) {
            const float* r0b = &Abuf[(wm + mi * 16 + g) * SSTR];
            const float* r1b = r0b + 8 * SSTR;
            float2 a00 = *(const float2*)(r0b + 2 * tg);
            float2 a10 = *(const float2*)(r1b + 2 * tg);
            float2 a01 = *(const float2*)(r0b + 8 + 2 * tg);
            float2 a11 = *(const float2*)(r1b + 8 + 2 * tg);
            af[mi][0] = f2h2(a00.x, a00.y);
            af[mi][1] = f2h2(a10.x, a10.y);
            af[mi][2] = f2h2(a01.x, a01.y);
            af[mi][3] = f2h2(a11.x, a11.y);
        }
        #pragma unroll
        for (int ni = 0; ni < 4; ni++) {
            const float* cb = &Bbuf[(wn + ni * 8 + g) * SSTR];
            float2 b0 = *(const float2*)(cb + 2 * tg);
            float2 b1 = *(const float2*)(cb + 8 + 2 * tg);
            bf[ni][0] = f2h2(b0.x, b0.y);
            bf[ni][1] = f2h2(b1.x, b1.y);
        }
        #pragma unroll
        for (int mi = 0; mi < 2; mi++)
            #pragma unroll
            for (int ni = 0; ni < 4; ni++)
                mmaf16(acc[mi][ni], af[mi], bf[ni]);
    }

    #pragma unroll
    for (int ni = 0; ni < 4; ni++) {
        int c = bn + wn + ni * 8 + 2 * tg;
        float b0 = bias ? bias[c] : 0.f;
        float b1 = bias ? bias[c + 1] : 0.f;
        #pragma unroll
        for (int mi = 0; mi < 2; mi++) {
            int r0 = bm + wm + mi * 16 + g;
            int r1 = r0 + 8;
            float v0 = acc[mi][ni][0] + b0, v1 = acc[mi][ni][1] + b1;
            float v2 = acc[mi][ni][2] + b0, v3 = acc[mi][ni][3] + b1;
            if (relu) {
                v0 = fmaxf(v0, 0.f); v1 = fmaxf(v1, 0.f);
                v2 = fmaxf(v2, 0.f); v3 = fmaxf(v3, 0.f);
            }
            if (r0 < M) {
                if (resid) {
                    float2 rr = *(const float2*)(resid + (size_t)r0 * N + c);
                    v0 += rr.x; v1 += rr.y;
                }
                *(float2*)(C + (size_t)r0 * N + c) = make_float2(v0, v1);
            }
            if (r1 < M) {
                if (resid) {
                    float2 rr = *(const float2*)(resid + (size_t)r1 * N + c);
                    v2 += rr.x; v3 += rr.y;
                }
                *(float2*)(C + (size_t)r1 * N + c) = make_float2(v2, v3);
            }
        }
    }
}

// ---------------- small NT GEMM (N=32 weights head) --------------------------
__global__ void gemm_nt(const float* __restrict__ A, const float* __restrict__ B,
                        const float* __restrict__ bias, const float* __restrict__ resid,
                        float* __restrict__ C, int M, int N, int K, int relu) {
    __shared__ float As[16][68];
    __shared__ float Bs[16][68];
    int tid = threadIdx.x;
    int tx = tid & 15, ty = tid >> 4;
    int bm = blockIdx.y * 64, bn = blockIdx.x * 64;
    int lm = tid >> 2;
    int kq = (tid & 3) * 4;
    float acc[4][4] = {};
    for (int k0 = 0; k0 < K; k0 += 16) {
        int gm = bm + lm;
        float4 va = make_float4(0.f, 0.f, 0.f, 0.f);
        if (gm < M) va = *(const float4*)(A + (size_t)gm * K + k0 + kq);
        As[kq + 0][lm] = va.x; As[kq + 1][lm] = va.y;
        As[kq + 2][lm] = va.z; As[kq + 3][lm] = va.w;
        int gn = bn + lm;
        float4 vb = make_float4(0.f, 0.f, 0.f, 0.f);
        if (gn < N) vb = *(const float4*)(B + (size_t)gn * K + k0 + kq);
        Bs[kq + 0][lm] = vb.x; Bs[kq + 1][lm] = vb.y;
        Bs[kq + 2][lm] = vb.z; Bs[kq + 3][lm] = vb.w;
        __syncthreads();
        #pragma unroll
        for (int k = 0; k < 16; k++) {
            float4 a4 = *(const float4*)&As[k][ty * 4];
            float4 b4 = *(const float4*)&Bs[k][tx * 4];
            float af[4] = {a4.x, a4.y, a4.z, a4.w};
            float bf[4] = {b4.x, b4.y, b4.z, b4.w};
            #pragma unroll
            for (int i = 0; i < 4; i++)
                #pragma unroll
                for (int j = 0; j < 4; j++)
                    acc[i][j] += af[i] * bf[j];
        }
        __syncthreads();
    }
    #pragma unroll
    for (int i = 0; i < 4; i++) {
        int r = bm + ty * 4 + i;
        if (r >= M) continue;
        #pragma unroll
        for (int j = 0; j < 4; j++) {
            int c = bn + tx * 4 + j;
            if (c >= N) continue;
            float v = acc[i][j];
            if (bias) v += bias[c];
            if (relu) v = fmaxf(v, 0.f);
            if (resid) v += resid[(size_t)r * N + c];
            C[(size_t)r * N + c] = v;
        }
    }
}

// ---------------- tensor-core flash attention v4 -----------------------------
// fp16 mma; double-buffered cp.async K/V tiles (raw [key][d]); P in half2.
// Kb stride 40 (QK pair loads 20g+tg conflict-free); Vb stride 36 (PV single
// loads 8tg+g conflict-free); PsH stride 36 half2-words (4g+4ni+tg / 4g+8s+tg).
#define AKST 40
#define AVST 36
#define APST 36   // half2 words per P row
__global__ __launch_bounds__(128)
void attn4_kernel(const float* __restrict__ qkv, float* __restrict__ out) {
    __shared__ __align__(16) float    Kb[2][64 * AKST];   // 20480 B
    __shared__ __align__(16) float    Vb[2][64 * AVST];   // 18432 B
    __shared__ __align__(16) uint32_t PsH[64 * APST];     //  9216 B (total 48128)

    const int b = blockIdx.z, h = blockIdx.y, qt = blockIdx.x;
    const int tid = threadIdx.x;
    const int w = tid >> 5, lane = tid & 31;
    const int g = lane >> 2, tg = lane & 3;
    const float scale = 0.17677669529663687f;   // 1/sqrt(32)
    const unsigned full = 0xffffffffu;

    const uint32_t kb0 = smem_u32(&Kb[0][0]);
    const uint32_t vb0 = smem_u32(&Vb[0][0]);
    const uint32_t KBYTES = 64 * AKST * 4;
    const uint32_t VBYTES = 64 * AVST * 4;

    // ---- per-thread fill slots ----
    const int fkey = tid >> 1, fdh = (tid & 1) * 16;
    const uint32_t kdst = kb0 + (uint32_t)(fkey * AKST + fdh) * 4u;
    const uint32_t vdst = vb0 + (uint32_t)(fkey * AVST + fdh) * 4u;

    // ---- Q fragments (pre-scaled, packed f16x2 k-pairs), 2 k16 steps ----
    const int r0 = qt * 64 + w * 16 + g;
    const int r1 = r0 + 8;
    uint32_t qa[2][4];
    {
        const float* q0p = qkv + ((size_t)(b * NQ + (r0 < NQ ? r0 : 0))) * 768 + h * HD;
        const float* q1p = qkv + ((size_t)(b * NQ + (r1 < NQ ? r1 : 0))) * 768 + h * HD;
        bool v0 = r0 < NQ, v1 = r1 < NQ;
        #pragma unroll
        for (int s = 0; s < 2; s++) {
            int c0 = s * 16 + 2 * tg;
            qa[s][0] = v0 ? f2h2(q0p[c0] * scale, q0p[c0 + 1] * scale) : 0u;
            qa[s][1] = v1 ? f2h2(q1p[c0] * scale, q1p[c0 + 1] * scale) : 0u;
            qa[s][2] = v0 ? f2h2(q0p[c0 + 8] * scale, q0p[c0 + 9] * scale) : 0u;
            qa[s][3] = v1 ? f2h2(q1p[c0 + 8] * scale, q1p[c0 + 9] * scale) : 0u;
        }
    }

    float m0 = -INFINITY, m1 = -INFINITY, l0 = 0.f, l1 = 0.f;
    float O[4][4];
    #pragma unroll
    for (int nd = 0; nd < 4; nd++)
        #pragma unroll
        for (int r = 0; r < 4; r++) O[nd][r] = 0.f;

    const int NKT = (NQ + 63) / 64;   // 15

    // ---- prologue: fill tile 0 into buffer 0 ----
    {
        int kk = fkey;   // jt = 0
        const float* src = qkv + ((size_t)(b * NQ + (kk < NQ ? kk : 0))) * 768
                         + 256 + h * HD + fdh;
        unsigned sz = (kk < NQ) ? 16u : 0u;
        #pragma unroll
        for (int i = 0; i < 4; i++) {
            cpa16z(kdst + i * 16, src + i * 4, sz);
            cpa16z(vdst + i * 16, src + 256 + i * 4, sz);
        }
        asm volatile("cp.async.commit_group;" ::: "memory");
    }

    for (int jt = 0; jt < NKT; jt++) {
        asm volatile("cp.async.wait_group 0;" ::: "memory");
        __syncthreads();   // tile jt visible; all warps done with tile jt-1

        // refill tile jt+1 into the other buffer (consumed at jt-1)
        if (jt + 1 < NKT) {
            int kk = (jt + 1) * 64 + fkey;
            const float* src = qkv + ((size_t)(b * NQ + (kk < NQ ? kk : 0))) * 768
                             + 256 + h * HD + fdh;
            unsigned sz = (kk < NQ) ? 16u : 0u;
            uint32_t bo = ((jt + 1) & 1) ? 1u : 0u;
            uint32_t kd = kdst + bo * KBYTES;
            uint32_t vd = vdst + bo * VBYTES;
            #pragma unroll
            for (int i = 0; i < 4; i++) {
                cpa16z(kd + i * 16, src + i * 4, sz);
                cpa16z(vd + i * 16, src + 256 + i * 4, sz);
            }
            asm volatile("cp.async.commit_group;" ::: "memory");
        }

        const float* Kc = Kb[jt & 1];
        const float* Vc = Vb[jt & 1];

        // ---- QK: S[16 x 64] per warp, fp16 k16 mmas ----
        float sacc[8][4];
        #pragma unroll
        for (int ni = 0; ni < 8; ni++)
            #pragma unroll
            for (int r = 0; r < 4; r++) sacc[ni][r] = 0.f;
        #pragma unroll
        for (int s = 0; s < 2; s++) {
            #pragma unroll
            for (int ni = 0; ni < 8; ni++) {
                const float* kbp = &Kc[(ni * 8 + g) * AKST + s * 16];
                float2 k0 = *(const float2*)(kbp + 2 * tg);
                float2 k1 = *(const float2*)(kbp + 8 + 2 * tg);
                uint32_t bf[2] = { f2h2(k0.x, k0.y), f2h2(k1.x, k1.y) };
                mmaf16(sacc[ni], qa[s], bf);
            }
        }
        // ---- mask invalid keys ----
        int kglob = jt * 64;
        if (kglob + 64 > NQ) {
            #pragma unroll
            for (int ni = 0; ni < 8; ni++) {
                int kc = kglob + ni * 8 + 2 * tg;
                if (kc >= NQ)     { sacc[ni][0] = -1e30f; sacc[ni][2] = -1e30f; }
                if (kc + 1 >= NQ) { sacc[ni][1] = -1e30f; sacc[ni][3] = -1e30f; }
            }
        }

        // ---- online softmax ----
        float mx0 = -INFINITY, mx1 = -INFINITY;
        #pragma unroll
        for (int ni = 0; ni < 8; ni++) {
            mx0 = fmaxf(mx0, fmaxf(sacc[ni][0], sacc[ni][1]));
            mx1 = fmaxf(mx1, fmaxf(sacc[ni][2], sacc[ni][3]));
        }
        mx0 = fmaxf(mx0, __shfl_xor_sync(full, mx0, 1));
        mx0 = fmaxf(mx0, __shfl_xor_sync(full, mx0, 2));
        mx1 = fmaxf(mx1, __shfl_xor_sync(full, mx1, 1));
        mx1 = fmaxf(mx1, __shfl_xor_sync(full, mx1, 2));
        float nm0 = fmaxf(m0, mx0), nm1 = fmaxf(m1, mx1);
        float fac0 = __expf(m0 - nm0), fac1 = __expf(m1 - nm1);
        float sum0 = 0.f, sum1 = 0.f;
        #pragma unroll
        for (int ni = 0; ni < 8; ni++) {
            sacc[ni][0] = __expf(sacc[ni][0] - nm0);
            sacc[ni][1] = __expf(sacc[ni][1] - nm0);
            sacc[ni][2] = __expf(sacc[ni][2] - nm1);
            sacc[ni][3] = __expf(sacc[ni][3] - nm1);
            sum0 += sacc[ni][0] + sacc[ni][1];
            sum1 += sacc[ni][2] + sacc[ni][3];
        }
        sum0 += __shfl_xor_sync(full, sum0, 1);
        sum0 += __shfl_xor_sync(full, sum0, 2);
        sum1 += __shfl_xor_sync(full, sum1, 1);
        sum1 += __shfl_xor_sync(full, sum1, 2);
        l0 = l0 * fac0 + sum0; m0 = nm0;
        l1 = l1 * fac1 + sum1; m1 = nm1;

        // ---- store P as half2 (warp-private rows; fragment-native) ----
        int q0 = w * 16 + g;
        #pragma unroll
        for (int ni = 0; ni < 8; ni++) {
            PsH[q0 * APST + ni * 4 + tg]       = f2h2(sacc[ni][0], sacc[ni][1]);
            PsH[(q0 + 8) * APST + ni * 4 + tg] = f2h2(sacc[ni][2], sacc[ni][3]);
        }
        __syncwarp();

        // ---- rescale O, then PV (A = PsH direct; B = raw V singles) ----
        #pragma unroll
        for (int nd = 0; nd < 4; nd++) {
            O[nd][0] *= fac0; O[nd][1] *= fac0;
            O[nd][2] *= fac1; O[nd][3] *= fac1;
        }
        #pragma unroll
        for (int s = 0; s < 4; s++) {
            uint32_t pa[4];
            pa[0] = PsH[q0 * APST + 8 * s + tg];
            pa[1] = PsH[(q0 + 8) * APST + 8 * s + tg];
            pa[2] = PsH[q0 * APST + 8 * s + 4 + tg];
            pa[3] = PsH[(q0 + 8) * APST + 8 * s + 4 + tg];
            #pragma unroll
            for (int nd = 0; nd < 4; nd++) {
                int d = nd * 8 + g;
                int kbase = s * 16 + 2 * tg;
                uint32_t bf[2];
                bf[0] = f2h2(Vc[kbase * AVST + d],       Vc[(kbase + 1) * AVST + d]);
                bf[1] = f2h2(Vc[(kbase + 8) * AVST + d], Vc[(kbase + 9) * AVST + d]);
                mmaf16(O[nd], pa, bf);
            }
        }
    }

    // ---- epilogue ----
    float inv0 = 1.f / l0, inv1 = 1.f / l1;
    #pragma unroll
    for (int nd = 0; nd < 4; nd++) {
        int c = h * HD + nd * 8 + 2 * tg;
        if (r0 < NQ)
            *(float2*)(out + ((size_t)(b * NQ + r0)) * DD + c) =
                make_float2(O[nd][0] * inv0, O[nd][1] * inv0);
        if (r1 < NQ)
            *(float2*)(out + ((size_t)(b * NQ + r1)) * DD + c) =
                make_float2(O[nd][2] * inv1, O[nd][3] * inv1);
    }
}

// ---------------- deformable sampling: warp = (head), block = (b,q) ---------
__global__ void sample_kernel(const float* __restrict__ mem, const float* __restrict__ ref,
                              const float* __restrict__ offs, const float* __restrict__ wts,
                              float* __restrict__ fused) {
    int row = blockIdx.x;
    int b = row / NQ;
    int h = threadIdx.x >> 5;
    int lane = threadIdx.x & 31;
    const unsigned full = 0xffffffffu;
    float rx = ref[row * 2], ry = ref[row * 2 + 1];
    float gx = 0.f, gy = 0.f, wl = 0.f;
    if (lane < PP) {
        float ox = offs[(size_t)row * (HH * PP * 2) + h * (PP * 2) + lane * 2];
        float oy = offs[(size_t)row * (HH * PP * 2) + h * (PP * 2) + lane * 2 + 1];
        gx = (rx + tanhf(ox) * 0.2f) * (float)BEV - 0.5f;
        gy = (ry + tanhf(oy) * 0.2f) * (float)BEV - 0.5f;
        wl = wts[(size_t)row * (HH * PP) + h * PP + lane];
    }
    float m = wl;
    m = fmaxf(m, __shfl_xor_sync(full, m, 1));
    m = fmaxf(m, __shfl_xor_sync(full, m, 2));
    float e = __expf(wl - m);
    float ssum = e;
    ssum += __shfl_xor_sync(full, ssum, 1);
    ssum += __shfl_xor_sync(full, ssum, 2);
    float w = e / ssum;
    const float* mb = mem + (size_t)b * (BEV * BEV) * DD + h * HD + lane;
    float acc = 0.f;
    #pragma unroll
    for (int p = 0; p < PP; p++) {
        float px = __shfl_sync(full, gx, p);
        float py = __shfl_sync(full, gy, p);
        float pw = __shfl_sync(full, w, p);
        float x0f = floorf(px), y0f = floorf(py);
        float wx1 = px - x0f, wy1 = py - y0f;
        float wx0 = 1.f - wx1, wy0 = 1.f - wy1;
        int x0 = (int)x0f, y0 = (int)y0f;
        bool xv0 = (x0 >= 0) && (x0 < BEV);
        bool xv1 = (x0 + 1 >= 0) && (x0 + 1 < BEV);
        bool yv0 = (y0 >= 0) && (y0 < BEV);
        bool yv1 = (y0 + 1 >= 0) && (y0 + 1 < BEV);
        float v = 0.f;
        if (yv0) {
            if (xv0) v += wx0 * wy0 * mb[(size_t)(y0 * BEV + x0) * DD];
            if (xv1) v += wx1 * wy0 * mb[(size_t)(y0 * BEV + x0 + 1) * DD];
        }
        if (yv1) {
            if (xv0) v += wx0 * wy1 * mb[(size_t)((y0 + 1) * BEV + x0) * DD];
            if (xv1) v += wx1 * wy1 * mb[(size_t)((y0 + 1) * BEV + x0 + 1) * DD];
        }
        acc += pw * v;
    }
    fused[(size_t)row * DD + h * HD + lane] = acc;
}

// ---------------- host launcher ---------------------------------------------
extern "C" void kernel_launch(void* const* d_in, const int* in_sizes, int n_in,
                              void* d_out, int out_size) {
    const float* query = (const float*)d_in[0];
    const float* memory = (const float*)d_in[1];
    const float* refp  = (const float*)d_in[2];
    const float* qpos  = (const float*)d_in[3];
    const float* in_w  = (const float*)d_in[4];
    const float* in_b  = (const float*)d_in[5];
    const float* out_w = (const float*)d_in[6];
    const float* out_b = (const float*)d_in[7];
    const float* off_w = (const float*)d_in[8];
    const float* off_b = (const float*)d_in[9];
    const float* wt_w  = (const float*)d_in[10];
    const float* wt_b  = (const float*)d_in[11];
    const float* co_w  = (const float*)d_in[12];
    const float* co_b  = (const float*)d_in[13];
    const float* f_w1  = (const float*)d_in[14];
    const float* f_b1  = (const float*)d_in[15];
    const float* f_w2  = (const float*)d_in[16];
    const float* f_b2  = (const float*)d_in[17];
    const float* n1s   = (const float*)d_in[18];
    const float* n1b   = (const float*)d_in[19];
    const float* n2s   = (const float*)d_in[20];
    const float* n2b   = (const float*)d_in[21];
    const float* n3s   = (const float*)d_in[22];
    const float* n3b   = (const float*)d_in[23];

    float *qin, *qkv, *attn, *q1, *q2, *offs, *wts, *fused, *qq2, *q3, *mid;
    cudaGetSymbolAddress((void**)&qin,   g_qin);
    cudaGetSymbolAddress((void**)&qkv,   g_qkv);
    cudaGetSymbolAddress((void**)&attn,  g_attn);
    cudaGetSymbolAddress((void**)&q1,    g_q1);
    cudaGetSymbolAddress((void**)&q2,    g_q2);
    cudaGetSymbolAddress((void**)&offs,  g_offs);
    cudaGetSymbolAddress((void**)&wts,   g_wts);
    cudaGetSymbolAddress((void**)&fused, g_fused);
    cudaGetSymbolAddress((void**)&qq2,   g_qq2);
    cudaGetSymbolAddress((void**)&q3,    g_q3);
    cudaGetSymbolAddress((void**)&mid,   g_mid);

    const int M = MROWS;
    const int MTC  = (M + 127) / 128;    // 57
    const int MT64 = (M + 63) / 64;      // 113
    const int LNG  = (M + 7) / 8;        // 900

    cudaFuncSetAttribute(gemm_tc, cudaFuncAttributeMaxDynamicSharedMemorySize,
                         GT_SMEM);

    // 1. q_in = LN(query + query_pos)
    add_ln_warp<<<LNG, 256>>>(query, qpos, n1s, n1b, qin);
    // 2. qkv = q_in @ in_w^T + in_b
    gemm_tc<<<dim3(12, MTC), 256, GT_SMEM>>>(qin, in_w, in_b, nullptr, qkv, M, 768, 256, 0);
    // 3. self-attention (fp16 mma, cp.async double-buffered K/V)
    attn4_kernel<<<dim3((NQ + 63) / 64, HH, BB), 128>>>(qkv, attn);
    // 4. q1 = attn @ out_w^T + out_b + query
    gemm_tc<<<dim3(4, MTC), 256, GT_SMEM>>>(attn, out_w, out_b, query, q1, M, 256, 256, 0);
    // 5. q2 = LN(q1 + query_pos)
    add_ln_warp<<<LNG, 256>>>(q1, qpos, n2s, n2b, q2);
    // 6/7. offset + weight heads
    gemm_tc<<<dim3(1, MTC), 256, GT_SMEM>>>(q2, off_w, off_b, nullptr, offs, M, 64, 256, 0);
    gemm_nt<<<dim3(1, MT64), 256>>>(q2, wt_w, wt_b, nullptr, wts, M, 32, 256, 0);
    // 8. deformable BEV sampling -> fused
    sample_kernel<<<M, 256>>>(memory, refp, offs, wts, fused);
    // 9. qq2 = fused @ co_w^T + co_b + q1
    gemm_tc<<<dim3(4, MTC), 256, GT_SMEM>>>(fused, co_w, co_b, q1, qq2, M, 256, 256, 0);
    // 10. q3 = LN(qq2)
    add_ln_warp<<<LNG, 256>>>(qq2, nullptr, n3s, n3b, q3);
    // 11. mid = relu(q3 @ f_w1^T + f_b1)
    gemm_tc<<<dim3(8, MTC), 256, GT_SMEM>>>(q3, f_w1, f_b1, nullptr, mid, M, 512, 256, 1);
    // 12. out = mid @ f_w2^T + f_b2 + qq2
    gemm_tc<<<dim3(4, MTC), 256, GT_SMEM>>>(mid, f_w2, f_b2, qq2, (float*)d_out, M, 256, 512, 0);
    (void)in_sizes; (void)n_in; (void)out_size;
}

// round 16
// speedup vs baseline: 2.0537x; 1.1378x over previous
#include <cuda_runtime.h>
#include <cuda_bf16.h>
#include <cuda_fp16.h>
#include <math.h>
#include <stdint.h>

// Problem constants
#define BB    8
#define NQ    900
#define DD    256
#define HH    8
#define HD    32
#define PP    4
#define BEV   200
#define FFN   512
#define MROWS (BB * NQ)          // 7200

// ---------------- scratch (allocation-free: __device__ globals) -------------
__device__ float  g_qkv  [MROWS * 3 * DD];
__device__ float  g_q1   [MROWS * DD];
__device__ float  g_qq2  [MROWS * DD];
__device__ float  g_owts [MROWS * 128];
__device__ __half g_qin_h  [MROWS * DD];
__device__ __half g_attn_h [MROWS * DD];
__device__ __half g_q2_h   [MROWS * DD];
__device__ __half g_q3_h   [MROWS * DD];
__device__ __half g_fused_h[MROWS * DD];
__device__ __half g_mid_h  [MROWS * FFN];
// converted weights
__device__ __half g_inw_h [3 * DD * DD];     // 196608
__device__ __half g_outw_h[DD * DD];         // 65536
__device__ __half g_cow_h [DD * DD];         // 65536
__device__ __half g_fw1_h [FFN * DD];        // 131072
__device__ __half g_fw2_h [DD * FFN];        // 131072
__device__ __half g_how_h [128 * DD];        // off_w(64) + wt_w(32) + zeros(32)
__device__ float  g_owb   [128];

// ---------------- weight conversion (one launch, 6 segments) -----------------
__global__ void cvt_weights(const float* __restrict__ inw, const float* __restrict__ outw,
                            const float* __restrict__ cow, const float* __restrict__ fw1,
                            const float* __restrict__ fw2, const float* __restrict__ offw,
                            const float* __restrict__ wtw, const float* __restrict__ offb,
                            const float* __restrict__ wtb) {
    const int seg = blockIdx.y;
    const int idx = (blockIdx.x * 256 + threadIdx.x) * 4;
    const float* src = nullptr;
    __half* dst = nullptr;
    int n = 0;
    switch (seg) {
        case 0: src = inw;  dst = g_inw_h;  n = 3 * DD * DD; break;
        case 1: src = outw; dst = g_outw_h; n = DD * DD; break;
        case 2: src = cow;  dst = g_cow_h;  n = DD * DD; break;
        case 3: src = fw1;  dst = g_fw1_h;  n = FFN * DD; break;
        case 4: src = fw2;  dst = g_fw2_h;  n = DD * FFN; break;
        case 5: {
            if (blockIdx.x == 0 && threadIdx.x < 128)
                g_owb[threadIdx.x] = (threadIdx.x < 64) ? offb[threadIdx.x]
                                   : (threadIdx.x < 96) ? wtb[threadIdx.x - 64] : 0.f;
            n = 128 * DD;
            if (idx >= n) return;
            float4 v;
            if (idx < 64 * DD) v = *(const float4*)(offw + idx);
            else if (idx < 96 * DD) v = *(const float4*)(wtw + idx - 64 * DD);
            else v = make_float4(0.f, 0.f, 0.f, 0.f);
            __half2* d2 = (__half2*)(g_how_h + idx);
            d2[0] = __floats2half2_rn(v.x, v.y);
            d2[1] = __floats2half2_rn(v.z, v.w);
            return;
        }
    }
    if (idx >= n) return;
    float4 v = *(const float4*)(src + idx);
    __half2* d2 = (__half2*)(dst + idx);
    d2[0] = __floats2half2_rn(v.x, v.y);
    d2[1] = __floats2half2_rn(v.z, v.w);
}

// ---------------- fused add + LayerNorm -> half output -----------------------
__global__ void add_ln_warp(const float* __restrict__ a, const float* __restrict__ b,
                            const float* __restrict__ s, const float* __restrict__ bias,
                            __half* __restrict__ out) {
    const unsigned full = 0xffffffffu;
    int w = threadIdx.x >> 5, lane = threadIdx.x & 31;
    int row = blockIdx.x * 8 + w;
    if (row >= MROWS) return;
    const float* ap = a + (size_t)row * DD;
    float4 x0 = *(const float4*)(ap + lane * 4);
    float4 x1 = *(const float4*)(ap + 128 + lane * 4);
    if (b) {
        const float* bp = b + (size_t)row * DD;
        float4 b0 = *(const float4*)(bp + lane * 4);
        float4 b1 = *(const float4*)(bp + 128 + lane * 4);
        x0.x += b0.x; x0.y += b0.y; x0.z += b0.z; x0.w += b0.w;
        x1.x += b1.x; x1.y += b1.y; x1.z += b1.z; x1.w += b1.w;
    }
    float sum = x0.x + x0.y + x0.z + x0.w + x1.x + x1.y + x1.z + x1.w;
    #pragma unroll
    for (int o = 16; o; o >>= 1) sum += __shfl_xor_sync(full, sum, o);
    float mean = sum * (1.f / DD);
    float c0x = x0.x - mean, c0y = x0.y - mean, c0z = x0.z - mean, c0w = x0.w - mean;
    float c1x = x1.x - mean, c1y = x1.y - mean, c1z = x1.z - mean, c1w = x1.w - mean;
    float vs = c0x*c0x + c0y*c0y + c0z*c0z + c0w*c0w
             + c1x*c1x + c1y*c1y + c1z*c1z + c1w*c1w;
    #pragma unroll
    for (int o = 16; o; o >>= 1) vs += __shfl_xor_sync(full, vs, o);
    float inv = rsqrtf(vs * (1.f / DD) + 1e-5f);
    float4 s0 = *(const float4*)(s + lane * 4);
    float4 s1 = *(const float4*)(s + 128 + lane * 4);
    float4 g0 = *(const float4*)(bias + lane * 4);
    float4 g1 = *(const float4*)(bias + 128 + lane * 4);
    __half2* op0 = (__half2*)(out + (size_t)row * DD + lane * 4);
    __half2* op1 = (__half2*)(out + (size_t)row * DD + 128 + lane * 4);
    op0[0] = __floats2half2_rn(c0x * inv * s0.x + g0.x, c0y * inv * s0.y + g0.y);
    op0[1] = __floats2half2_rn(c0z * inv * s0.z + g0.z, c0w * inv * s0.w + g0.w);
    op1[0] = __floats2half2_rn(c1x * inv * s1.x + g1.x, c1y * inv * s1.y + g1.y);
    op1[1] = __floats2half2_rn(c1z * inv * s1.z + g1.z, c1w * inv * s1.w + g1.w);
}

// ---------------- fp16 helpers ----------------------------------------------
__device__ __forceinline__ uint32_t f2h2(float lo, float hi) {
    __half2 h = __floats2half2_rn(lo, hi);
    return *(uint32_t*)&h;
}
__device__ __forceinline__ void mmaf16(float* d, const uint32_t* a, const uint32_t* b) {
    asm volatile(
        "mma.sync.aligned.m16n8k16.row.col.f32.f16.f16.f32 "
        "{%0,%1,%2,%3}, {%4,%5,%6,%7}, {%8,%9}, {%0,%1,%2,%3};\n"
        : "+f"(d[0]), "+f"(d[1]), "+f"(d[2]), "+f"(d[3])
        : "r"(a[0]), "r"(a[1]), "r"(a[2]), "r"(a[3]), "r"(b[0]), "r"(b[1]));
}
__device__ __forceinline__ uint32_t smem_u32(const void* p) {
    uint32_t a;
    asm("{ .reg .u64 t; cvta.to.shared.u64 t, %1; cvt.u32.u64 %0, t; }"
        : "=r"(a) : "l"(p));
    return a;
}
__device__ __forceinline__ void cpa16(uint32_t d, const void* s) {
    asm volatile("cp.async.cg.shared.global [%0], [%1], 16;"
                 :: "r"(d), "l"(s) : "memory");
}
__device__ __forceinline__ void cpa16z(uint32_t d, const void* s, unsigned sz) {
    asm volatile("cp.async.cg.shared.global [%0], [%1], 16, %2;"
                 :: "r"(d), "l"(s), "r"(sz) : "memory");
}

// ---------------- half-input tensor-core NT GEMM: C = A*B^T + epi -----------
// A,B fp16. 128x64 tile, BK=16, 4-stage cp.async, 8 warps 4x2, 2 CTAs/SM.
// Zero cvts in mainloop; fragments are direct LDS.32 of packed half2 pairs.
// Row stride 12 words (24 halfs): banks 12g+tg (+4) all-distinct.
#define HSTRW 12
#define HSTAGE_WORDS (192 * HSTRW)            // 2304 words = 9216 B
#define GTH_SMEM (4 * HSTAGE_WORDS * 4)       // 36864 B
__global__ __launch_bounds__(256, 2)
void gemm_tch(const __half* __restrict__ A, const __half* __restrict__ B,
              const float* __restrict__ bias, const float* __restrict__ resid,
              float* __restrict__ C, __half* __restrict__ Ch,
              int M, int N, int K, int relu) {
    extern __shared__ __align__(16) uint32_t smw[];
    const int tid = threadIdx.x;
    const int lane = tid & 31, wid = tid >> 5;
    const int g = lane >> 2, tg = lane & 3;
    const int wm = (wid >> 1) * 32, wn = (wid & 1) * 32;
    const int bm = blockIdx.y * 128, bn = blockIdx.x * 64;

    // fill slots: every thread 1 A-chunk (row=tid>>1, 8-half offset (tid&1)*8);
    // threads <128 additionally 1 B-chunk.
    const int rowA = tid >> 1, offH = (tid & 1) * 8;
    int gmA = bm + rowA; if (gmA >= M) gmA = M - 1;
    const __half* ap = A + (size_t)gmA * K + offH;
    const bool hasB = tid < 128;
    const int rowB = tid >> 1;               // 0..63 for tid<128
    const __half* bp = B + (size_t)(bn + rowB) * K + offH;

    const uint32_t sbase = smem_u32(smw);
    const uint32_t dA = sbase + (uint32_t)(rowA * HSTRW + (tid & 1) * 4) * 4u;
    const uint32_t dB = sbase + (uint32_t)((128 + rowB) * HSTRW + (tid & 1) * 4) * 4u;

    const int NIT = K >> 4;

    #pragma unroll
    for (int s = 0; s < 3; s++) {
        uint32_t off = (uint32_t)(s * HSTAGE_WORDS) * 4u;
        cpa16(dA + off, ap + s * 16);
        if (hasB) cpa16(dB + off, bp + s * 16);
        asm volatile("cp.async.commit_group;" ::: "memory");
    }

    float acc[2][4][4];
    #pragma unroll
    for (int mi = 0; mi < 2; mi++)
        #pragma unroll
        for (int ni = 0; ni < 4; ni++)
            #pragma unroll
            for (int r = 0; r < 4; r++) acc[mi][ni][r] = 0.f;

    for (int i = 0; i < NIT; i++) {
        if (i <= NIT - 3)      asm volatile("cp.async.wait_group 2;" ::: "memory");
        else if (i == NIT - 2) asm volatile("cp.async.wait_group 1;" ::: "memory");
        else                   asm volatile("cp.async.wait_group 0;" ::: "memory");
        __syncthreads();

        int snext = i + 3;
        if (snext < NIT) {
            uint32_t off = (uint32_t)((snext & 3) * HSTAGE_WORDS) * 4u;
            const int kof = snext * 16;
            cpa16(dA + off, ap + kof);
            if (hasB) cpa16(dB + off, bp + kof);
            asm volatile("cp.async.commit_group;" ::: "memory");
        }

        const uint32_t* Wb = smw + (i & 3) * HSTAGE_WORDS;
        uint32_t af[2][4], bf[4][2];
        #pragma unroll
        for (int mi = 0; mi < 2; mi++) {
            const uint32_t* r0b = Wb + (wm + mi * 16 + g) * HSTRW;
            const uint32_t* r1b = r0b + 8 * HSTRW;
            af[mi][0] = r0b[tg];
            af[mi][1] = r1b[tg];
            af[mi][2] = r0b[4 + tg];
            af[mi][3] = r1b[4 + tg];
        }
        #pragma unroll
        for (int ni = 0; ni < 4; ni++) {
            const uint32_t* cb = Wb + (128 + wn + ni * 8 + g) * HSTRW;
            bf[ni][0] = cb[tg];
            bf[ni][1] = cb[4 + tg];
        }
        #pragma unroll
        for (int mi = 0; mi < 2; mi++)
            #pragma unroll
            for (int ni = 0; ni < 4; ni++)
                mmaf16(acc[mi][ni], af[mi], bf[ni]);
    }

    #pragma unroll
    for (int ni = 0; ni < 4; ni++) {
        int c = bn + wn + ni * 8 + 2 * tg;
        float b0 = bias ? bias[c] : 0.f;
        float b1 = bias ? bias[c + 1] : 0.f;
        #pragma unroll
        for (int mi = 0; mi < 2; mi++) {
            int r0 = bm + wm + mi * 16 + g;
            int r1 = r0 + 8;
            float v0 = acc[mi][ni][0] + b0, v1 = acc[mi][ni][1] + b1;
            float v2 = acc[mi][ni][2] + b0, v3 = acc[mi][ni][3] + b1;
            if (relu) {
                v0 = fmaxf(v0, 0.f); v1 = fmaxf(v1, 0.f);
                v2 = fmaxf(v2, 0.f); v3 = fmaxf(v3, 0.f);
            }
            if (r0 < M) {
                if (resid) {
                    float2 rr = *(const float2*)(resid + (size_t)r0 * N + c);
                    v0 += rr.x; v1 += rr.y;
                }
                if (Ch) *(__half2*)(Ch + (size_t)r0 * N + c) = __floats2half2_rn(v0, v1);
                else    *(float2*)(C + (size_t)r0 * N + c) = make_float2(v0, v1);
            }
            if (r1 < M) {
                if (resid) {
                    float2 rr = *(const float2*)(resid + (size_t)r1 * N + c);
                    v2 += rr.x; v3 += rr.y;
                }
                if (Ch) *(__half2*)(Ch + (size_t)r1 * N + c) = __floats2half2_rn(v2, v3);
                else    *(float2*)(C + (size_t)r1 * N + c) = make_float2(v2, v3);
            }
        }
    }
}

// ---------------- tensor-core flash attention (fp16 mma, cp.async) ----------
// identical to round-15 passing version, except epilogue writes half.
#define AKST 40
#define AVST 36
#define APST 36
__global__ __launch_bounds__(128)
void attn4_kernel(const float* __restrict__ qkv, __half* __restrict__ out) {
    __shared__ __align__(16) float    Kb[2][64 * AKST];
    __shared__ __align__(16) float    Vb[2][64 * AVST];
    __shared__ __align__(16) uint32_t PsH[64 * APST];

    const int b = blockIdx.z, h = blockIdx.y, qt = blockIdx.x;
    const int tid = threadIdx.x;
    const int w = tid >> 5, lane = tid & 31;
    const int g = lane >> 2, tg = lane & 3;
    const float scale = 0.17677669529663687f;
    const unsigned full = 0xffffffffu;

    const uint32_t kb0 = smem_u32(&Kb[0][0]);
    const uint32_t vb0 = smem_u32(&Vb[0][0]);
    const uint32_t KBYTES = 64 * AKST * 4;
    const uint32_t VBYTES = 64 * AVST * 4;

    const int fkey = tid >> 1, fdh = (tid & 1) * 16;
    const uint32_t kdst = kb0 + (uint32_t)(fkey * AKST + fdh) * 4u;
    const uint32_t vdst = vb0 + (uint32_t)(fkey * AVST + fdh) * 4u;

    const int r0 = qt * 64 + w * 16 + g;
    const int r1 = r0 + 8;
    uint32_t qa[2][4];
    {
        const float* q0p = qkv + ((size_t)(b * NQ + (r0 < NQ ? r0 : 0))) * 768 + h * HD;
        const float* q1p = qkv + ((size_t)(b * NQ + (r1 < NQ ? r1 : 0))) * 768 + h * HD;
        bool v0 = r0 < NQ, v1 = r1 < NQ;
        #pragma unroll
        for (int s = 0; s < 2; s++) {
            int c0 = s * 16 + 2 * tg;
            qa[s][0] = v0 ? f2h2(q0p[c0] * scale, q0p[c0 + 1] * scale) : 0u;
            qa[s][1] = v1 ? f2h2(q1p[c0] * scale, q1p[c0 + 1] * scale) : 0u;
            qa[s][2] = v0 ? f2h2(q0p[c0 + 8] * scale, q0p[c0 + 9] * scale) : 0u;
            qa[s][3] = v1 ? f2h2(q1p[c0 + 8] * scale, q1p[c0 + 9] * scale) : 0u;
        }
    }

    float m0 = -INFINITY, m1 = -INFINITY, l0 = 0.f, l1 = 0.f;
    float O[4][4];
    #pragma unroll
    for (int nd = 0; nd < 4; nd++)
        #pragma unroll
        for (int r = 0; r < 4; r++) O[nd][r] = 0.f;

    const int NKT = (NQ + 63) / 64;

    {
        int kk = fkey;
        const float* src = qkv + ((size_t)(b * NQ + (kk < NQ ? kk : 0))) * 768
                         + 256 + h * HD + fdh;
        unsigned sz = (kk < NQ) ? 16u : 0u;
        #pragma unroll
        for (int i = 0; i < 4; i++) {
            cpa16z(kdst + i * 16, src + i * 4, sz);
            cpa16z(vdst + i * 16, src + 256 + i * 4, sz);
        }
        asm volatile("cp.async.commit_group;" ::: "memory");
    }

    for (int jt = 0; jt < NKT; jt++) {
        asm volatile("cp.async.wait_group 0;" ::: "memory");
        __syncthreads();

        if (jt + 1 < NKT) {
            int kk = (jt + 1) * 64 + fkey;
            const float* src = qkv + ((size_t)(b * NQ + (kk < NQ ? kk : 0))) * 768
                             + 256 + h * HD + fdh;
            unsigned sz = (kk < NQ) ? 16u : 0u;
            uint32_t bo = ((jt + 1) & 1) ? 1u : 0u;
            uint32_t kd = kdst + bo * KBYTES;
            uint32_t vd = vdst + bo * VBYTES;
            #pragma unroll
            for (int i = 0; i < 4; i++) {
                cpa16z(kd + i * 16, src + i * 4, sz);
                cpa16z(vd + i * 16, src + 256 + i * 4, sz);
            }
            asm volatile("cp.async.commit_group;" ::: "memory");
        }

        const float* Kc = Kb[jt & 1];
        const float* Vc = Vb[jt & 1];

        float sacc[8][4];
        #pragma unroll
        for (int ni = 0; ni < 8; ni++)
            #pragma unroll
            for (int r = 0; r < 4; r++) sacc[ni][r] = 0.f;
        #pragma unroll
        for (int s = 0; s < 2; s++) {
            #pragma unroll
            for (int ni = 0; ni < 8; ni++) {
                const float* kbp = &Kc[(ni * 8 + g) * AKST + s * 16];
                float2 k0 = *(const float2*)(kbp + 2 * tg);
                float2 k1 = *(const float2*)(kbp + 8 + 2 * tg);
                uint32_t bf[2] = { f2h2(k0.x, k0.y), f2h2(k1.x, k1.y) };
                mmaf16(sacc[ni], qa[s], bf);
            }
        }
        int kglob = jt * 64;
        if (kglob + 64 > NQ) {
            #pragma unroll
            for (int ni = 0; ni < 8; ni++) {
                int kc = kglob + ni * 8 + 2 * tg;
                if (kc >= NQ)     { sacc[ni][0] = -1e30f; sacc[ni][2] = -1e30f; }
                if (kc + 1 >= NQ) { sacc[ni][1] = -1e30f; sacc[ni][3] = -1e30f; }
            }
        }

        float mx0 = -INFINITY, mx1 = -INFINITY;
        #pragma unroll
        for (int ni = 0; ni < 8; ni++) {
            mx0 = fmaxf(mx0, fmaxf(sacc[ni][0], sacc[ni][1]));
            mx1 = fmaxf(mx1, fmaxf(sacc[ni][2], sacc[ni][3]));
        }
        mx0 = fmaxf(mx0, __shfl_xor_sync(full, mx0, 1));
        mx0 = fmaxf(mx0, __shfl_xor_sync(full, mx0, 2));
        mx1 = fmaxf(mx1, __shfl_xor_sync(full, mx1, 1));
        mx1 = fmaxf(mx1, __shfl_xor_sync(full, mx1, 2));
        float nm0 = fmaxf(m0, mx0), nm1 = fmaxf(m1, mx1);
        float fac0 = __expf(m0 - nm0), fac1 = __expf(m1 - nm1);
        float sum0 = 0.f, sum1 = 0.f;
        #pragma unroll
        for (int ni = 0; ni < 8; ni++) {
            sacc[ni][0] = __expf(sacc[ni][0] - nm0);
            sacc[ni][1] = __expf(sacc[ni][1] - nm0);
            sacc[ni][2] = __expf(sacc[ni][2] - nm1);
            sacc[ni][3] = __expf(sacc[ni][3] - nm1);
            sum0 += sacc[ni][0] + sacc[ni][1];
            sum1 += sacc[ni][2] + sacc[ni][3];
        }
        sum0 += __shfl_xor_sync(full, sum0, 1);
        sum0 += __shfl_xor_sync(full, sum0, 2);
        sum1 += __shfl_xor_sync(full, sum1, 1);
        sum1 += __shfl_xor_sync(full, sum1, 2);
        l0 = l0 * fac0 + sum0; m0 = nm0;
        l1 = l1 * fac1 + sum1; m1 = nm1;

        int q0 = w * 16 + g;
        #pragma unroll
        for (int ni = 0; ni < 8; ni++) {
            PsH[q0 * APST + ni * 4 + tg]       = f2h2(sacc[ni][0], sacc[ni][1]);
            PsH[(q0 + 8) * APST + ni * 4 + tg] = f2h2(sacc[ni][2], sacc[ni][3]);
        }
        __syncwarp();

        #pragma unroll
        for (int nd = 0; nd < 4; nd++) {
            O[nd][0] *= fac0; O[nd][1] *= fac0;
            O[nd][2] *= fac1; O[nd][3] *= fac1;
        }
        #pragma unroll
        for (int s = 0; s < 4; s++) {
            uint32_t pa[4];
            pa[0] = PsH[q0 * APST + 8 * s + tg];
            pa[1] = PsH[(q0 + 8) * APST + 8 * s + tg];
            pa[2] = PsH[q0 * APST + 8 * s + 4 + tg];
            pa[3] = PsH[(q0 + 8) * APST + 8 * s + 4 + tg];
            #pragma unroll
            for (int nd = 0; nd < 4; nd++) {
                int d = nd * 8 + g;
                int kbase = s * 16 + 2 * tg;
                uint32_t bf[2];
                bf[0] = f2h2(Vc[kbase * AVST + d],       Vc[(kbase + 1) * AVST + d]);
                bf[1] = f2h2(Vc[(kbase + 8) * AVST + d], Vc[(kbase + 9) * AVST + d]);
                mmaf16(O[nd], pa, bf);
            }
        }
    }

    float inv0 = 1.f / l0, inv1 = 1.f / l1;
    #pragma unroll
    for (int nd = 0; nd < 4; nd++) {
        int c = h * HD + nd * 8 + 2 * tg;
        if (r0 < NQ)
            *(__half2*)(out + ((size_t)(b * NQ + r0)) * DD + c) =
                __floats2half2_rn(O[nd][0] * inv0, O[nd][1] * inv0);
        if (r1 < NQ)
            *(__half2*)(out + ((size_t)(b * NQ + r1)) * DD + c) =
                __floats2half2_rn(O[nd][2] * inv1, O[nd][3] * inv1);
    }
}

// ---------------- deformable sampling (reads combined owts, writes half) ----
__global__ void sample_kernel(const float* __restrict__ mem, const float* __restrict__ ref,
                              const float* __restrict__ owts, __half* __restrict__ fused) {
    int row = blockIdx.x;
    int b = row / NQ;
    int h = threadIdx.x >> 5;
    int lane = threadIdx.x & 31;
    const unsigned full = 0xffffffffu;
    float rx = ref[row * 2], ry = ref[row * 2 + 1];
    float gx = 0.f, gy = 0.f, wl = 0.f;
    if (lane < PP) {
        float ox = owts[(size_t)row * 128 + h * (PP * 2) + lane * 2];
        float oy = owts[(size_t)row * 128 + h * (PP * 2) + lane * 2 + 1];
        gx = (rx + tanhf(ox) * 0.2f) * (float)BEV - 0.5f;
        gy = (ry + tanhf(oy) * 0.2f) * (float)BEV - 0.5f;
        wl = owts[(size_t)row * 128 + 64 + h * PP + lane];
    }
    float m = wl;
    m = fmaxf(m, __shfl_xor_sync(full, m, 1));
    m = fmaxf(m, __shfl_xor_sync(full, m, 2));
    float e = __expf(wl - m);
    float ssum = e;
    ssum += __shfl_xor_sync(full, ssum, 1);
    ssum += __shfl_xor_sync(full, ssum, 2);
    float w = e / ssum;
    const float* mb = mem + (size_t)b * (BEV * BEV) * DD + h * HD + lane;
    float acc = 0.f;
    #pragma unroll
    for (int p = 0; p < PP; p++) {
        float px = __shfl_sync(full, gx, p);
        float py = __shfl_sync(full, gy, p);
        float pw = __shfl_sync(full, w, p);
        float x0f = floorf(px), y0f = floorf(py);
        float wx1 = px - x0f, wy1 = py - y0f;
        float wx0 = 1.f - wx1, wy0 = 1.f - wy1;
        int x0 = (int)x0f, y0 = (int)y0f;
        bool xv0 = (x0 >= 0) && (x0 < BEV);
        bool xv1 = (x0 + 1 >= 0) && (x0 + 1 < BEV);
        bool yv0 = (y0 >= 0) && (y0 < BEV);
        bool yv1 = (y0 + 1 >= 0) && (y0 + 1 < BEV);
        float v = 0.f;
        if (yv0) {
            if (xv0) v += wx0 * wy0 * mb[(size_t)(y0 * BEV + x0) * DD];
            if (xv1) v += wx1 * wy0 * mb[(size_t)(y0 * BEV + x0 + 1) * DD];
        }
        if (yv1) {
            if (xv0) v += wx0 * wy1 * mb[(size_t)((y0 + 1) * BEV + x0) * DD];
            if (xv1) v += wx1 * wy1 * mb[(size_t)((y0 + 1) * BEV + x0 + 1) * DD];
        }
        acc += pw * v;
    }
    fused[(size_t)row * DD + h * HD + lane] = __float2half(acc);
}

// ---------------- host launcher ---------------------------------------------
extern "C" void kernel_launch(void* const* d_in, const int* in_sizes, int n_in,
                              void* d_out, int out_size) {
    const float* query = (const float*)d_in[0];
    const float* memory = (const float*)d_in[1];
    const float* refp  = (const float*)d_in[2];
    const float* qpos  = (const float*)d_in[3];
    const float* in_w  = (const float*)d_in[4];
    const float* in_b  = (const float*)d_in[5];
    const float* out_w = (const float*)d_in[6];
    const float* out_b = (const float*)d_in[7];
    const float* off_w = (const float*)d_in[8];
    const float* off_b = (const float*)d_in[9];
    const float* wt_w  = (const float*)d_in[10];
    const float* wt_b  = (const float*)d_in[11];
    const float* co_w  = (const float*)d_in[12];
    const float* co_b  = (const float*)d_in[13];
    const float* f_w1  = (const float*)d_in[14];
    const float* f_b1  = (const float*)d_in[15];
    const float* f_w2  = (const float*)d_in[16];
    const float* f_b2  = (const float*)d_in[17];
    const float* n1s   = (const float*)d_in[18];
    const float* n1b   = (const float*)d_in[19];
    const float* n2s   = (const float*)d_in[20];
    const float* n2b   = (const float*)d_in[21];
    const float* n3s   = (const float*)d_in[22];
    const float* n3b   = (const float*)d_in[23];

    float *qkv, *q1, *qq2, *owts, *owb;
    __half *qin_h, *attn_h, *q2_h, *q3_h, *fused_h, *mid_h;
    __half *inw_h, *outw_h, *cow_h, *fw1_h, *fw2_h, *how_h;
    cudaGetSymbolAddress((void**)&qkv,    g_qkv);
    cudaGetSymbolAddress((void**)&q1,     g_q1);
    cudaGetSymbolAddress((void**)&qq2,    g_qq2);
    cudaGetSymbolAddress((void**)&owts,   g_owts);
    cudaGetSymbolAddress((void**)&owb,    g_owb);
    cudaGetSymbolAddress((void**)&qin_h,  g_qin_h);
    cudaGetSymbolAddress((void**)&attn_h, g_attn_h);
    cudaGetSymbolAddress((void**)&q2_h,   g_q2_h);
    cudaGetSymbolAddress((void**)&q3_h,   g_q3_h);
    cudaGetSymbolAddress((void**)&fused_h,g_fused_h);
    cudaGetSymbolAddress((void**)&mid_h,  g_mid_h);
    cudaGetSymbolAddress((void**)&inw_h,  g_inw_h);
    cudaGetSymbolAddress((void**)&outw_h, g_outw_h);
    cudaGetSymbolAddress((void**)&cow_h,  g_cow_h);
    cudaGetSymbolAddress((void**)&fw1_h,  g_fw1_h);
    cudaGetSymbolAddress((void**)&fw2_h,  g_fw2_h);
    cudaGetSymbolAddress((void**)&how_h,  g_how_h);

    const int M = MROWS;
    const int MTC = (M + 127) / 128;     // 57
    const int LNG = (M + 7) / 8;         // 900

    cudaFuncSetAttribute(gemm_tch, cudaFuncAttributeMaxDynamicSharedMemorySize,
                         GTH_SMEM);

    // 0. convert weights to fp16 (+ combined off/wt head)
    cvt_weights<<<dim3(192, 6), 256>>>(in_w, out_w, co_w, f_w1, f_w2,
                                       off_w, wt_w, off_b, wt_b);
    // 1. q_in = LN(query + query_pos) -> half
    add_ln_warp<<<LNG, 256>>>(query, qpos, n1s, n1b, qin_h);
    // 2. qkv = q_in @ in_w^T + in_b (float out)
    gemm_tch<<<dim3(12, MTC), 256, GTH_SMEM>>>(qin_h, inw_h, in_b, nullptr,
                                               qkv, nullptr, M, 768, 256, 0);
    // 3. self-attention -> half attn
    attn4_kernel<<<dim3((NQ + 63) / 64, HH, BB), 128>>>(qkv, attn_h);
    // 4. q1 = attn @ out_w^T + out_b + query (float)
    gemm_tch<<<dim3(4, MTC), 256, GTH_SMEM>>>(attn_h, outw_h, out_b, query,
                                              q1, nullptr, M, 256, 256, 0);
    // 5. q2 = LN(q1 + query_pos) -> half
    add_ln_warp<<<LNG, 256>>>(q1, qpos, n2s, n2b, q2_h);
    // 6. combined offset+weight heads (float out, cols 0..63 offs / 64..95 wts)
    gemm_tch<<<dim3(2, MTC), 256, GTH_SMEM>>>(q2_h, how_h, owb, nullptr,
                                              owts, nullptr, M, 128, 256, 0);
    // 7. deformable BEV sampling -> half fused
    sample_kernel<<<M, 256>>>(memory, refp, owts, fused_h);
    // 8. qq2 = fused @ co_w^T + co_b + q1 (float)
    gemm_tch<<<dim3(4, MTC), 256, GTH_SMEM>>>(fused_h, cow_h, co_b, q1,
                                              qq2, nullptr, M, 256, 256, 0);
    // 9. q3 = LN(qq2) -> half
    add_ln_warp<<<LNG, 256>>>(qq2, nullptr, n3s, n3b, q3_h);
    // 10. mid = relu(q3 @ f_w1^T + f_b1) -> half
    gemm_tch<<<dim3(8, MTC), 256, GTH_SMEM>>>(q3_h, fw1_h, f_b1, nullptr,
                                              nullptr, mid_h, M, 512, 256, 1);
    // 11. out = mid @ f_w2^T + f_b2 + qq2 (float)
    gemm_tch<<<dim3(4, MTC), 256, GTH_SMEM>>>(mid_h, fw2_h, f_b2, qq2,
                                              (float*)d_out, nullptr, M, 256, 512, 0);
    (void)in_sizes; (void)n_in; (void)out_size;
}

// round 17
// speedup vs baseline: 2.2428x; 1.0921x over previous
#include <cuda_runtime.h>
#include <cuda_bf16.h>
#include <cuda_fp16.h>
#include <math.h>
#include <stdint.h>

// Problem constants
#define BB    8
#define NQ    900
#define NQV   960                 // padded key length for vT (15 x 64)
#define DD    256
#define HH    8
#define HD    32
#define PP    4
#define BEV   200
#define FFN   512
#define MROWS (BB * NQ)          // 7200

// ---------------- scratch (allocation-free: __device__ globals) -------------
__device__ float  g_qkv  [MROWS * 3 * DD];
__device__ float  g_q1   [MROWS * DD];
__device__ float  g_qq2  [MROWS * DD];
__device__ float  g_owts [MROWS * 128];
__device__ __half g_qkv_h  [MROWS * 3 * DD];
__device__ __half g_vT_h   [BB * HH * HD * NQV];   // [bh][d][key]
__device__ __half g_qin_h  [MROWS * DD];
__device__ __half g_attn_h [MROWS * DD];
__device__ __half g_q2_h   [MROWS * DD];
__device__ __half g_q3_h   [MROWS * DD];
__device__ __half g_fused_h[MROWS * DD];
__device__ __half g_mid_h  [MROWS * FFN];
// converted weights
__device__ __half g_inw_h [3 * DD * DD];
__device__ __half g_outw_h[DD * DD];
__device__ __half g_cow_h [DD * DD];
__device__ __half g_fw1_h [FFN * DD];
__device__ __half g_fw2_h [DD * FFN];
__device__ __half g_how_h [128 * DD];
__device__ float  g_owb   [128];

// ---------------- weight conversion (one launch, 6 segments) -----------------
__global__ void cvt_weights(const float* __restrict__ inw, const float* __restrict__ outw,
                            const float* __restrict__ cow, const float* __restrict__ fw1,
                            const float* __restrict__ fw2, const float* __restrict__ offw,
                            const float* __restrict__ wtw, const float* __restrict__ offb,
                            const float* __restrict__ wtb) {
    const int seg = blockIdx.y;
    const int idx = (blockIdx.x * 256 + threadIdx.x) * 4;
    const float* src = nullptr;
    __half* dst = nullptr;
    int n = 0;
    switch (seg) {
        case 0: src = inw;  dst = g_inw_h;  n = 3 * DD * DD; break;
        case 1: src = outw; dst = g_outw_h; n = DD * DD; break;
        case 2: src = cow;  dst = g_cow_h;  n = DD * DD; break;
        case 3: src = fw1;  dst = g_fw1_h;  n = FFN * DD; break;
        case 4: src = fw2;  dst = g_fw2_h;  n = DD * FFN; break;
        case 5: {
            if (blockIdx.x == 0 && threadIdx.x < 128)
                g_owb[threadIdx.x] = (threadIdx.x < 64) ? offb[threadIdx.x]
                                   : (threadIdx.x < 96) ? wtb[threadIdx.x - 64] : 0.f;
            n = 128 * DD;
            if (idx >= n) return;
            float4 v;
            if (idx < 64 * DD) v = *(const float4*)(offw + idx);
            else if (idx < 96 * DD) v = *(const float4*)(wtw + idx - 64 * DD);
            else v = make_float4(0.f, 0.f, 0.f, 0.f);
            __half2* d2 = (__half2*)(g_how_h + idx);
            d2[0] = __floats2half2_rn(v.x, v.y);
            d2[1] = __floats2half2_rn(v.z, v.w);
            return;
        }
    }
    if (idx >= n) return;
    float4 v = *(const float4*)(src + idx);
    __half2* d2 = (__half2*)(dst + idx);
    d2[0] = __floats2half2_rn(v.x, v.y);
    d2[1] = __floats2half2_rn(v.z, v.w);
}

// ---------------- V transpose: qkv_h V-part -> vT_h[bh][d][key] --------------
__global__ void vtrans_kernel(const __half* __restrict__ qkvh, __half* __restrict__ vT) {
    __shared__ __half ts[32][72];   // [d][key-local], pad 8 halfs
    const int bh = blockIdx.y;      // b*8 + h
    const int b = bh >> 3, h = bh & 7;
    const int k0 = blockIdx.x * 64;
    const int t = threadIdx.x;
    // read: thread -> key=k0+(t>>2), 8 d-halfs at (t&3)*8
    {
        int key = k0 + (t >> 2), dq = (t & 3) * 8;
        if (key < NQ) {
            const __half* src = qkvh + ((size_t)(b * NQ + key)) * 768 + 512 + h * HD + dq;
            uint4 v = *(const uint4*)src;
            const __half* hv = (const __half*)&v;
            #pragma unroll
            for (int i = 0; i < 8; i++) ts[dq + i][t >> 2] = hv[i];
        } else {
            #pragma unroll
            for (int i = 0; i < 8; i++) ts[dq + i][t >> 2] = __float2half(0.f);
        }
    }
    __syncthreads();
    // write: thread -> d=t>>3, 8 keys at (t&7)*8
    {
        int d = t >> 3, kc = (t & 7) * 8;
        int keyg = k0 + kc;
        __half* dst = vT + ((size_t)(bh * HD + d)) * NQV + keyg;
        uint4 v;
        __half* hv = (__half*)&v;
        #pragma unroll
        for (int i = 0; i < 8; i++) hv[i] = ts[d][kc + i];
        *(uint4*)dst = v;
    }
}

// ---------------- fused add + LayerNorm -> half output -----------------------
__global__ void add_ln_warp(const float* __restrict__ a, const float* __restrict__ b,
                            const float* __restrict__ s, const float* __restrict__ bias,
                            __half* __restrict__ out) {
    const unsigned full = 0xffffffffu;
    int w = threadIdx.x >> 5, lane = threadIdx.x & 31;
    int row = blockIdx.x * 8 + w;
    if (row >= MROWS) return;
    const float* ap = a + (size_t)row * DD;
    float4 x0 = *(const float4*)(ap + lane * 4);
    float4 x1 = *(const float4*)(ap + 128 + lane * 4);
    if (b) {
        const float* bp = b + (size_t)row * DD;
        float4 b0 = *(const float4*)(bp + lane * 4);
        float4 b1 = *(const float4*)(bp + 128 + lane * 4);
        x0.x += b0.x; x0.y += b0.y; x0.z += b0.z; x0.w += b0.w;
        x1.x += b1.x; x1.y += b1.y; x1.z += b1.z; x1.w += b1.w;
    }
    float sum = x0.x + x0.y + x0.z + x0.w + x1.x + x1.y + x1.z + x1.w;
    #pragma unroll
    for (int o = 16; o; o >>= 1) sum += __shfl_xor_sync(full, sum, o);
    float mean = sum * (1.f / DD);
    float c0x = x0.x - mean, c0y = x0.y - mean, c0z = x0.z - mean, c0w = x0.w - mean;
    float c1x = x1.x - mean, c1y = x1.y - mean, c1z = x1.z - mean, c1w = x1.w - mean;
    float vs = c0x*c0x + c0y*c0y + c0z*c0z + c0w*c0w
             + c1x*c1x + c1y*c1y + c1z*c1z + c1w*c1w;
    #pragma unroll
    for (int o = 16; o; o >>= 1) vs += __shfl_xor_sync(full, vs, o);
    float inv = rsqrtf(vs * (1.f / DD) + 1e-5f);
    float4 s0 = *(const float4*)(s + lane * 4);
    float4 s1 = *(const float4*)(s + 128 + lane * 4);
    float4 g0 = *(const float4*)(bias + lane * 4);
    float4 g1 = *(const float4*)(bias + 128 + lane * 4);
    __half2* op0 = (__half2*)(out + (size_t)row * DD + lane * 4);
    __half2* op1 = (__half2*)(out + (size_t)row * DD + 128 + lane * 4);
    op0[0] = __floats2half2_rn(c0x * inv * s0.x + g0.x, c0y * inv * s0.y + g0.y);
    op0[1] = __floats2half2_rn(c0z * inv * s0.z + g0.z, c0w * inv * s0.w + g0.w);
    op1[0] = __floats2half2_rn(c1x * inv * s1.x + g1.x, c1y * inv * s1.y + g1.y);
    op1[1] = __floats2half2_rn(c1z * inv * s1.z + g1.z, c1w * inv * s1.w + g1.w);
}

// ---------------- fp16 helpers ----------------------------------------------
__device__ __forceinline__ uint32_t f2h2(float lo, float hi) {
    __half2 h = __floats2half2_rn(lo, hi);
    return *(uint32_t*)&h;
}
__device__ __forceinline__ void mmaf16(float* d, const uint32_t* a, const uint32_t* b) {
    asm volatile(
        "mma.sync.aligned.m16n8k16.row.col.f32.f16.f16.f32 "
        "{%0,%1,%2,%3}, {%4,%5,%6,%7}, {%8,%9}, {%0,%1,%2,%3};\n"
        : "+f"(d[0]), "+f"(d[1]), "+f"(d[2]), "+f"(d[3])
        : "r"(a[0]), "r"(a[1]), "r"(a[2]), "r"(a[3]), "r"(b[0]), "r"(b[1]));
}
__device__ __forceinline__ uint32_t smem_u32(const void* p) {
    uint32_t a;
    asm("{ .reg .u64 t; cvta.to.shared.u64 t, %1; cvt.u32.u64 %0, t; }"
        : "=r"(a) : "l"(p));
    return a;
}
__device__ __forceinline__ void cpa16(uint32_t d, const void* s) {
    asm volatile("cp.async.cg.shared.global [%0], [%1], 16;"
                 :: "r"(d), "l"(s) : "memory");
}
__device__ __forceinline__ void cpa16z(uint32_t d, const void* s, unsigned sz) {
    asm volatile("cp.async.cg.shared.global [%0], [%1], 16, %2;"
                 :: "r"(d), "l"(s), "r"(sz) : "memory");
}

// ---------------- half-input tensor-core NT GEMM: C = A*B^T + epi -----------
// (round-16 proven; epilogue now supports dual float+half output)
#define HSTRW 12
#define HSTAGE_WORDS (192 * HSTRW)
#define GTH_SMEM (4 * HSTAGE_WORDS * 4)       // 36864 B
__global__ __launch_bounds__(256, 2)
void gemm_tch(const __half* __restrict__ A, const __half* __restrict__ B,
              const float* __restrict__ bias, const float* __restrict__ resid,
              float* __restrict__ C, __half* __restrict__ Ch,
              int M, int N, int K, int relu) {
    extern __shared__ __align__(16) uint32_t smw[];
    const int tid = threadIdx.x;
    const int lane = tid & 31, wid = tid >> 5;
    const int g = lane >> 2, tg = lane & 3;
    const int wm = (wid >> 1) * 32, wn = (wid & 1) * 32;
    const int bm = blockIdx.y * 128, bn = blockIdx.x * 64;

    const int rowA = tid >> 1, offH = (tid & 1) * 8;
    int gmA = bm + rowA; if (gmA >= M) gmA = M - 1;
    const __half* ap = A + (size_t)gmA * K + offH;
    const bool hasB = tid < 128;
    const int rowB = tid >> 1;
    const __half* bp = B + (size_t)(bn + rowB) * K + offH;

    const uint32_t sbase = smem_u32(smw);
    const uint32_t dA = sbase + (uint32_t)(rowA * HSTRW + (tid & 1) * 4) * 4u;
    const uint32_t dB = sbase + (uint32_t)((128 + rowB) * HSTRW + (tid & 1) * 4) * 4u;

    const int NIT = K >> 4;

    #pragma unroll
    for (int s = 0; s < 3; s++) {
        uint32_t off = (uint32_t)(s * HSTAGE_WORDS) * 4u;
        cpa16(dA + off, ap + s * 16);
        if (hasB) cpa16(dB + off, bp + s * 16);
        asm volatile("cp.async.commit_group;" ::: "memory");
    }

    float acc[2][4][4];
    #pragma unroll
    for (int mi = 0; mi < 2; mi++)
        #pragma unroll
        for (int ni = 0; ni < 4; ni++)
            #pragma unroll
            for (int r = 0; r < 4; r++) acc[mi][ni][r] = 0.f;

    for (int i = 0; i < NIT; i++) {
        if (i <= NIT - 3)      asm volatile("cp.async.wait_group 2;" ::: "memory");
        else if (i == NIT - 2) asm volatile("cp.async.wait_group 1;" ::: "memory");
        else                   asm volatile("cp.async.wait_group 0;" ::: "memory");
        __syncthreads();

        int snext = i + 3;
        if (snext < NIT) {
            uint32_t off = (uint32_t)((snext & 3) * HSTAGE_WORDS) * 4u;
            const int kof = snext * 16;
            cpa16(dA + off, ap + kof);
            if (hasB) cpa16(dB + off, bp + kof);
            asm volatile("cp.async.commit_group;" ::: "memory");
        }

        const uint32_t* Wb = smw + (i & 3) * HSTAGE_WORDS;
        uint32_t af[2][4], bf[4][2];
        #pragma unroll
        for (int mi = 0; mi < 2; mi++) {
            const uint32_t* r0b = Wb + (wm + mi * 16 + g) * HSTRW;
            const uint32_t* r1b = r0b + 8 * HSTRW;
            af[mi][0] = r0b[tg];
            af[mi][1] = r1b[tg];
            af[mi][2] = r0b[4 + tg];
            af[mi][3] = r1b[4 + tg];
        }
        #pragma unroll
        for (int ni = 0; ni < 4; ni++) {
            const uint32_t* cb = Wb + (128 + wn + ni * 8 + g) * HSTRW;
            bf[ni][0] = cb[tg];
            bf[ni][1] = cb[4 + tg];
        }
        #pragma unroll
        for (int mi = 0; mi < 2; mi++)
            #pragma unroll
            for (int ni = 0; ni < 4; ni++)
                mmaf16(acc[mi][ni], af[mi], bf[ni]);
    }

    #pragma unroll
    for (int ni = 0; ni < 4; ni++) {
        int c = bn + wn + ni * 8 + 2 * tg;
        float b0 = bias ? bias[c] : 0.f;
        float b1 = bias ? bias[c + 1] : 0.f;
        #pragma unroll
        for (int mi = 0; mi < 2; mi++) {
            int r0 = bm + wm + mi * 16 + g;
            int r1 = r0 + 8;
            float v0 = acc[mi][ni][0] + b0, v1 = acc[mi][ni][1] + b1;
            float v2 = acc[mi][ni][2] + b0, v3 = acc[mi][ni][3] + b1;
            if (relu) {
                v0 = fmaxf(v0, 0.f); v1 = fmaxf(v1, 0.f);
                v2 = fmaxf(v2, 0.f); v3 = fmaxf(v3, 0.f);
            }
            if (r0 < M) {
                if (resid) {
                    float2 rr = *(const float2*)(resid + (size_t)r0 * N + c);
                    v0 += rr.x; v1 += rr.y;
                }
                if (C)  *(float2*)(C + (size_t)r0 * N + c) = make_float2(v0, v1);
                if (Ch) *(__half2*)(Ch + (size_t)r0 * N + c) = __floats2half2_rn(v0, v1);
            }
            if (r1 < M) {
                if (resid) {
                    float2 rr = *(const float2*)(resid + (size_t)r1 * N + c);
                    v2 += rr.x; v3 += rr.y;
                }
                if (C)  *(float2*)(C + (size_t)r1 * N + c) = make_float2(v2, v3);
                if (Ch) *(__half2*)(Ch + (size_t)r1 * N + c) = __floats2half2_rn(v2, v3);
            }
        }
    }
}

// ---------------- flash attention v5: all-half operands ----------------------
// K half [key][d] word-stride 20 (banks 20g+tg distinct); V half [d][key]
// word-stride 36 (banks 4g+tg distinct); P half2. cp.async double-buffered.
#define AKSTW 20
#define AVSTW 36
#define APST  36
__global__ __launch_bounds__(128)
void attn5_kernel(const float* __restrict__ qkv, const __half* __restrict__ qkvh,
                  const __half* __restrict__ vT, __half* __restrict__ out) {
    __shared__ __align__(16) uint32_t Kw[2][64 * AKSTW];   // 10240 B
    __shared__ __align__(16) uint32_t Vw[2][32 * AVSTW];   //  9216 B
    __shared__ __align__(16) uint32_t PsH[64 * APST];      //  9216 B

    const int b = blockIdx.z, h = blockIdx.y, qt = blockIdx.x;
    const int tid = threadIdx.x;
    const int w = tid >> 5, lane = tid & 31;
    const int g = lane >> 2, tg = lane & 3;
    const float scale = 0.17677669529663687f;
    const unsigned full = 0xffffffffu;

    const uint32_t kb0 = smem_u32(&Kw[0][0]);
    const uint32_t vb0 = smem_u32(&Vw[0][0]);
    const uint32_t KBYTES = 64 * AKSTW * 4;
    const uint32_t VBYTES = 32 * AVSTW * 4;

    // K fill: thread -> key=tid>>1, 16 halfs at (tid&1)*16 (2 x 16B chunks)
    const int fkey = tid >> 1, fho = (tid & 1) * 16;
    const uint32_t kdst = kb0 + (uint32_t)(fkey * AKSTW + (tid & 1) * 8) * 4u;
    // V fill: thread -> d=tid>>2, 16 keys at (tid&3)*16 (2 x 16B chunks)
    const int fd = tid >> 2, fkc = (tid & 3) * 16;
    const uint32_t vdst = vb0 + (uint32_t)(fd * AVSTW + (tid & 3) * 8) * 4u;
    const __half* vrow = vT + ((size_t)((b * HH + h) * HD + fd)) * NQV + fkc;

    // ---- Q fragments from float qkv (pre-scaled), 2 k16 steps ----
    const int r0 = qt * 64 + w * 16 + g;
    const int r1 = r0 + 8;
    uint32_t qa[2][4];
    {
        const float* q0p = qkv + ((size_t)(b * NQ + (r0 < NQ ? r0 : 0))) * 768 + h * HD;
        const float* q1p = qkv + ((size_t)(b * NQ + (r1 < NQ ? r1 : 0))) * 768 + h * HD;
        bool v0 = r0 < NQ, v1 = r1 < NQ;
        #pragma unroll
        for (int s = 0; s < 2; s++) {
            int c0 = s * 16 + 2 * tg;
            qa[s][0] = v0 ? f2h2(q0p[c0] * scale, q0p[c0 + 1] * scale) : 0u;
            qa[s][1] = v1 ? f2h2(q1p[c0] * scale, q1p[c0 + 1] * scale) : 0u;
            qa[s][2] = v0 ? f2h2(q0p[c0 + 8] * scale, q0p[c0 + 9] * scale) : 0u;
            qa[s][3] = v1 ? f2h2(q1p[c0 + 8] * scale, q1p[c0 + 9] * scale) : 0u;
        }
    }

    float m0 = -INFINITY, m1 = -INFINITY, l0 = 0.f, l1 = 0.f;
    float O[4][4];
    #pragma unroll
    for (int nd = 0; nd < 4; nd++)
        #pragma unroll
        for (int r = 0; r < 4; r++) O[nd][r] = 0.f;

    const int NKT = (NQ + 63) / 64;   // 15

    // ---- prologue: fill tile 0 ----
    {
        int kk = fkey;
        const __half* ksrc = qkvh + ((size_t)(b * NQ + (kk < NQ ? kk : 0))) * 768
                           + 256 + h * HD + fho;
        unsigned ksz = (kk < NQ) ? 16u : 0u;
        cpa16z(kdst,      ksrc,     ksz);
        cpa16z(kdst + 16, ksrc + 8, ksz);
        cpa16(vdst,      vrow);
        cpa16(vdst + 16, vrow + 8);
        asm volatile("cp.async.commit_group;" ::: "memory");
    }

    for (int jt = 0; jt < NKT; jt++) {
        asm volatile("cp.async.wait_group 0;" ::: "memory");
        __syncthreads();

        if (jt + 1 < NKT) {
            int kk = (jt + 1) * 64 + fkey;
            const __half* ksrc = qkvh + ((size_t)(b * NQ + (kk < NQ ? kk : 0))) * 768
                               + 256 + h * HD + fho;
            unsigned ksz = (kk < NQ) ? 16u : 0u;
            uint32_t bo = (jt + 1) & 1;
            uint32_t kd = kdst + bo * KBYTES;
            uint32_t vd = vdst + bo * VBYTES;
            const __half* vs = vrow + (jt + 1) * 64;
            cpa16z(kd,      ksrc,     ksz);
            cpa16z(kd + 16, ksrc + 8, ksz);
            cpa16(vd,      vs);
            cpa16(vd + 16, vs + 8);
            asm volatile("cp.async.commit_group;" ::: "memory");
        }

        const uint32_t* Kc = Kw[jt & 1];
        const uint32_t* Vc = Vw[jt & 1];

        // ---- QK ----
        float sacc[8][4];
        #pragma unroll
        for (int ni = 0; ni < 8; ni++)
            #pragma unroll
            for (int r = 0; r < 4; r++) sacc[ni][r] = 0.f;
        #pragma unroll
        for (int s = 0; s < 2; s++) {
            #pragma unroll
            for (int ni = 0; ni < 8; ni++) {
                const uint32_t* kb = Kc + (ni * 8 + g) * AKSTW + s * 8;
                uint32_t bf[2] = { kb[tg], kb[4 + tg] };
                mmaf16(sacc[ni], qa[s], bf);
            }
        }
        int kglob = jt * 64;
        if (kglob + 64 > NQ) {
            #pragma unroll
            for (int ni = 0; ni < 8; ni++) {
                int kc = kglob + ni * 8 + 2 * tg;
                if (kc >= NQ)     { sacc[ni][0] = -1e30f; sacc[ni][2] = -1e30f; }
                if (kc + 1 >= NQ) { sacc[ni][1] = -1e30f; sacc[ni][3] = -1e30f; }
            }
        }

        // ---- online softmax ----
        float mx0 = -INFINITY, mx1 = -INFINITY;
        #pragma unroll
        for (int ni = 0; ni < 8; ni++) {
            mx0 = fmaxf(mx0, fmaxf(sacc[ni][0], sacc[ni][1]));
            mx1 = fmaxf(mx1, fmaxf(sacc[ni][2], sacc[ni][3]));
        }
        mx0 = fmaxf(mx0, __shfl_xor_sync(full, mx0, 1));
        mx0 = fmaxf(mx0, __shfl_xor_sync(full, mx0, 2));
        mx1 = fmaxf(mx1, __shfl_xor_sync(full, mx1, 1));
        mx1 = fmaxf(mx1, __shfl_xor_sync(full, mx1, 2));
        float nm0 = fmaxf(m0, mx0), nm1 = fmaxf(m1, mx1);
        float fac0 = __expf(m0 - nm0), fac1 = __expf(m1 - nm1);
        float sum0 = 0.f, sum1 = 0.f;
        #pragma unroll
        for (int ni = 0; ni < 8; ni++) {
            sacc[ni][0] = __expf(sacc[ni][0] - nm0);
            sacc[ni][1] = __expf(sacc[ni][1] - nm0);
            sacc[ni][2] = __expf(sacc[ni][2] - nm1);
            sacc[ni][3] = __expf(sacc[ni][3] - nm1);
            sum0 += sacc[ni][0] + sacc[ni][1];
            sum1 += sacc[ni][2] + sacc[ni][3];
        }
        sum0 += __shfl_xor_sync(full, sum0, 1);
        sum0 += __shfl_xor_sync(full, sum0, 2);
        sum1 += __shfl_xor_sync(full, sum1, 1);
        sum1 += __shfl_xor_sync(full, sum1, 2);
        l0 = l0 * fac0 + sum0; m0 = nm0;
        l1 = l1 * fac1 + sum1; m1 = nm1;

        // ---- store P half2 ----
        int q0 = w * 16 + g;
        #pragma unroll
        for (int ni = 0; ni < 8; ni++) {
            PsH[q0 * APST + ni * 4 + tg]       = f2h2(sacc[ni][0], sacc[ni][1]);
            PsH[(q0 + 8) * APST + ni * 4 + tg] = f2h2(sacc[ni][2], sacc[ni][3]);
        }
        __syncwarp();

        // ---- rescale O, PV (all-half fragments) ----
        #pragma unroll
        for (int nd = 0; nd < 4; nd++) {
            O[nd][0] *= fac0; O[nd][1] *= fac0;
            O[nd][2] *= fac1; O[nd][3] *= fac1;
        }
        #pragma unroll
        for (int s = 0; s < 4; s++) {
            uint32_t pa[4];
            pa[0] = PsH[q0 * APST + 8 * s + tg];
            pa[1] = PsH[(q0 + 8) * APST + 8 * s + tg];
            pa[2] = PsH[q0 * APST + 8 * s + 4 + tg];
            pa[3] = PsH[(q0 + 8) * APST + 8 * s + 4 + tg];
            #pragma unroll
            for (int nd = 0; nd < 4; nd++) {
                const uint32_t* vb = Vc + (nd * 8 + g) * AVSTW + s * 8;
                uint32_t bf[2] = { vb[tg], vb[4 + tg] };
                mmaf16(O[nd], pa, bf);
            }
        }
    }

    float inv0 = 1.f / l0, inv1 = 1.f / l1;
    #pragma unroll
    for (int nd = 0; nd < 4; nd++) {
        int c = h * HD + nd * 8 + 2 * tg;
        if (r0 < NQ)
            *(__half2*)(out + ((size_t)(b * NQ + r0)) * DD + c) =
                __floats2half2_rn(O[nd][0] * inv0, O[nd][1] * inv0);
        if (r1 < NQ)
            *(__half2*)(out + ((size_t)(b * NQ + r1)) * DD + c) =
                __floats2half2_rn(O[nd][2] * inv1, O[nd][3] * inv1);
    }
}

// ---------------- deformable sampling (reads combined owts, writes half) ----
__global__ void sample_kernel(const float* __restrict__ mem, const float* __restrict__ ref,
                              const float* __restrict__ owts, __half* __restrict__ fused) {
    int row = blockIdx.x;
    int b = row / NQ;
    int h = threadIdx.x >> 5;
    int lane = threadIdx.x & 31;
    const unsigned full = 0xffffffffu;
    float rx = ref[row * 2], ry = ref[row * 2 + 1];
    float gx = 0.f, gy = 0.f, wl = 0.f;
    if (lane < PP) {
        float ox = owts[(size_t)row * 128 + h * (PP * 2) + lane * 2];
        float oy = owts[(size_t)row * 128 + h * (PP * 2) + lane * 2 + 1];
        gx = (rx + tanhf(ox) * 0.2f) * (float)BEV - 0.5f;
        gy = (ry + tanhf(oy) * 0.2f) * (float)BEV - 0.5f;
        wl = owts[(size_t)row * 128 + 64 + h * PP + lane];
    }
    float m = wl;
    m = fmaxf(m, __shfl_xor_sync(full, m, 1));
    m = fmaxf(m, __shfl_xor_sync(full, m, 2));
    float e = __expf(wl - m);
    float ssum = e;
    ssum += __shfl_xor_sync(full, ssum, 1);
    ssum += __shfl_xor_sync(full, ssum, 2);
    float w = e / ssum;
    const float* mb = mem + (size_t)b * (BEV * BEV) * DD + h * HD + lane;
    float acc = 0.f;
    #pragma unroll
    for (int p = 0; p < PP; p++) {
        float px = __shfl_sync(full, gx, p);
        float py = __shfl_sync(full, gy, p);
        float pw = __shfl_sync(full, w, p);
        float x0f = floorf(px), y0f = floorf(py);
        float wx1 = px - x0f, wy1 = py - y0f;
        float wx0 = 1.f - wx1, wy0 = 1.f - wy1;
        int x0 = (int)x0f, y0 = (int)y0f;
        bool xv0 = (x0 >= 0) && (x0 < BEV);
        bool xv1 = (x0 + 1 >= 0) && (x0 + 1 < BEV);
        bool yv0 = (y0 >= 0) && (y0 < BEV);
        bool yv1 = (y0 + 1 >= 0) && (y0 + 1 < BEV);
        float v = 0.f;
        if (yv0) {
            if (xv0) v += wx0 * wy0 * mb[(size_t)(y0 * BEV + x0) * DD];
            if (xv1) v += wx1 * wy0 * mb[(size_t)(y0 * BEV + x0 + 1) * DD];
        }
        if (yv1) {
            if (xv0) v += wx0 * wy1 * mb[(size_t)((y0 + 1) * BEV + x0) * DD];
            if (xv1) v += wx1 * wy1 * mb[(size_t)((y0 + 1) * BEV + x0 + 1) * DD];
        }
        acc += pw * v;
    }
    fused[(size_t)row * DD + h * HD + lane] = __float2half(acc);
}

// ---------------- host launcher ---------------------------------------------
extern "C" void kernel_launch(void* const* d_in, const int* in_sizes, int n_in,
                              void* d_out, int out_size) {
    const float* query = (const float*)d_in[0];
    const float* memory = (const float*)d_in[1];
    const float* refp  = (const float*)d_in[2];
    const float* qpos  = (const float*)d_in[3];
    const float* in_w  = (const float*)d_in[4];
    const float* in_b  = (const float*)d_in[5];
    const float* out_w = (const float*)d_in[6];
    const float* out_b = (const float*)d_in[7];
    const float* off_w = (const float*)d_in[8];
    const float* off_b = (const float*)d_in[9];
    const float* wt_w  = (const float*)d_in[10];
    const float* wt_b  = (const float*)d_in[11];
    const float* co_w  = (const float*)d_in[12];
    const float* co_b  = (const float*)d_in[13];
    const float* f_w1  = (const float*)d_in[14];
    const float* f_b1  = (const float*)d_in[15];
    const float* f_w2  = (const float*)d_in[16];
    const float* f_b2  = (const float*)d_in[17];
    const float* n1s   = (const float*)d_in[18];
    const float* n1b   = (const float*)d_in[19];
    const float* n2s   = (const float*)d_in[20];
    const float* n2b   = (const float*)d_in[21];
    const float* n3s   = (const float*)d_in[22];
    const float* n3b   = (const float*)d_in[23];

    float *qkv, *q1, *qq2, *owts, *owb;
    __half *qkv_h, *vT_h, *qin_h, *attn_h, *q2_h, *q3_h, *fused_h, *mid_h;
    __half *inw_h, *outw_h, *cow_h, *fw1_h, *fw2_h, *how_h;
    cudaGetSymbolAddress((void**)&qkv,    g_qkv);
    cudaGetSymbolAddress((void**)&q1,     g_q1);
    cudaGetSymbolAddress((void**)&qq2,    g_qq2);
    cudaGetSymbolAddress((void**)&owts,   g_owts);
    cudaGetSymbolAddress((void**)&owb,    g_owb);
    cudaGetSymbolAddress((void**)&qkv_h,  g_qkv_h);
    cudaGetSymbolAddress((void**)&vT_h,   g_vT_h);
    cudaGetSymbolAddress((void**)&qin_h,  g_qin_h);
    cudaGetSymbolAddress((void**)&attn_h, g_attn_h);
    cudaGetSymbolAddress((void**)&q2_h,   g_q2_h);
    cudaGetSymbolAddress((void**)&q3_h,   g_q3_h);
    cudaGetSymbolAddress((void**)&fused_h,g_fused_h);
    cudaGetSymbolAddress((void**)&mid_h,  g_mid_h);
    cudaGetSymbolAddress((void**)&inw_h,  g_inw_h);
    cudaGetSymbolAddress((void**)&outw_h, g_outw_h);
    cudaGetSymbolAddress((void**)&cow_h,  g_cow_h);
    cudaGetSymbolAddress((void**)&fw1_h,  g_fw1_h);
    cudaGetSymbolAddress((void**)&fw2_h,  g_fw2_h);
    cudaGetSymbolAddress((void**)&how_h,  g_how_h);

    const int M = MROWS;
    const int MTC = (M + 127) / 128;     // 57
    const int LNG = (M + 7) / 8;         // 900

    cudaFuncSetAttribute(gemm_tch, cudaFuncAttributeMaxDynamicSharedMemorySize,
                         GTH_SMEM);

    // 0. convert weights to fp16 (+ combined off/wt head)
    cvt_weights<<<dim3(192, 6), 256>>>(in_w, out_w, co_w, f_w1, f_w2,
                                       off_w, wt_w, off_b, wt_b);
    // 1. q_in = LN(query + query_pos) -> half
    add_ln_warp<<<LNG, 256>>>(query, qpos, n1s, n1b, qin_h);
    // 2. qkv = q_in @ in_w^T + in_b (dual float + half)
    gemm_tch<<<dim3(12, MTC), 256, GTH_SMEM>>>(qin_h, inw_h, in_b, nullptr,
                                               qkv, qkv_h, M, 768, 256, 0);
    // 2b. V transpose -> vT_h
    vtrans_kernel<<<dim3(15, BB * HH), 256>>>(qkv_h, vT_h);
    // 3. self-attention (all-half operands) -> half attn
    attn5_kernel<<<dim3((NQ + 63) / 64, HH, BB), 128>>>(qkv, qkv_h, vT_h, attn_h);
    // 4. q1 = attn @ out_w^T + out_b + query (float)
    gemm_tch<<<dim3(4, MTC), 256, GTH_SMEM>>>(attn_h, outw_h, out_b, query,
                                              q1, nullptr, M, 256, 256, 0);
    // 5. q2 = LN(q1 + query_pos) -> half
    add_ln_warp<<<LNG, 256>>>(q1, qpos, n2s, n2b, q2_h);
    // 6. combined offset+weight heads (float out)
    gemm_tch<<<dim3(2, MTC), 256, GTH_SMEM>>>(q2_h, how_h, owb, nullptr,
                                              owts, nullptr, M, 128, 256, 0);
    // 7. deformable BEV sampling -> half fused
    sample_kernel<<<M, 256>>>(memory, refp, owts, fused_h);
    // 8. qq2 = fused @ co_w^T + co_b + q1 (float)
    gemm_tch<<<dim3(4, MTC), 256, GTH_SMEM>>>(fused_h, cow_h, co_b, q1,
                                              qq2, nullptr, M, 256, 256, 0);
    // 9. q3 = LN(qq2) -> half
    add_ln_warp<<<LNG, 256>>>(qq2, nullptr, n3s, n3b, q3_h);
    // 10. mid = relu(q3 @ f_w1^T + f_b1) -> half
    gemm_tch<<<dim3(8, MTC), 256, GTH_SMEM>>>(q3_h, fw1_h, f_b1, nullptr,
                                              nullptr, mid_h, M, 512, 256, 1);
    // 11. out = mid @ f_w2^T + f_b2 + qq2 (float)
    gemm_tch<<<dim3(4, MTC), 256, GTH_SMEM>>>(mid_h, fw2_h, f_b2, qq2,
                                              (float*)d_out, nullptr, M, 256, 512, 0);
    (void)in_sizes; (void)n_in; (void)out_size;
}